// round 1
// baseline (speedup 1.0000x reference)
#include <cuda_runtime.h>
#include <math.h>

#define NN 20000
#define EE 320000
#define DD 256
#define HH 8
#define DKK 32
#define DVV 32
#define LL 2
#define HUSZ 1024

// ---------------- scratch (no allocation allowed) ----------------
__device__ float g_q[NN * DD];
__device__ float g_k[NN * DD];
__device__ float g_v[NN * DD];
__device__ float g_e[EE * HH];       // logits, then exp(a) in-place
__device__ float g_m[NN * HH];       // segment max
__device__ float g_z[NN * HH];       // segment sum
__device__ float g_agg[NN * DD];     // aggregated messages
__device__ float g_h[NN * DD];       // current hidden state
__device__ float g_attn[NN * DD];    // attn out pre-LN
__device__ float g_ffn[NN * HUSZ];   // FFN hidden

// ---------------- generic fp32 GEMM: C[M,Nc] = A[M,Kc] @ B[Kc,Nc] (+bias)(relu) ----------------
// BM=BN=64, BK=16, 256 threads, 4x4 micro-tile per thread.
__global__ __launch_bounds__(256) void gemm64(
    const float* __restrict__ A, const float* __restrict__ B,
    const float* __restrict__ bias, float* __restrict__ C,
    int M, int Nc, int Kc, int relu)
{
    __shared__ float As[16][66];   // padded: conflict-free transpose store
    __shared__ float Bs[16][64];

    int tid = threadIdx.x;
    int tx = tid & 15, ty = tid >> 4;
    int row0 = blockIdx.y * 64, col0 = blockIdx.x * 64;

    int ar = tid >> 2;          // 0..63 (A tile row)
    int ak = (tid & 3) * 4;     // 0,4,8,12 (A tile k base)
    int bk = tid >> 4;          // 0..15 (B tile k)
    int bc = (tid & 15) * 4;    // 0..60 (B tile col base)

    float acc[4][4] = {};

    for (int k0 = 0; k0 < Kc; k0 += 16) {
        float4 av;
        if (row0 + ar < M)
            av = *reinterpret_cast<const float4*>(&A[(size_t)(row0 + ar) * Kc + k0 + ak]);
        else
            av = make_float4(0.f, 0.f, 0.f, 0.f);
        As[ak + 0][ar] = av.x;
        As[ak + 1][ar] = av.y;
        As[ak + 2][ar] = av.z;
        As[ak + 3][ar] = av.w;

        float4 bv = *reinterpret_cast<const float4*>(&B[(size_t)(k0 + bk) * Nc + col0 + bc]);
        *reinterpret_cast<float4*>(&Bs[bk][bc]) = bv;

        __syncthreads();

        #pragma unroll
        for (int kk = 0; kk < 16; kk++) {
            float a[4], b[4];
            #pragma unroll
            for (int i = 0; i < 4; i++) a[i] = As[kk][ty + 16 * i];
            #pragma unroll
            for (int j = 0; j < 4; j++) b[j] = Bs[kk][tx + 16 * j];
            #pragma unroll
            for (int i = 0; i < 4; i++)
                #pragma unroll
                for (int j = 0; j < 4; j++)
                    acc[i][j] += a[i] * b[j];
        }
        __syncthreads();
    }

    #pragma unroll
    for (int i = 0; i < 4; i++) {
        int r = row0 + ty + 16 * i;
        if (r >= M) continue;
        #pragma unroll
        for (int j = 0; j < 4; j++) {
            int c = col0 + tx + 16 * j;
            float v = acc[i][j];
            if (bias) v += bias[c];
            if (relu) v = fmaxf(v, 0.f);
            C[(size_t)r * Nc + c] = v;
        }
    }
}

// ---------------- init m/z/agg ----------------
__global__ void init_mzagg(float* m, float* z, float* agg)
{
    int i = blockIdx.x * blockDim.x + threadIdx.x;
    if (i < NN * DD) agg[i] = 0.f;
    if (i < NN * HH) { m[i] = -INFINITY; z[i] = 0.f; }
}

__device__ __forceinline__ void atomicMaxF(float* addr, float val)
{
    int old = __float_as_int(*addr);
    while (__int_as_float(old) < val) {
        int prev = atomicCAS((int*)addr, old, __float_as_int(val));
        if (prev == old) break;
        old = prev;
    }
}

// ---------------- edge logits + segment max: one warp per edge ----------------
__global__ void edge_logits(const int* __restrict__ src, const int* __restrict__ dst,
                            const float* __restrict__ q, const float* __restrict__ k,
                            float* __restrict__ e, float* __restrict__ m)
{
    int eidx = (blockIdx.x * blockDim.x + threadIdx.x) >> 5;
    int lane = threadIdx.x & 31;
    if (eidx >= EE) return;
    int s = src[eidx], d = dst[eidx];
    const float* qr = q + (size_t)d * DD;
    const float* kr = k + (size_t)s * DD;

    float part[HH];
    #pragma unroll
    for (int j = 0; j < HH; j++)
        part[j] = qr[j * 32 + lane] * kr[j * 32 + lane];

    float res = 0.f;
    #pragma unroll
    for (int j = 0; j < HH; j++) {
        float v = part[j];
        #pragma unroll
        for (int off = 16; off; off >>= 1) v += __shfl_xor_sync(0xffffffffu, v, off);
        if (lane == j) res = v;
    }
    if (lane < HH) {
        float logit = res * 0.17677669529663687f;  // 1/sqrt(32)
        e[(size_t)eidx * HH + lane] = logit;
        atomicMaxF(&m[d * HH + lane], logit);
    }
}

// ---------------- exp + segment sum: one thread per (edge, head) ----------------
__global__ void edge_expsum(const int* __restrict__ dst, float* __restrict__ e,
                            const float* __restrict__ m, float* __restrict__ z)
{
    int i = blockIdx.x * blockDim.x + threadIdx.x;
    if (i >= EE * HH) return;
    int eidx = i >> 3, hh = i & 7;
    int d = dst[eidx];
    float a = expf(e[i] - m[d * HH + hh]);
    e[i] = a;
    atomicAdd(&z[d * HH + hh], a);
}

// ---------------- scatter messages: one warp per edge ----------------
__global__ void edge_scatter(const int* __restrict__ src, const int* __restrict__ dst,
                             const float* __restrict__ v, const float* __restrict__ e,
                             const float* __restrict__ z, float* __restrict__ agg)
{
    int eidx = (blockIdx.x * blockDim.x + threadIdx.x) >> 5;
    int lane = threadIdx.x & 31;
    if (eidx >= EE) return;
    int s = src[eidx], d = dst[eidx];
    const float* vr = v + (size_t)s * DD;
    float* ar = agg + (size_t)d * DD;

    #pragma unroll
    for (int j = 0; j < HH; j++) {
        float alpha = e[(size_t)eidx * HH + j] / (z[d * HH + j] + 1e-9f);
        atomicAdd(&ar[j * 32 + lane], vr[j * 32 + lane] * alpha);
    }
}

// ---------------- residual + layernorm: one warp per row ----------------
__global__ void ln_residual(const float* __restrict__ attn, float* __restrict__ h,
                            const float* __restrict__ gamma, const float* __restrict__ beta)
{
    int row = (blockIdx.x * blockDim.x + threadIdx.x) >> 5;
    int lane = threadIdx.x & 31;
    if (row >= NN) return;
    float x[8];
    float s = 0.f;
    #pragma unroll
    for (int j = 0; j < 8; j++) {
        x[j] = attn[(size_t)row * DD + j * 32 + lane] + h[(size_t)row * DD + j * 32 + lane];
        s += x[j];
    }
    #pragma unroll
    for (int off = 16; off; off >>= 1) s += __shfl_xor_sync(0xffffffffu, s, off);
    float mu = s * (1.f / DD);
    float vs = 0.f;
    #pragma unroll
    for (int j = 0; j < 8; j++) { float dlt = x[j] - mu; vs += dlt * dlt; }
    #pragma unroll
    for (int off = 16; off; off >>= 1) vs += __shfl_xor_sync(0xffffffffu, vs, off);
    float inv = rsqrtf(vs * (1.f / DD) + 1e-5f);
    #pragma unroll
    for (int j = 0; j < 8; j++) {
        int c = j * 32 + lane;
        h[(size_t)row * DD + c] = (x[j] - mu) * inv * gamma[c] + beta[c];
    }
}

// ---------------- launch ----------------
extern "C" void kernel_launch(void* const* d_in, const int* in_sizes, int n_in,
                              void* d_out, int out_size)
{
    const float* h_in = (const float*)d_in[0];
    const int* src = (const int*)d_in[1];
    const int* dst = (const int*)d_in[2];
    const float* Wq = (const float*)d_in[3];
    const float* Wk = (const float*)d_in[4];
    const float* Wv = (const float*)d_in[5];
    const float* Wo = (const float*)d_in[6];
    const float* ln_g = (const float*)d_in[7];
    const float* ln_b = (const float*)d_in[8];
    const float* w1 = (const float*)d_in[9];
    const float* b1 = (const float*)d_in[10];
    const float* w2 = (const float*)d_in[11];
    const float* b2 = (const float*)d_in[12];
    float* out = (float*)d_out;

    float *pq, *pk, *pv, *pe, *pm, *pz, *pagg, *ph, *pattn, *pffn;
    cudaGetSymbolAddress((void**)&pq, g_q);
    cudaGetSymbolAddress((void**)&pk, g_k);
    cudaGetSymbolAddress((void**)&pv, g_v);
    cudaGetSymbolAddress((void**)&pe, g_e);
    cudaGetSymbolAddress((void**)&pm, g_m);
    cudaGetSymbolAddress((void**)&pz, g_z);
    cudaGetSymbolAddress((void**)&pagg, g_agg);
    cudaGetSymbolAddress((void**)&ph, g_h);
    cudaGetSymbolAddress((void**)&pattn, g_attn);
    cudaGetSymbolAddress((void**)&pffn, g_ffn);

    // h -> g_h
    cudaMemcpyAsync(ph, h_in, (size_t)NN * DD * sizeof(float), cudaMemcpyDeviceToDevice);

    dim3 gemm_grid_d(DD / 64, (NN + 63) / 64);      // Nc=256
    dim3 gemm_grid_hus(HUSZ / 64, (NN + 63) / 64);  // Nc=1024

    for (int l = 0; l < LL; l++) {
        const float* wq = Wq + (size_t)l * DD * DD;
        const float* wk = Wk + (size_t)l * DD * DD;
        const float* wv = Wv + (size_t)l * DD * DD;
        const float* wo = Wo + (size_t)l * DD * DD;
        const float* lg = ln_g + (size_t)l * DD;
        const float* lb = ln_b + (size_t)l * DD;

        gemm64<<<gemm_grid_d, 256>>>(ph, wq, nullptr, pq, NN, DD, DD, 0);
        gemm64<<<gemm_grid_d, 256>>>(ph, wk, nullptr, pk, NN, DD, DD, 0);
        gemm64<<<gemm_grid_d, 256>>>(ph, wv, nullptr, pv, NN, DD, DD, 0);

        init_mzagg<<<(NN * DD + 255) / 256, 256>>>(pm, pz, pagg);

        edge_logits<<<(EE * 32) / 256, 256>>>(src, dst, pq, pk, pe, pm);
        edge_expsum<<<(EE * HH) / 256, 256>>>(dst, pe, pm, pz);
        edge_scatter<<<(EE * 32) / 256, 256>>>(src, dst, pv, pe, pz, pagg);

        gemm64<<<gemm_grid_d, 256>>>(pagg, wo, nullptr, pattn, NN, DD, DD, 0);
        ln_residual<<<(NN * 32) / 256, 256>>>(pattn, ph, lg, lb);
    }

    // FFN
    gemm64<<<gemm_grid_hus, 256>>>(ph, w1, b1, pffn, NN, HUSZ, DD, 1);
    gemm64<<<gemm_grid_d, 256>>>(pffn, w2, b2, out, NN, DD, HUSZ, 0);
}

// round 2
// speedup vs baseline: 2.0855x; 2.0855x over previous
#include <cuda_runtime.h>
#include <math.h>

#define NN 20000
#define EE 320000
#define DD 256
#define HH 8
#define LL 2
#define HUSZ 1024

// ---------------- scratch (no allocation allowed) ----------------
__device__ float g_q[NN * DD];
__device__ float g_k[NN * DD];
__device__ float g_v[NN * DD];
__device__ float g_e[EE * HH];
__device__ float g_m[NN * HH];
__device__ float g_z[NN * HH];
__device__ float g_agg[NN * DD];
__device__ float g_h[NN * DD];
__device__ float g_attn[NN * DD];
__device__ float g_ffn[NN * HUSZ];

// ---------------- tf32 tensor-core GEMM ----------------
// C[M,Nc] = A[M,Kc] @ B[Kc,Nc] (+bias)(relu), all row-major fp32.
// Block tile 128x128, BK=32, 256 threads = 8 warps (2x4), warp tile 64x32.
// mma.sync.aligned.m16n8k8.row.col.f32.tf32.tf32.f32

__device__ __forceinline__ unsigned f2tf32(float x) {
    unsigned r;
    asm("cvt.rna.tf32.f32 %0, %1;" : "=r"(r) : "f"(x));
    return r;
}

#define AS_PAD 36   // 32 + 4  -> frag loads conflict-free
#define BS_PAD 136  // 128 + 8 -> frag loads conflict-free

__global__ __launch_bounds__(256) void gemm_tc(
    const float* __restrict__ A, const float* __restrict__ B,
    const float* __restrict__ bias, float* __restrict__ C,
    int M, int Nc, int Kc, int relu)
{
    __shared__ float As[128 * AS_PAD];
    __shared__ float Bs[32 * BS_PAD];

    const int tid = threadIdx.x;
    const int wid = tid >> 5;
    const int lane = tid & 31;
    const int g = lane >> 2;   // group id 0..7
    const int t = lane & 3;    // thread-in-group 0..3

    const int warp_m = wid >> 2;       // 0..1
    const int warp_n = wid & 3;        // 0..3
    const int row0 = blockIdx.y * 128;
    const int col0 = blockIdx.x * 128;

    // global load mapping
    const int a_r = tid >> 3;          // 0..31 (plus i*32)
    const int a_c = (tid & 7) * 4;     // 0..28
    const int b_r = tid >> 6;          // 0..3 (plus i*4... see loop)
    const int b_c = (tid & 63) * 4 & 127; // unused; use explicit below

    float acc[4][4][4];
    #pragma unroll
    for (int mi = 0; mi < 4; mi++)
        #pragma unroll
        for (int ni = 0; ni < 4; ni++)
            #pragma unroll
            for (int r = 0; r < 4; r++) acc[mi][ni][r] = 0.f;

    for (int k0 = 0; k0 < Kc; k0 += 32) {
        // load A tile: 128 rows x 32 cols
        #pragma unroll
        for (int i = 0; i < 4; i++) {
            int r = i * 32 + a_r;
            float4 v;
            if (row0 + r < M)
                v = *reinterpret_cast<const float4*>(&A[(size_t)(row0 + r) * Kc + k0 + a_c]);
            else
                v = make_float4(0.f, 0.f, 0.f, 0.f);
            float* dst = &As[r * AS_PAD + a_c];
            dst[0] = __uint_as_float(f2tf32(v.x));
            dst[1] = __uint_as_float(f2tf32(v.y));
            dst[2] = __uint_as_float(f2tf32(v.z));
            dst[3] = __uint_as_float(f2tf32(v.w));
        }
        // load B tile: 32 rows x 128 cols
        #pragma unroll
        for (int i = 0; i < 4; i++) {
            int r = i * 8 + (tid >> 5);
            int c = (tid & 31) * 4;
            float4 v = *reinterpret_cast<const float4*>(&B[(size_t)(k0 + r) * Nc + col0 + c]);
            float* dst = &Bs[r * BS_PAD + c];
            dst[0] = __uint_as_float(f2tf32(v.x));
            dst[1] = __uint_as_float(f2tf32(v.y));
            dst[2] = __uint_as_float(f2tf32(v.z));
            dst[3] = __uint_as_float(f2tf32(v.w));
        }
        __syncthreads();

        #pragma unroll
        for (int ks = 0; ks < 4; ks++) {
            const int kk = ks * 8;
            unsigned af[4][4];
            #pragma unroll
            for (int mi = 0; mi < 4; mi++) {
                int rb = warp_m * 64 + mi * 16;
                const float* ap = &As[(rb + g) * AS_PAD + kk + t];
                af[mi][0] = __float_as_uint(ap[0]);
                af[mi][1] = __float_as_uint(ap[8 * AS_PAD]);
                af[mi][2] = __float_as_uint(ap[4]);
                af[mi][3] = __float_as_uint(ap[8 * AS_PAD + 4]);
            }
            unsigned bf[4][2];
            #pragma unroll
            for (int ni = 0; ni < 4; ni++) {
                int nb = warp_n * 32 + ni * 8;
                const float* bp = &Bs[(kk + t) * BS_PAD + nb + g];
                bf[ni][0] = __float_as_uint(bp[0]);
                bf[ni][1] = __float_as_uint(bp[4 * BS_PAD]);
            }
            #pragma unroll
            for (int mi = 0; mi < 4; mi++)
                #pragma unroll
                for (int ni = 0; ni < 4; ni++) {
                    asm volatile(
                        "mma.sync.aligned.m16n8k8.row.col.f32.tf32.tf32.f32 "
                        "{%0,%1,%2,%3}, {%4,%5,%6,%7}, {%8,%9}, {%0,%1,%2,%3};"
                        : "+f"(acc[mi][ni][0]), "+f"(acc[mi][ni][1]),
                          "+f"(acc[mi][ni][2]), "+f"(acc[mi][ni][3])
                        : "r"(af[mi][0]), "r"(af[mi][1]), "r"(af[mi][2]), "r"(af[mi][3]),
                          "r"(bf[ni][0]), "r"(bf[ni][1]));
                }
        }
        __syncthreads();
    }

    // epilogue
    #pragma unroll
    for (int mi = 0; mi < 4; mi++) {
        int rb = row0 + warp_m * 64 + mi * 16 + g;
        #pragma unroll
        for (int ni = 0; ni < 4; ni++) {
            int cb = col0 + warp_n * 32 + ni * 8 + 2 * t;
            #pragma unroll
            for (int half = 0; half < 2; half++) {
                int r = rb + half * 8;
                if (r >= M) continue;
                float v0 = acc[mi][ni][half * 2 + 0];
                float v1 = acc[mi][ni][half * 2 + 1];
                if (bias) { v0 += bias[cb]; v1 += bias[cb + 1]; }
                if (relu) { v0 = fmaxf(v0, 0.f); v1 = fmaxf(v1, 0.f); }
                *reinterpret_cast<float2*>(&C[(size_t)r * Nc + cb]) = make_float2(v0, v1);
            }
        }
    }
}

// ---------------- init m/z/agg ----------------
__global__ void init_mzagg(float* m, float* z, float* agg)
{
    int i = blockIdx.x * blockDim.x + threadIdx.x;
    if (i < NN * DD) agg[i] = 0.f;
    if (i < NN * HH) { m[i] = -INFINITY; z[i] = 0.f; }
}

__device__ __forceinline__ void atomicMaxF(float* addr, float val)
{
    int old = __float_as_int(*addr);
    while (__int_as_float(old) < val) {
        int prev = atomicCAS((int*)addr, old, __float_as_int(val));
        if (prev == old) break;
        old = prev;
    }
}

// ---------------- edge logits + segment max: one warp per edge ----------------
__global__ void edge_logits(const int* __restrict__ src, const int* __restrict__ dst,
                            const float* __restrict__ q, const float* __restrict__ k,
                            float* __restrict__ e, float* __restrict__ m)
{
    int eidx = (blockIdx.x * blockDim.x + threadIdx.x) >> 5;
    int lane = threadIdx.x & 31;
    if (eidx >= EE) return;
    int s = src[eidx], d = dst[eidx];
    const float* qr = q + (size_t)d * DD;
    const float* kr = k + (size_t)s * DD;

    float part[HH];
    #pragma unroll
    for (int j = 0; j < HH; j++)
        part[j] = qr[j * 32 + lane] * kr[j * 32 + lane];

    float res = 0.f;
    #pragma unroll
    for (int j = 0; j < HH; j++) {
        float v = part[j];
        #pragma unroll
        for (int off = 16; off; off >>= 1) v += __shfl_xor_sync(0xffffffffu, v, off);
        if (lane == j) res = v;
    }
    if (lane < HH) {
        float logit = res * 0.17677669529663687f;  // 1/sqrt(32)
        e[(size_t)eidx * HH + lane] = logit;
        atomicMaxF(&m[d * HH + lane], logit);
    }
}

// ---------------- exp + segment sum ----------------
__global__ void edge_expsum(const int* __restrict__ dst, float* __restrict__ e,
                            const float* __restrict__ m, float* __restrict__ z)
{
    int i = blockIdx.x * blockDim.x + threadIdx.x;
    if (i >= EE * HH) return;
    int eidx = i >> 3, hh = i & 7;
    int d = dst[eidx];
    float a = expf(e[i] - m[d * HH + hh]);
    e[i] = a;
    atomicAdd(&z[d * HH + hh], a);
}

// ---------------- scatter messages: one warp per edge ----------------
__global__ void edge_scatter(const int* __restrict__ src, const int* __restrict__ dst,
                             const float* __restrict__ v, const float* __restrict__ e,
                             const float* __restrict__ z, float* __restrict__ agg)
{
    int eidx = (blockIdx.x * blockDim.x + threadIdx.x) >> 5;
    int lane = threadIdx.x & 31;
    if (eidx >= EE) return;
    int s = src[eidx], d = dst[eidx];
    const float* vr = v + (size_t)s * DD;
    float* ar = agg + (size_t)d * DD;

    #pragma unroll
    for (int j = 0; j < HH; j++) {
        float alpha = e[(size_t)eidx * HH + j] / (z[d * HH + j] + 1e-9f);
        atomicAdd(&ar[j * 32 + lane], vr[j * 32 + lane] * alpha);
    }
}

// ---------------- residual + layernorm: one warp per row ----------------
__global__ void ln_residual(const float* __restrict__ attn, float* __restrict__ h,
                            const float* __restrict__ gamma, const float* __restrict__ beta)
{
    int row = (blockIdx.x * blockDim.x + threadIdx.x) >> 5;
    int lane = threadIdx.x & 31;
    if (row >= NN) return;
    float x[8];
    float s = 0.f;
    #pragma unroll
    for (int j = 0; j < 8; j++) {
        x[j] = attn[(size_t)row * DD + j * 32 + lane] + h[(size_t)row * DD + j * 32 + lane];
        s += x[j];
    }
    #pragma unroll
    for (int off = 16; off; off >>= 1) s += __shfl_xor_sync(0xffffffffu, s, off);
    float mu = s * (1.f / DD);
    float vs = 0.f;
    #pragma unroll
    for (int j = 0; j < 8; j++) { float dlt = x[j] - mu; vs += dlt * dlt; }
    #pragma unroll
    for (int off = 16; off; off >>= 1) vs += __shfl_xor_sync(0xffffffffu, vs, off);
    float inv = rsqrtf(vs * (1.f / DD) + 1e-5f);
    #pragma unroll
    for (int j = 0; j < 8; j++) {
        int c = j * 32 + lane;
        h[(size_t)row * DD + c] = (x[j] - mu) * inv * gamma[c] + beta[c];
    }
}

// ---------------- launch ----------------
extern "C" void kernel_launch(void* const* d_in, const int* in_sizes, int n_in,
                              void* d_out, int out_size)
{
    const float* h_in = (const float*)d_in[0];
    const int* src = (const int*)d_in[1];
    const int* dst = (const int*)d_in[2];
    const float* Wq = (const float*)d_in[3];
    const float* Wk = (const float*)d_in[4];
    const float* Wv = (const float*)d_in[5];
    const float* Wo = (const float*)d_in[6];
    const float* ln_g = (const float*)d_in[7];
    const float* ln_b = (const float*)d_in[8];
    const float* w1 = (const float*)d_in[9];
    const float* b1 = (const float*)d_in[10];
    const float* w2 = (const float*)d_in[11];
    const float* b2 = (const float*)d_in[12];
    float* out = (float*)d_out;

    float *pq, *pk, *pv, *pe, *pm, *pz, *pagg, *ph, *pattn, *pffn;
    cudaGetSymbolAddress((void**)&pq, g_q);
    cudaGetSymbolAddress((void**)&pk, g_k);
    cudaGetSymbolAddress((void**)&pv, g_v);
    cudaGetSymbolAddress((void**)&pe, g_e);
    cudaGetSymbolAddress((void**)&pm, g_m);
    cudaGetSymbolAddress((void**)&pz, g_z);
    cudaGetSymbolAddress((void**)&pagg, g_agg);
    cudaGetSymbolAddress((void**)&ph, g_h);
    cudaGetSymbolAddress((void**)&pattn, g_attn);
    cudaGetSymbolAddress((void**)&pffn, g_ffn);

    cudaMemcpyAsync(ph, h_in, (size_t)NN * DD * sizeof(float), cudaMemcpyDeviceToDevice);

    dim3 grid_d(DD / 128, (NN + 127) / 128);       // Nc=256
    dim3 grid_hus(HUSZ / 128, (NN + 127) / 128);   // Nc=1024

    for (int l = 0; l < LL; l++) {
        const float* wq = Wq + (size_t)l * DD * DD;
        const float* wk = Wk + (size_t)l * DD * DD;
        const float* wv = Wv + (size_t)l * DD * DD;
        const float* wo = Wo + (size_t)l * DD * DD;
        const float* lg = ln_g + (size_t)l * DD;
        const float* lb = ln_b + (size_t)l * DD;

        gemm_tc<<<grid_d, 256>>>(ph, wq, nullptr, pq, NN, DD, DD, 0);
        gemm_tc<<<grid_d, 256>>>(ph, wk, nullptr, pk, NN, DD, DD, 0);
        gemm_tc<<<grid_d, 256>>>(ph, wv, nullptr, pv, NN, DD, DD, 0);

        init_mzagg<<<(NN * DD + 255) / 256, 256>>>(pm, pz, pagg);

        edge_logits<<<(EE * 32) / 256, 256>>>(src, dst, pq, pk, pe, pm);
        edge_expsum<<<(EE * HH) / 256, 256>>>(dst, pe, pm, pz);
        edge_scatter<<<(EE * 32) / 256, 256>>>(src, dst, pv, pe, pz, pagg);

        gemm_tc<<<grid_d, 256>>>(pagg, wo, nullptr, pattn, NN, DD, DD, 0);
        ln_residual<<<(NN * 32) / 256, 256>>>(pattn, ph, lg, lb);
    }

    gemm_tc<<<grid_hus, 256>>>(ph, w1, b1, pffn, NN, HUSZ, DD, 1);
    gemm_tc<<<grid_d, 256>>>(pffn, w2, b2, out, NN, DD, HUSZ, 0);
}

// round 3
// speedup vs baseline: 2.8898x; 1.3857x over previous
#include <cuda_runtime.h>
#include <math.h>

#define NN 20000
#define EE 320000
#define DD 256
#define HH 8
#define LL 2
#define HUSZ 1024

// ---------------- scratch (no allocation allowed) ----------------
__device__ float g_q[NN * DD];
__device__ float g_k[NN * DD];
__device__ float g_v[NN * DD];
__device__ float g_agg[NN * DD];
__device__ float g_h[NN * DD];
__device__ float g_attn[NN * DD];
__device__ float g_ffn[NN * HUSZ];
__device__ int   g_cnt[NN];
__device__ int   g_off[NN + 1];
__device__ int   g_cur[NN];
__device__ int   g_csrc[EE];

// ---------------- tf32 tensor-core GEMM ----------------
__device__ __forceinline__ unsigned f2tf32(float x) {
    unsigned r;
    asm("cvt.rna.tf32.f32 %0, %1;" : "=r"(r) : "f"(x));
    return r;
}

#define AS_PAD 36
#define BS_PAD 136

__global__ __launch_bounds__(256) void gemm_tc(
    const float* __restrict__ A, const float* __restrict__ B,
    const float* __restrict__ bias, float* __restrict__ C,
    int M, int Nc, int Kc, int relu)
{
    __shared__ float As[128 * AS_PAD];
    __shared__ float Bs[32 * BS_PAD];

    const int tid = threadIdx.x;
    const int wid = tid >> 5;
    const int lane = tid & 31;
    const int g = lane >> 2;
    const int t = lane & 3;

    const int warp_m = wid >> 2;
    const int warp_n = wid & 3;
    const int row0 = blockIdx.y * 128;
    const int col0 = blockIdx.x * 128;

    const int a_r = tid >> 3;
    const int a_c = (tid & 7) * 4;

    float acc[4][4][4];
    #pragma unroll
    for (int mi = 0; mi < 4; mi++)
        #pragma unroll
        for (int ni = 0; ni < 4; ni++)
            #pragma unroll
            for (int r = 0; r < 4; r++) acc[mi][ni][r] = 0.f;

    for (int k0 = 0; k0 < Kc; k0 += 32) {
        #pragma unroll
        for (int i = 0; i < 4; i++) {
            int r = i * 32 + a_r;
            float4 v;
            if (row0 + r < M)
                v = *reinterpret_cast<const float4*>(&A[(size_t)(row0 + r) * Kc + k0 + a_c]);
            else
                v = make_float4(0.f, 0.f, 0.f, 0.f);
            float* dst = &As[r * AS_PAD + a_c];
            dst[0] = __uint_as_float(f2tf32(v.x));
            dst[1] = __uint_as_float(f2tf32(v.y));
            dst[2] = __uint_as_float(f2tf32(v.z));
            dst[3] = __uint_as_float(f2tf32(v.w));
        }
        #pragma unroll
        for (int i = 0; i < 4; i++) {
            int r = i * 8 + (tid >> 5);
            int c = (tid & 31) * 4;
            float4 v = *reinterpret_cast<const float4*>(&B[(size_t)(k0 + r) * Nc + col0 + c]);
            float* dst = &Bs[r * BS_PAD + c];
            dst[0] = __uint_as_float(f2tf32(v.x));
            dst[1] = __uint_as_float(f2tf32(v.y));
            dst[2] = __uint_as_float(f2tf32(v.z));
            dst[3] = __uint_as_float(f2tf32(v.w));
        }
        __syncthreads();

        #pragma unroll
        for (int ks = 0; ks < 4; ks++) {
            const int kk = ks * 8;
            unsigned af[4][4];
            #pragma unroll
            for (int mi = 0; mi < 4; mi++) {
                int rb = warp_m * 64 + mi * 16;
                const float* ap = &As[(rb + g) * AS_PAD + kk + t];
                af[mi][0] = __float_as_uint(ap[0]);
                af[mi][1] = __float_as_uint(ap[8 * AS_PAD]);
                af[mi][2] = __float_as_uint(ap[4]);
                af[mi][3] = __float_as_uint(ap[8 * AS_PAD + 4]);
            }
            unsigned bf[4][2];
            #pragma unroll
            for (int ni = 0; ni < 4; ni++) {
                int nb = warp_n * 32 + ni * 8;
                const float* bp = &Bs[(kk + t) * BS_PAD + nb + g];
                bf[ni][0] = __float_as_uint(bp[0]);
                bf[ni][1] = __float_as_uint(bp[4 * BS_PAD]);
            }
            #pragma unroll
            for (int mi = 0; mi < 4; mi++)
                #pragma unroll
                for (int ni = 0; ni < 4; ni++) {
                    asm volatile(
                        "mma.sync.aligned.m16n8k8.row.col.f32.tf32.tf32.f32 "
                        "{%0,%1,%2,%3}, {%4,%5,%6,%7}, {%8,%9}, {%0,%1,%2,%3};"
                        : "+f"(acc[mi][ni][0]), "+f"(acc[mi][ni][1]),
                          "+f"(acc[mi][ni][2]), "+f"(acc[mi][ni][3])
                        : "r"(af[mi][0]), "r"(af[mi][1]), "r"(af[mi][2]), "r"(af[mi][3]),
                          "r"(bf[ni][0]), "r"(bf[ni][1]));
                }
        }
        __syncthreads();
    }

    #pragma unroll
    for (int mi = 0; mi < 4; mi++) {
        int rb = row0 + warp_m * 64 + mi * 16 + g;
        #pragma unroll
        for (int ni = 0; ni < 4; ni++) {
            int cb = col0 + warp_n * 32 + ni * 8 + 2 * t;
            #pragma unroll
            for (int half = 0; half < 2; half++) {
                int r = rb + half * 8;
                if (r >= M) continue;
                float v0 = acc[mi][ni][half * 2 + 0];
                float v1 = acc[mi][ni][half * 2 + 1];
                if (bias) { v0 += bias[cb]; v1 += bias[cb + 1]; }
                if (relu) { v0 = fmaxf(v0, 0.f); v1 = fmaxf(v1, 0.f); }
                *reinterpret_cast<float2*>(&C[(size_t)r * Nc + cb]) = make_float2(v0, v1);
            }
        }
    }
}

// ---------------- CSR build ----------------
__global__ void zero_cnt(int* cnt)
{
    int i = blockIdx.x * blockDim.x + threadIdx.x;
    if (i < NN) cnt[i] = 0;
}

__global__ void hist_dst(const int* __restrict__ dst, int* __restrict__ cnt)
{
    int i = blockIdx.x * blockDim.x + threadIdx.x;
    if (i < EE) atomicAdd(&cnt[dst[i]], 1);
}

// single-block exclusive scan over NN counters; writes off[NN+1] and cursor copy
__global__ __launch_bounds__(1024) void scan_offsets(const int* __restrict__ cnt,
                                                     int* __restrict__ off,
                                                     int* __restrict__ cur)
{
    __shared__ int tmp[1024];
    __shared__ int carry_s;
    if (threadIdx.x == 0) carry_s = 0;
    __syncthreads();
    for (int base = 0; base < NN; base += 1024) {
        int i = base + threadIdx.x;
        int v = (i < NN) ? cnt[i] : 0;
        tmp[threadIdx.x] = v;
        __syncthreads();
        #pragma unroll
        for (int s = 1; s < 1024; s <<= 1) {
            int t = (threadIdx.x >= s) ? tmp[threadIdx.x - s] : 0;
            __syncthreads();
            tmp[threadIdx.x] += t;
            __syncthreads();
        }
        int carry = carry_s;
        int excl = carry + tmp[threadIdx.x] - v;
        if (i < NN) { off[i] = excl; cur[i] = excl; }
        __syncthreads();
        if (threadIdx.x == 1023) carry_s = carry + tmp[1023];
        __syncthreads();
    }
    if (threadIdx.x == 0) off[NN] = carry_s;
}

__global__ void scatter_csr(const int* __restrict__ src, const int* __restrict__ dst,
                            int* __restrict__ cur, int* __restrict__ csrc)
{
    int i = blockIdx.x * blockDim.x + threadIdx.x;
    if (i >= EE) return;
    int pos = atomicAdd(&cur[dst[i]], 1);
    csrc[pos] = src[i];
}

// ---------------- fused attention gather: one warp per dst node ----------------
// lane L: head h = L>>4? no: h = L>>2 (0..7), sub = L&3, dims h*32 + sub*8 .. +8
__global__ __launch_bounds__(256) void attn_gather(
    const int* __restrict__ off, const int* __restrict__ csrc,
    const float* __restrict__ q, const float* __restrict__ k,
    const float* __restrict__ v, float* __restrict__ agg)
{
    int node = (blockIdx.x * blockDim.x + threadIdx.x) >> 5;
    int lane = threadIdx.x & 31;
    if (node >= NN) return;
    const int h = lane >> 2;
    const int sub = lane & 3;
    const int doff = h * 32 + sub * 8;   // this lane's 8 dims

    int beg = off[node], end = off[node + 1];

    float4 q0 = *reinterpret_cast<const float4*>(&q[(size_t)node * DD + doff]);
    float4 q1 = *reinterpret_cast<const float4*>(&q[(size_t)node * DD + doff + 4]);

    float m = -INFINITY, z = 0.f;
    float acc[8];
    #pragma unroll
    for (int j = 0; j < 8; j++) acc[j] = 0.f;

    const float scale = 0.17677669529663687f; // 1/sqrt(32)

    for (int p = beg; p < end; p++) {
        int s = csrc[p];
        const float* kr = k + (size_t)s * DD + doff;
        const float* vr = v + (size_t)s * DD + doff;
        float4 k0 = *reinterpret_cast<const float4*>(kr);
        float4 k1 = *reinterpret_cast<const float4*>(kr + 4);
        float4 v0 = *reinterpret_cast<const float4*>(vr);
        float4 v1 = *reinterpret_cast<const float4*>(vr + 4);

        float part = q0.x * k0.x + q0.y * k0.y + q0.z * k0.z + q0.w * k0.w
                   + q1.x * k1.x + q1.y * k1.y + q1.z * k1.z + q1.w * k1.w;
        // reduce over the 4 lanes of this head
        part += __shfl_xor_sync(0xffffffffu, part, 1);
        part += __shfl_xor_sync(0xffffffffu, part, 2);

        float logit = part * scale;
        float nm = fmaxf(m, logit);
        float f = __expf(m - nm);
        float a = __expf(logit - nm);
        z = z * f + a;
        m = nm;
        acc[0] = acc[0] * f + a * v0.x;
        acc[1] = acc[1] * f + a * v0.y;
        acc[2] = acc[2] * f + a * v0.z;
        acc[3] = acc[3] * f + a * v0.w;
        acc[4] = acc[4] * f + a * v1.x;
        acc[5] = acc[5] * f + a * v1.y;
        acc[6] = acc[6] * f + a * v1.z;
        acc[7] = acc[7] * f + a * v1.w;
    }

    float inv = 1.f / (z + 1e-9f);
    float4 o0 = make_float4(acc[0] * inv, acc[1] * inv, acc[2] * inv, acc[3] * inv);
    float4 o1 = make_float4(acc[4] * inv, acc[5] * inv, acc[6] * inv, acc[7] * inv);
    if (end == beg) { o0 = make_float4(0.f, 0.f, 0.f, 0.f); o1 = o0; }
    *reinterpret_cast<float4*>(&agg[(size_t)node * DD + doff]) = o0;
    *reinterpret_cast<float4*>(&agg[(size_t)node * DD + doff + 4]) = o1;
}

// ---------------- residual + layernorm: one warp per row ----------------
__global__ void ln_residual(const float* __restrict__ attn, float* __restrict__ h,
                            const float* __restrict__ gamma, const float* __restrict__ beta)
{
    int row = (blockIdx.x * blockDim.x + threadIdx.x) >> 5;
    int lane = threadIdx.x & 31;
    if (row >= NN) return;
    float x[8];
    float s = 0.f;
    #pragma unroll
    for (int j = 0; j < 8; j++) {
        x[j] = attn[(size_t)row * DD + j * 32 + lane] + h[(size_t)row * DD + j * 32 + lane];
        s += x[j];
    }
    #pragma unroll
    for (int off = 16; off; off >>= 1) s += __shfl_xor_sync(0xffffffffu, s, off);
    float mu = s * (1.f / DD);
    float vs = 0.f;
    #pragma unroll
    for (int j = 0; j < 8; j++) { float dlt = x[j] - mu; vs += dlt * dlt; }
    #pragma unroll
    for (int off = 16; off; off >>= 1) vs += __shfl_xor_sync(0xffffffffu, vs, off);
    float inv = rsqrtf(vs * (1.f / DD) + 1e-5f);
    #pragma unroll
    for (int j = 0; j < 8; j++) {
        int c = j * 32 + lane;
        h[(size_t)row * DD + c] = (x[j] - mu) * inv * gamma[c] + beta[c];
    }
}

// ---------------- launch ----------------
extern "C" void kernel_launch(void* const* d_in, const int* in_sizes, int n_in,
                              void* d_out, int out_size)
{
    const float* h_in = (const float*)d_in[0];
    const int* src = (const int*)d_in[1];
    const int* dst = (const int*)d_in[2];
    const float* Wq = (const float*)d_in[3];
    const float* Wk = (const float*)d_in[4];
    const float* Wv = (const float*)d_in[5];
    const float* Wo = (const float*)d_in[6];
    const float* ln_g = (const float*)d_in[7];
    const float* ln_b = (const float*)d_in[8];
    const float* w1 = (const float*)d_in[9];
    const float* b1 = (const float*)d_in[10];
    const float* w2 = (const float*)d_in[11];
    const float* b2 = (const float*)d_in[12];
    float* out = (float*)d_out;

    float *pq, *pk, *pv, *pagg, *ph, *pattn, *pffn;
    int *pcnt, *poff, *pcur, *pcsrc;
    cudaGetSymbolAddress((void**)&pq, g_q);
    cudaGetSymbolAddress((void**)&pk, g_k);
    cudaGetSymbolAddress((void**)&pv, g_v);
    cudaGetSymbolAddress((void**)&pagg, g_agg);
    cudaGetSymbolAddress((void**)&ph, g_h);
    cudaGetSymbolAddress((void**)&pattn, g_attn);
    cudaGetSymbolAddress((void**)&pffn, g_ffn);
    cudaGetSymbolAddress((void**)&pcnt, g_cnt);
    cudaGetSymbolAddress((void**)&poff, g_off);
    cudaGetSymbolAddress((void**)&pcur, g_cur);
    cudaGetSymbolAddress((void**)&pcsrc, g_csrc);

    cudaMemcpyAsync(ph, h_in, (size_t)NN * DD * sizeof(float), cudaMemcpyDeviceToDevice);

    // CSR build (once; reused by both layers)
    zero_cnt<<<(NN + 255) / 256, 256>>>(pcnt);
    hist_dst<<<(EE + 255) / 256, 256>>>(dst, pcnt);
    scan_offsets<<<1, 1024>>>(pcnt, poff, pcur);
    scatter_csr<<<(EE + 255) / 256, 256>>>(src, dst, pcur, pcsrc);

    dim3 grid_d(DD / 128, (NN + 127) / 128);
    dim3 grid_hus(HUSZ / 128, (NN + 127) / 128);

    for (int l = 0; l < LL; l++) {
        const float* wq = Wq + (size_t)l * DD * DD;
        const float* wk = Wk + (size_t)l * DD * DD;
        const float* wv = Wv + (size_t)l * DD * DD;
        const float* wo = Wo + (size_t)l * DD * DD;
        const float* lg = ln_g + (size_t)l * DD;
        const float* lb = ln_b + (size_t)l * DD;

        gemm_tc<<<grid_d, 256>>>(ph, wq, nullptr, pq, NN, DD, DD, 0);
        gemm_tc<<<grid_d, 256>>>(ph, wk, nullptr, pk, NN, DD, DD, 0);
        gemm_tc<<<grid_d, 256>>>(ph, wv, nullptr, pv, NN, DD, DD, 0);

        attn_gather<<<(NN * 32 + 255) / 256, 256>>>(poff, pcsrc, pq, pk, pv, pagg);

        gemm_tc<<<grid_d, 256>>>(pagg, wo, nullptr, pattn, NN, DD, DD, 0);
        ln_residual<<<(NN * 32 + 255) / 256, 256>>>(pattn, ph, lg, lb);
    }

    gemm_tc<<<grid_hus, 256>>>(ph, w1, b1, pffn, NN, HUSZ, DD, 1);
    gemm_tc<<<grid_d, 256>>>(pffn, w2, b2, out, NN, DD, HUSZ, 0);
}

// round 4
// speedup vs baseline: 3.5600x; 1.2319x over previous
#include <cuda_runtime.h>
#include <math.h>

#define NN 20000
#define EE 320000
#define DD 256
#define HH 8
#define LL 2
#define HUSZ 1024
#define QKVW 768   // fused q|k|v width

// ---------------- scratch (no allocation allowed) ----------------
__device__ float g_qkv[NN * QKVW];         // fused q|k|v activations
__device__ float g_wqkv[LL * DD * QKVW];   // fused weights per layer
__device__ float g_agg[NN * DD];
__device__ float g_h[NN * DD];
__device__ float g_attn[NN * DD];
__device__ float g_ffn[NN * HUSZ];
__device__ int   g_cnt[NN];
__device__ int   g_off[NN + 1];
__device__ int   g_cur[NN];
__device__ int   g_csrc[EE];

// ---------------- helpers ----------------
__device__ __forceinline__ unsigned f2tf32(float x) {
    unsigned r;
    asm("cvt.rna.tf32.f32 %0, %1;" : "=r"(r) : "f"(x));
    return r;
}

__device__ __forceinline__ void cp16(float* smem_ptr, const float* gptr, bool p) {
    unsigned s = (unsigned)__cvta_generic_to_shared(smem_ptr);
    int bytes = p ? 16 : 0;
    asm volatile("cp.async.cg.shared.global [%0], [%1], 16, %2;\n"
                 :: "r"(s), "l"(gptr), "r"(bytes));
}
__device__ __forceinline__ void cp_commit() { asm volatile("cp.async.commit_group;\n" ::: "memory"); }
template <int N>
__device__ __forceinline__ void cp_wait() { asm volatile("cp.async.wait_group %0;\n" :: "n"(N) : "memory"); }

// ---------------- tf32 tensor-core GEMM, cp.async double-buffered ----------------
// C[M,Nc] = A[M,Kc] @ B[Kc,Nc] (+bias)(relu). Block 128x128, BK=32, 8 warps.
#define AS_PAD 36
#define BS_PAD 136
#define A_STAGE (128 * AS_PAD)
#define B_STAGE (32 * BS_PAD)
#define GEMM_SMEM ((2 * (A_STAGE + B_STAGE)) * sizeof(float))

__global__ __launch_bounds__(256) void gemm_tc(
    const float* __restrict__ A, const float* __restrict__ B,
    const float* __restrict__ bias, float* __restrict__ C,
    int M, int Nc, int Kc, int relu)
{
    extern __shared__ float sm[];
    float* As = sm;                    // 2 stages
    float* Bs = sm + 2 * A_STAGE;      // 2 stages

    const int tid = threadIdx.x;
    const int wid = tid >> 5;
    const int lane = tid & 31;
    const int g = lane >> 2;
    const int t = lane & 3;

    const int warp_m = wid >> 2;
    const int warp_n = wid & 3;
    const int row0 = blockIdx.y * 128;
    const int col0 = blockIdx.x * 128;

    const int a_r = tid >> 3;          // 0..31
    const int a_c = (tid & 7) * 4;     // 0..28
    const int b_r = tid >> 5;          // 0..7
    const int b_c = (tid & 31) * 4;    // 0..124

    float acc[4][4][4];
    #pragma unroll
    for (int mi = 0; mi < 4; mi++)
        #pragma unroll
        for (int ni = 0; ni < 4; ni++)
            #pragma unroll
            for (int r = 0; r < 4; r++) acc[mi][ni][r] = 0.f;

    const int ntiles = Kc >> 5;

    // ---- stage loader ----
    auto load_stage = [&](int st, int k0) {
        float* as = As + st * A_STAGE;
        float* bs = Bs + st * B_STAGE;
        #pragma unroll
        for (int i = 0; i < 4; i++) {
            int r = i * 32 + a_r;
            cp16(&as[r * AS_PAD + a_c],
                 &A[(size_t)(row0 + r) * Kc + k0 + a_c],
                 row0 + r < M);
        }
        #pragma unroll
        for (int i = 0; i < 4; i++) {
            int r = i * 8 + b_r;
            cp16(&bs[r * BS_PAD + b_c],
                 &B[(size_t)(k0 + r) * Nc + col0 + b_c],
                 true);
        }
    };

    load_stage(0, 0);
    cp_commit();

    for (int kt = 0; kt < ntiles; kt++) {
        if (kt + 1 < ntiles) load_stage((kt + 1) & 1, (kt + 1) * 32);
        cp_commit();
        cp_wait<1>();
        __syncthreads();

        const float* as = As + (kt & 1) * A_STAGE;
        const float* bs = Bs + (kt & 1) * B_STAGE;

        #pragma unroll
        for (int ks = 0; ks < 4; ks++) {
            const int kk = ks * 8;
            unsigned af[4][4];
            #pragma unroll
            for (int mi = 0; mi < 4; mi++) {
                int rb = warp_m * 64 + mi * 16;
                const float* ap = &as[(rb + g) * AS_PAD + kk + t];
                af[mi][0] = f2tf32(ap[0]);
                af[mi][1] = f2tf32(ap[8 * AS_PAD]);
                af[mi][2] = f2tf32(ap[4]);
                af[mi][3] = f2tf32(ap[8 * AS_PAD + 4]);
            }
            unsigned bf[4][2];
            #pragma unroll
            for (int ni = 0; ni < 4; ni++) {
                int nb = warp_n * 32 + ni * 8;
                const float* bp = &bs[(kk + t) * BS_PAD + nb + g];
                bf[ni][0] = f2tf32(bp[0]);
                bf[ni][1] = f2tf32(bp[4 * BS_PAD]);
            }
            #pragma unroll
            for (int mi = 0; mi < 4; mi++)
                #pragma unroll
                for (int ni = 0; ni < 4; ni++) {
                    asm volatile(
                        "mma.sync.aligned.m16n8k8.row.col.f32.tf32.tf32.f32 "
                        "{%0,%1,%2,%3}, {%4,%5,%6,%7}, {%8,%9}, {%0,%1,%2,%3};"
                        : "+f"(acc[mi][ni][0]), "+f"(acc[mi][ni][1]),
                          "+f"(acc[mi][ni][2]), "+f"(acc[mi][ni][3])
                        : "r"(af[mi][0]), "r"(af[mi][1]), "r"(af[mi][2]), "r"(af[mi][3]),
                          "r"(bf[ni][0]), "r"(bf[ni][1]));
                }
        }
        __syncthreads();
    }

    #pragma unroll
    for (int mi = 0; mi < 4; mi++) {
        int rb = row0 + warp_m * 64 + mi * 16 + g;
        #pragma unroll
        for (int ni = 0; ni < 4; ni++) {
            int cb = col0 + warp_n * 32 + ni * 8 + 2 * t;
            #pragma unroll
            for (int half = 0; half < 2; half++) {
                int r = rb + half * 8;
                if (r >= M) continue;
                float v0 = acc[mi][ni][half * 2 + 0];
                float v1 = acc[mi][ni][half * 2 + 1];
                if (bias) { v0 += bias[cb]; v1 += bias[cb + 1]; }
                if (relu) { v0 = fmaxf(v0, 0.f); v1 = fmaxf(v1, 0.f); }
                *reinterpret_cast<float2*>(&C[(size_t)r * Nc + cb]) = make_float2(v0, v1);
            }
        }
    }
}

// ---------------- weight repack: Wq|Wk|Wv -> [L][D][768] ----------------
__global__ void repack_w(const float* __restrict__ Wq, const float* __restrict__ Wk,
                         const float* __restrict__ Wv, float* __restrict__ out)
{
    int i = blockIdx.x * blockDim.x + threadIdx.x;
    if (i >= LL * DD * QKVW) return;
    int c = i % QKVW;
    int d = (i / QKVW) % DD;
    int l = i / (QKVW * DD);
    float v;
    if (c < 256)      v = Wq[(size_t)l * DD * DD + d * DD + c];
    else if (c < 512) v = Wk[(size_t)l * DD * DD + d * DD + (c - 256)];
    else              v = Wv[(size_t)l * DD * DD + d * DD + (c - 512)];
    out[i] = v;
}

// ---------------- CSR build ----------------
__global__ void hist_dst(const int* __restrict__ dst, int* __restrict__ cnt)
{
    int i = blockIdx.x * blockDim.x + threadIdx.x;
    if (i < EE) atomicAdd(&cnt[dst[i]], 1);
}

// single-block shfl-based exclusive scan
__global__ __launch_bounds__(1024) void scan_offsets(const int* __restrict__ cnt,
                                                     int* __restrict__ off,
                                                     int* __restrict__ cur)
{
    __shared__ int wsum[32];
    __shared__ int carry_s;
    const int lane = threadIdx.x & 31;
    const int wid = threadIdx.x >> 5;
    if (threadIdx.x == 0) carry_s = 0;
    __syncthreads();
    for (int base = 0; base < NN; base += 1024) {
        int i = base + threadIdx.x;
        int v = (i < NN) ? cnt[i] : 0;
        // warp inclusive scan
        int x = v;
        #pragma unroll
        for (int s = 1; s < 32; s <<= 1) {
            int t = __shfl_up_sync(0xffffffffu, x, s);
            if (lane >= s) x += t;
        }
        if (lane == 31) wsum[wid] = x;
        __syncthreads();
        if (wid == 0) {
            int w = wsum[lane];
            #pragma unroll
            for (int s = 1; s < 32; s <<= 1) {
                int t = __shfl_up_sync(0xffffffffu, w, s);
                if (lane >= s) w += t;
            }
            wsum[lane] = w;
        }
        __syncthreads();
        int warp_prefix = (wid > 0) ? wsum[wid - 1] : 0;
        int carry = carry_s;
        int excl = carry + warp_prefix + x - v;
        if (i < NN) { off[i] = excl; cur[i] = excl; }
        __syncthreads();
        if (threadIdx.x == 1023) carry_s = carry + wsum[31];
        __syncthreads();
    }
    if (threadIdx.x == 0) off[NN] = carry_s;
}

__global__ void scatter_csr(const int* __restrict__ src, const int* __restrict__ dst,
                            int* __restrict__ cur, int* __restrict__ csrc)
{
    int i = blockIdx.x * blockDim.x + threadIdx.x;
    if (i >= EE) return;
    int pos = atomicAdd(&cur[dst[i]], 1);
    csrc[pos] = src[i];
}

// ---------------- fused attention gather: one warp per dst node ----------------
// qkv layout [NN, 768]: q at +0, k at +256, v at +512
__global__ __launch_bounds__(256) void attn_gather(
    const int* __restrict__ off, const int* __restrict__ csrc,
    const float* __restrict__ qkv, float* __restrict__ agg)
{
    int node = (blockIdx.x * blockDim.x + threadIdx.x) >> 5;
    int lane = threadIdx.x & 31;
    if (node >= NN) return;
    const int h = lane >> 2;
    const int sub = lane & 3;
    const int doff = h * 32 + sub * 8;

    int beg = off[node], end = off[node + 1];

    const float* qr = qkv + (size_t)node * QKVW + doff;
    float4 q0 = *reinterpret_cast<const float4*>(qr);
    float4 q1 = *reinterpret_cast<const float4*>(qr + 4);

    float m = -INFINITY, z = 0.f;
    float acc[8];
    #pragma unroll
    for (int j = 0; j < 8; j++) acc[j] = 0.f;

    const float scale = 0.17677669529663687f;

    for (int p = beg; p < end; p++) {
        int s = csrc[p];
        const float* kr = qkv + (size_t)s * QKVW + 256 + doff;
        const float* vr = qkv + (size_t)s * QKVW + 512 + doff;
        float4 k0 = *reinterpret_cast<const float4*>(kr);
        float4 k1 = *reinterpret_cast<const float4*>(kr + 4);
        float4 v0 = *reinterpret_cast<const float4*>(vr);
        float4 v1 = *reinterpret_cast<const float4*>(vr + 4);

        float part = q0.x * k0.x + q0.y * k0.y + q0.z * k0.z + q0.w * k0.w
                   + q1.x * k1.x + q1.y * k1.y + q1.z * k1.z + q1.w * k1.w;
        part += __shfl_xor_sync(0xffffffffu, part, 1);
        part += __shfl_xor_sync(0xffffffffu, part, 2);

        float logit = part * scale;
        float nm = fmaxf(m, logit);
        float f = __expf(m - nm);
        float a = __expf(logit - nm);
        z = z * f + a;
        m = nm;
        acc[0] = acc[0] * f + a * v0.x;
        acc[1] = acc[1] * f + a * v0.y;
        acc[2] = acc[2] * f + a * v0.z;
        acc[3] = acc[3] * f + a * v0.w;
        acc[4] = acc[4] * f + a * v1.x;
        acc[5] = acc[5] * f + a * v1.y;
        acc[6] = acc[6] * f + a * v1.z;
        acc[7] = acc[7] * f + a * v1.w;
    }

    float inv = 1.f / (z + 1e-9f);
    float4 o0 = make_float4(acc[0] * inv, acc[1] * inv, acc[2] * inv, acc[3] * inv);
    float4 o1 = make_float4(acc[4] * inv, acc[5] * inv, acc[6] * inv, acc[7] * inv);
    if (end == beg) { o0 = make_float4(0.f, 0.f, 0.f, 0.f); o1 = o0; }
    *reinterpret_cast<float4*>(&agg[(size_t)node * DD + doff]) = o0;
    *reinterpret_cast<float4*>(&agg[(size_t)node * DD + doff + 4]) = o1;
}

// ---------------- residual + layernorm: one warp per row ----------------
__global__ void ln_residual(const float* __restrict__ attn, float* __restrict__ h,
                            const float* __restrict__ gamma, const float* __restrict__ beta)
{
    int row = (blockIdx.x * blockDim.x + threadIdx.x) >> 5;
    int lane = threadIdx.x & 31;
    if (row >= NN) return;
    float x[8];
    float s = 0.f;
    #pragma unroll
    for (int j = 0; j < 8; j++) {
        x[j] = attn[(size_t)row * DD + j * 32 + lane] + h[(size_t)row * DD + j * 32 + lane];
        s += x[j];
    }
    #pragma unroll
    for (int off = 16; off; off >>= 1) s += __shfl_xor_sync(0xffffffffu, s, off);
    float mu = s * (1.f / DD);
    float vs = 0.f;
    #pragma unroll
    for (int j = 0; j < 8; j++) { float dlt = x[j] - mu; vs += dlt * dlt; }
    #pragma unroll
    for (int off = 16; off; off >>= 1) vs += __shfl_xor_sync(0xffffffffu, vs, off);
    float inv = rsqrtf(vs * (1.f / DD) + 1e-5f);
    #pragma unroll
    for (int j = 0; j < 8; j++) {
        int c = j * 32 + lane;
        h[(size_t)row * DD + c] = (x[j] - mu) * inv * gamma[c] + beta[c];
    }
}

// ---------------- launch ----------------
extern "C" void kernel_launch(void* const* d_in, const int* in_sizes, int n_in,
                              void* d_out, int out_size)
{
    const float* h_in = (const float*)d_in[0];
    const int* src = (const int*)d_in[1];
    const int* dst = (const int*)d_in[2];
    const float* Wq = (const float*)d_in[3];
    const float* Wk = (const float*)d_in[4];
    const float* Wv = (const float*)d_in[5];
    const float* Wo = (const float*)d_in[6];
    const float* ln_g = (const float*)d_in[7];
    const float* ln_b = (const float*)d_in[8];
    const float* w1 = (const float*)d_in[9];
    const float* b1 = (const float*)d_in[10];
    const float* w2 = (const float*)d_in[11];
    const float* b2 = (const float*)d_in[12];
    float* out = (float*)d_out;

    float *pqkv, *pwqkv, *pagg, *ph, *pattn, *pffn;
    int *pcnt, *poff, *pcur, *pcsrc;
    cudaGetSymbolAddress((void**)&pqkv, g_qkv);
    cudaGetSymbolAddress((void**)&pwqkv, g_wqkv);
    cudaGetSymbolAddress((void**)&pagg, g_agg);
    cudaGetSymbolAddress((void**)&ph, g_h);
    cudaGetSymbolAddress((void**)&pattn, g_attn);
    cudaGetSymbolAddress((void**)&pffn, g_ffn);
    cudaGetSymbolAddress((void**)&pcnt, g_cnt);
    cudaGetSymbolAddress((void**)&poff, g_off);
    cudaGetSymbolAddress((void**)&pcur, g_cur);
    cudaGetSymbolAddress((void**)&pcsrc, g_csrc);

    static bool smem_set = false;
    if (!smem_set) {
        cudaFuncSetAttribute(gemm_tc, cudaFuncAttributeMaxDynamicSharedMemorySize, GEMM_SMEM);
        smem_set = true;
    }

    cudaMemcpyAsync(ph, h_in, (size_t)NN * DD * sizeof(float), cudaMemcpyDeviceToDevice);
    cudaMemsetAsync(pcnt, 0, NN * sizeof(int));

    repack_w<<<(LL * DD * QKVW + 255) / 256, 256>>>(Wq, Wk, Wv, pwqkv);

    hist_dst<<<(EE + 255) / 256, 256>>>(dst, pcnt);
    scan_offsets<<<1, 1024>>>(pcnt, poff, pcur);
    scatter_csr<<<(EE + 255) / 256, 256>>>(src, dst, pcur, pcsrc);

    dim3 grid_qkv(QKVW / 128, (NN + 127) / 128);
    dim3 grid_d(DD / 128, (NN + 127) / 128);
    dim3 grid_hus(HUSZ / 128, (NN + 127) / 128);

    for (int l = 0; l < LL; l++) {
        const float* wqkv = pwqkv + (size_t)l * DD * QKVW;
        const float* wo = Wo + (size_t)l * DD * DD;
        const float* lg = ln_g + (size_t)l * DD;
        const float* lb = ln_b + (size_t)l * DD;

        gemm_tc<<<grid_qkv, 256, GEMM_SMEM>>>(ph, wqkv, nullptr, pqkv, NN, QKVW, DD, 0);
        attn_gather<<<(NN * 32 + 255) / 256, 256>>>(poff, pcsrc, pqkv, pagg);
        gemm_tc<<<grid_d, 256, GEMM_SMEM>>>(pagg, wo, nullptr, pattn, NN, DD, DD, 0);
        ln_residual<<<(NN * 32 + 255) / 256, 256>>>(pattn, ph, lg, lb);
    }

    gemm_tc<<<grid_hus, 256, GEMM_SMEM>>>(ph, w1, b1, pffn, NN, HUSZ, DD, 1);
    gemm_tc<<<grid_d, 256, GEMM_SMEM>>>(pffn, w2, b2, out, NN, DD, HUSZ, 0);
}

// round 5
// speedup vs baseline: 3.7401x; 1.0506x over previous
#include <cuda_runtime.h>
#include <math.h>

#define NN 20000
#define EE 320000
#define DD 256
#define HH 8
#define LL 2
#define HUSZ 1024
#define QKVW 768   // fused q|k|v width

// ---------------- scratch (no allocation allowed) ----------------
__device__ float g_qkv[NN * QKVW];         // fused q|k|v activations
__device__ float g_wqkv[LL * DD * QKVW];   // fused weights per layer
__device__ float g_agg[NN * DD];
__device__ float g_h[NN * DD];
__device__ float g_attn[NN * DD];
__device__ float g_ffn[NN * HUSZ];
__device__ int   g_cnt[NN];
__device__ int   g_off[NN + 1];
__device__ int   g_cur[NN];
__device__ int   g_csrc[EE];

// ---------------- helpers ----------------
__device__ __forceinline__ unsigned f2tf32(float x) {
    unsigned r;
    asm("cvt.rna.tf32.f32 %0, %1;" : "=r"(r) : "f"(x));
    return r;
}

__device__ __forceinline__ void cp16(float* smem_ptr, const float* gptr, bool p) {
    unsigned s = (unsigned)__cvta_generic_to_shared(smem_ptr);
    int bytes = p ? 16 : 0;
    asm volatile("cp.async.cg.shared.global [%0], [%1], 16, %2;\n"
                 :: "r"(s), "l"(gptr), "r"(bytes));
}
__device__ __forceinline__ void cp_commit() { asm volatile("cp.async.commit_group;\n" ::: "memory"); }
template <int N>
__device__ __forceinline__ void cp_wait() { asm volatile("cp.async.wait_group %0;\n" :: "n"(N) : "memory"); }

// ---------------- tf32 tensor-core GEMM, cp.async double-buffered ----------------
#define AS_PAD 36
#define BS_PAD 136
#define A_STAGE (128 * AS_PAD)
#define B_STAGE (32 * BS_PAD)
#define GEMM_SMEM ((2 * (A_STAGE + B_STAGE)) * sizeof(float))

__global__ __launch_bounds__(256) void gemm_tc(
    const float* __restrict__ A, const float* __restrict__ B,
    const float* __restrict__ bias, float* __restrict__ C,
    int M, int Nc, int Kc, int relu)
{
    extern __shared__ float sm[];
    float* As = sm;
    float* Bs = sm + 2 * A_STAGE;

    const int tid = threadIdx.x;
    const int wid = tid >> 5;
    const int lane = tid & 31;
    const int g = lane >> 2;
    const int t = lane & 3;

    const int warp_m = wid >> 2;
    const int warp_n = wid & 3;
    const int row0 = blockIdx.y * 128;
    const int col0 = blockIdx.x * 128;

    const int a_r = tid >> 3;
    const int a_c = (tid & 7) * 4;
    const int b_r = tid >> 5;
    const int b_c = (tid & 31) * 4;

    float acc[4][4][4];
    #pragma unroll
    for (int mi = 0; mi < 4; mi++)
        #pragma unroll
        for (int ni = 0; ni < 4; ni++)
            #pragma unroll
            for (int r = 0; r < 4; r++) acc[mi][ni][r] = 0.f;

    const int ntiles = Kc >> 5;

    auto load_stage = [&](int st, int k0) {
        float* as = As + st * A_STAGE;
        float* bs = Bs + st * B_STAGE;
        #pragma unroll
        for (int i = 0; i < 4; i++) {
            int r = i * 32 + a_r;
            cp16(&as[r * AS_PAD + a_c],
                 &A[(size_t)(row0 + r) * Kc + k0 + a_c],
                 row0 + r < M);
        }
        #pragma unroll
        for (int i = 0; i < 4; i++) {
            int r = i * 8 + b_r;
            cp16(&bs[r * BS_PAD + b_c],
                 &B[(size_t)(k0 + r) * Nc + col0 + b_c],
                 true);
        }
    };

    load_stage(0, 0);
    cp_commit();

    for (int kt = 0; kt < ntiles; kt++) {
        if (kt + 1 < ntiles) load_stage((kt + 1) & 1, (kt + 1) * 32);
        cp_commit();
        cp_wait<1>();
        __syncthreads();

        const float* as = As + (kt & 1) * A_STAGE;
        const float* bs = Bs + (kt & 1) * B_STAGE;

        #pragma unroll
        for (int ks = 0; ks < 4; ks++) {
            const int kk = ks * 8;
            unsigned af[4][4];
            #pragma unroll
            for (int mi = 0; mi < 4; mi++) {
                int rb = warp_m * 64 + mi * 16;
                const float* ap = &as[(rb + g) * AS_PAD + kk + t];
                af[mi][0] = f2tf32(ap[0]);
                af[mi][1] = f2tf32(ap[8 * AS_PAD]);
                af[mi][2] = f2tf32(ap[4]);
                af[mi][3] = f2tf32(ap[8 * AS_PAD + 4]);
            }
            unsigned bf[4][2];
            #pragma unroll
            for (int ni = 0; ni < 4; ni++) {
                int nb = warp_n * 32 + ni * 8;
                const float* bp = &bs[(kk + t) * BS_PAD + nb + g];
                bf[ni][0] = f2tf32(bp[0]);
                bf[ni][1] = f2tf32(bp[4 * BS_PAD]);
            }
            #pragma unroll
            for (int mi = 0; mi < 4; mi++)
                #pragma unroll
                for (int ni = 0; ni < 4; ni++) {
                    asm volatile(
                        "mma.sync.aligned.m16n8k8.row.col.f32.tf32.tf32.f32 "
                        "{%0,%1,%2,%3}, {%4,%5,%6,%7}, {%8,%9}, {%0,%1,%2,%3};"
                        : "+f"(acc[mi][ni][0]), "+f"(acc[mi][ni][1]),
                          "+f"(acc[mi][ni][2]), "+f"(acc[mi][ni][3])
                        : "r"(af[mi][0]), "r"(af[mi][1]), "r"(af[mi][2]), "r"(af[mi][3]),
                          "r"(bf[ni][0]), "r"(bf[ni][1]));
                }
        }
        __syncthreads();
    }

    #pragma unroll
    for (int mi = 0; mi < 4; mi++) {
        int rb = row0 + warp_m * 64 + mi * 16 + g;
        #pragma unroll
        for (int ni = 0; ni < 4; ni++) {
            int cb = col0 + warp_n * 32 + ni * 8 + 2 * t;
            #pragma unroll
            for (int half = 0; half < 2; half++) {
                int r = rb + half * 8;
                if (r >= M) continue;
                float v0 = acc[mi][ni][half * 2 + 0];
                float v1 = acc[mi][ni][half * 2 + 1];
                if (bias) { v0 += bias[cb]; v1 += bias[cb + 1]; }
                if (relu) { v0 = fmaxf(v0, 0.f); v1 = fmaxf(v1, 0.f); }
                *reinterpret_cast<float2*>(&C[(size_t)r * Nc + cb]) = make_float2(v0, v1);
            }
        }
    }
}

// ---------------- weight repack: Wq|Wk|Wv -> [L][D][768] ----------------
__global__ void repack_w(const float* __restrict__ Wq, const float* __restrict__ Wk,
                         const float* __restrict__ Wv, float* __restrict__ out)
{
    int i = blockIdx.x * blockDim.x + threadIdx.x;
    if (i >= LL * DD * QKVW) return;
    int c = i % QKVW;
    int d = (i / QKVW) % DD;
    int l = i / (QKVW * DD);
    float v;
    if (c < 256)      v = Wq[(size_t)l * DD * DD + d * DD + c];
    else if (c < 512) v = Wk[(size_t)l * DD * DD + d * DD + (c - 256)];
    else              v = Wv[(size_t)l * DD * DD + d * DD + (c - 512)];
    out[i] = v;
}

// ---------------- CSR build ----------------
__global__ void hist_dst(const int* __restrict__ dst, int* __restrict__ cnt)
{
    int i = blockIdx.x * blockDim.x + threadIdx.x;
    if (i < EE) atomicAdd(&cnt[dst[i]], 1);
}

__global__ __launch_bounds__(1024) void scan_offsets(const int* __restrict__ cnt,
                                                     int* __restrict__ off,
                                                     int* __restrict__ cur)
{
    __shared__ int wsum[32];
    __shared__ int carry_s;
    const int lane = threadIdx.x & 31;
    const int wid = threadIdx.x >> 5;
    if (threadIdx.x == 0) carry_s = 0;
    __syncthreads();
    for (int base = 0; base < NN; base += 1024) {
        int i = base + threadIdx.x;
        int v = (i < NN) ? cnt[i] : 0;
        int x = v;
        #pragma unroll
        for (int s = 1; s < 32; s <<= 1) {
            int t = __shfl_up_sync(0xffffffffu, x, s);
            if (lane >= s) x += t;
        }
        if (lane == 31) wsum[wid] = x;
        __syncthreads();
        if (wid == 0) {
            int w = wsum[lane];
            #pragma unroll
            for (int s = 1; s < 32; s <<= 1) {
                int t = __shfl_up_sync(0xffffffffu, w, s);
                if (lane >= s) w += t;
            }
            wsum[lane] = w;
        }
        __syncthreads();
        int warp_prefix = (wid > 0) ? wsum[wid - 1] : 0;
        int carry = carry_s;
        int excl = carry + warp_prefix + x - v;
        if (i < NN) { off[i] = excl; cur[i] = excl; }
        __syncthreads();
        if (threadIdx.x == 1023) carry_s = carry + wsum[31];
        __syncthreads();
    }
    if (threadIdx.x == 0) off[NN] = carry_s;
}

__global__ void scatter_csr(const int* __restrict__ src, const int* __restrict__ dst,
                            int* __restrict__ cur, int* __restrict__ csrc)
{
    int i = blockIdx.x * blockDim.x + threadIdx.x;
    if (i >= EE) return;
    int pos = atomicAdd(&cur[dst[i]], 1);
    csrc[pos] = src[i];
}

// ---------------- fused attention gather: one warp per dst node ----------------
// Dual independent online-softmax states (even/odd edges) for 2x memory-level
// parallelism in the latency-bound gather chain; merged at the end.
__global__ __launch_bounds__(256) void attn_gather(
    const int* __restrict__ off, const int* __restrict__ csrc,
    const float* __restrict__ qkv, float* __restrict__ agg)
{
    int node = (blockIdx.x * blockDim.x + threadIdx.x) >> 5;
    int lane = threadIdx.x & 31;
    if (node >= NN) return;
    const int h = lane >> 2;
    const int sub = lane & 3;
    const int doff = h * 32 + sub * 8;

    int beg = off[node], end = off[node + 1];

    const float* qr = qkv + (size_t)node * QKVW + doff;
    float4 q0 = *reinterpret_cast<const float4*>(qr);
    float4 q1 = *reinterpret_cast<const float4*>(qr + 4);

    const float scale = 0.17677669529663687f;

    float mA = -INFINITY, zA = 0.f;
    float mB = -INFINITY, zB = 0.f;
    float accA[8], accB[8];
    #pragma unroll
    for (int j = 0; j < 8; j++) { accA[j] = 0.f; accB[j] = 0.f; }

    int p = beg;
    for (; p + 1 < end; p += 2) {
        int sA = csrc[p];
        int sB = csrc[p + 1];
        const float* krA = qkv + (size_t)sA * QKVW + 256 + doff;
        const float* vrA = qkv + (size_t)sA * QKVW + 512 + doff;
        const float* krB = qkv + (size_t)sB * QKVW + 256 + doff;
        const float* vrB = qkv + (size_t)sB * QKVW + 512 + doff;
        float4 kA0 = *reinterpret_cast<const float4*>(krA);
        float4 kB0 = *reinterpret_cast<const float4*>(krB);
        float4 kA1 = *reinterpret_cast<const float4*>(krA + 4);
        float4 kB1 = *reinterpret_cast<const float4*>(krB + 4);
        float4 vA0 = *reinterpret_cast<const float4*>(vrA);
        float4 vB0 = *reinterpret_cast<const float4*>(vrB);
        float4 vA1 = *reinterpret_cast<const float4*>(vrA + 4);
        float4 vB1 = *reinterpret_cast<const float4*>(vrB + 4);

        float pA = q0.x * kA0.x + q0.y * kA0.y + q0.z * kA0.z + q0.w * kA0.w
                 + q1.x * kA1.x + q1.y * kA1.y + q1.z * kA1.z + q1.w * kA1.w;
        float pB = q0.x * kB0.x + q0.y * kB0.y + q0.z * kB0.z + q0.w * kB0.w
                 + q1.x * kB1.x + q1.y * kB1.y + q1.z * kB1.z + q1.w * kB1.w;
        pA += __shfl_xor_sync(0xffffffffu, pA, 1);
        pB += __shfl_xor_sync(0xffffffffu, pB, 1);
        pA += __shfl_xor_sync(0xffffffffu, pA, 2);
        pB += __shfl_xor_sync(0xffffffffu, pB, 2);

        float lA = pA * scale;
        float lB = pB * scale;

        float nmA = fmaxf(mA, lA);
        float fA = __expf(mA - nmA);
        float aA = __expf(lA - nmA);
        zA = zA * fA + aA;
        mA = nmA;
        accA[0] = accA[0] * fA + aA * vA0.x;
        accA[1] = accA[1] * fA + aA * vA0.y;
        accA[2] = accA[2] * fA + aA * vA0.z;
        accA[3] = accA[3] * fA + aA * vA0.w;
        accA[4] = accA[4] * fA + aA * vA1.x;
        accA[5] = accA[5] * fA + aA * vA1.y;
        accA[6] = accA[6] * fA + aA * vA1.z;
        accA[7] = accA[7] * fA + aA * vA1.w;

        float nmB = fmaxf(mB, lB);
        float fB = __expf(mB - nmB);
        float aB = __expf(lB - nmB);
        zB = zB * fB + aB;
        mB = nmB;
        accB[0] = accB[0] * fB + aB * vB0.x;
        accB[1] = accB[1] * fB + aB * vB0.y;
        accB[2] = accB[2] * fB + aB * vB0.z;
        accB[3] = accB[3] * fB + aB * vB0.w;
        accB[4] = accB[4] * fB + aB * vB1.x;
        accB[5] = accB[5] * fB + aB * vB1.y;
        accB[6] = accB[6] * fB + aB * vB1.z;
        accB[7] = accB[7] * fB + aB * vB1.w;
    }
    if (p < end) {
        int s = csrc[p];
        const float* kr = qkv + (size_t)s * QKVW + 256 + doff;
        const float* vr = qkv + (size_t)s * QKVW + 512 + doff;
        float4 k0 = *reinterpret_cast<const float4*>(kr);
        float4 k1 = *reinterpret_cast<const float4*>(kr + 4);
        float4 v0 = *reinterpret_cast<const float4*>(vr);
        float4 v1 = *reinterpret_cast<const float4*>(vr + 4);
        float part = q0.x * k0.x + q0.y * k0.y + q0.z * k0.z + q0.w * k0.w
                   + q1.x * k1.x + q1.y * k1.y + q1.z * k1.z + q1.w * k1.w;
        part += __shfl_xor_sync(0xffffffffu, part, 1);
        part += __shfl_xor_sync(0xffffffffu, part, 2);
        float logit = part * scale;
        float nm = fmaxf(mA, logit);
        float f = __expf(mA - nm);
        float a = __expf(logit - nm);
        zA = zA * f + a;
        mA = nm;
        accA[0] = accA[0] * f + a * v0.x;
        accA[1] = accA[1] * f + a * v0.y;
        accA[2] = accA[2] * f + a * v0.z;
        accA[3] = accA[3] * f + a * v0.w;
        accA[4] = accA[4] * f + a * v1.x;
        accA[5] = accA[5] * f + a * v1.y;
        accA[6] = accA[6] * f + a * v1.z;
        accA[7] = accA[7] * f + a * v1.w;
    }

    // merge states
    float m = fmaxf(mA, mB);
    float fA = (zA > 0.f) ? __expf(mA - m) : 0.f;
    float fB = (zB > 0.f) ? __expf(mB - m) : 0.f;
    float z = zA * fA + zB * fB;
    float inv = 1.f / (z + 1e-9f);

    float4 o0, o1;
    o0.x = (accA[0] * fA + accB[0] * fB) * inv;
    o0.y = (accA[1] * fA + accB[1] * fB) * inv;
    o0.z = (accA[2] * fA + accB[2] * fB) * inv;
    o0.w = (accA[3] * fA + accB[3] * fB) * inv;
    o1.x = (accA[4] * fA + accB[4] * fB) * inv;
    o1.y = (accA[5] * fA + accB[5] * fB) * inv;
    o1.z = (accA[6] * fA + accB[6] * fB) * inv;
    o1.w = (accA[7] * fA + accB[7] * fB) * inv;
    if (end == beg) { o0 = make_float4(0.f, 0.f, 0.f, 0.f); o1 = o0; }
    *reinterpret_cast<float4*>(&agg[(size_t)node * DD + doff]) = o0;
    *reinterpret_cast<float4*>(&agg[(size_t)node * DD + doff + 4]) = o1;
}

// ---------------- residual + layernorm: one warp per row ----------------
__global__ void ln_residual(const float* __restrict__ attn, float* __restrict__ h,
                            const float* __restrict__ gamma, const float* __restrict__ beta)
{
    int row = (blockIdx.x * blockDim.x + threadIdx.x) >> 5;
    int lane = threadIdx.x & 31;
    if (row >= NN) return;
    float x[8];
    float s = 0.f;
    #pragma unroll
    for (int j = 0; j < 8; j++) {
        x[j] = attn[(size_t)row * DD + j * 32 + lane] + h[(size_t)row * DD + j * 32 + lane];
        s += x[j];
    }
    #pragma unroll
    for (int off = 16; off; off >>= 1) s += __shfl_xor_sync(0xffffffffu, s, off);
    float mu = s * (1.f / DD);
    float vs = 0.f;
    #pragma unroll
    for (int j = 0; j < 8; j++) { float dlt = x[j] - mu; vs += dlt * dlt; }
    #pragma unroll
    for (int off = 16; off; off >>= 1) vs += __shfl_xor_sync(0xffffffffu, vs, off);
    float inv = rsqrtf(vs * (1.f / DD) + 1e-5f);
    #pragma unroll
    for (int j = 0; j < 8; j++) {
        int c = j * 32 + lane;
        h[(size_t)row * DD + c] = (x[j] - mu) * inv * gamma[c] + beta[c];
    }
}

// ---------------- launch ----------------
extern "C" void kernel_launch(void* const* d_in, const int* in_sizes, int n_in,
                              void* d_out, int out_size)
{
    const float* h_in = (const float*)d_in[0];
    const int* src = (const int*)d_in[1];
    const int* dst = (const int*)d_in[2];
    const float* Wq = (const float*)d_in[3];
    const float* Wk = (const float*)d_in[4];
    const float* Wv = (const float*)d_in[5];
    const float* Wo = (const float*)d_in[6];
    const float* ln_g = (const float*)d_in[7];
    const float* ln_b = (const float*)d_in[8];
    const float* w1 = (const float*)d_in[9];
    const float* b1 = (const float*)d_in[10];
    const float* w2 = (const float*)d_in[11];
    const float* b2 = (const float*)d_in[12];
    float* out = (float*)d_out;

    float *pqkv, *pwqkv, *pagg, *ph, *pattn, *pffn;
    int *pcnt, *poff, *pcur, *pcsrc;
    cudaGetSymbolAddress((void**)&pqkv, g_qkv);
    cudaGetSymbolAddress((void**)&pwqkv, g_wqkv);
    cudaGetSymbolAddress((void**)&pagg, g_agg);
    cudaGetSymbolAddress((void**)&ph, g_h);
    cudaGetSymbolAddress((void**)&pattn, g_attn);
    cudaGetSymbolAddress((void**)&pffn, g_ffn);
    cudaGetSymbolAddress((void**)&pcnt, g_cnt);
    cudaGetSymbolAddress((void**)&poff, g_off);
    cudaGetSymbolAddress((void**)&pcur, g_cur);
    cudaGetSymbolAddress((void**)&pcsrc, g_csrc);

    static cudaStream_t s2 = nullptr;
    static cudaEvent_t ev_fork = nullptr, ev_join = nullptr;
    static bool init_done = false;
    if (!init_done) {
        cudaFuncSetAttribute(gemm_tc, cudaFuncAttributeMaxDynamicSharedMemorySize, GEMM_SMEM);
        cudaStreamCreateWithFlags(&s2, cudaStreamNonBlocking);
        cudaEventCreateWithFlags(&ev_fork, cudaEventDisableTiming);
        cudaEventCreateWithFlags(&ev_join, cudaEventDisableTiming);
        init_done = true;
    }

    // fork: CSR build runs on s2 concurrently with repack + first QKV GEMM
    cudaEventRecord(ev_fork, 0);
    cudaStreamWaitEvent(s2, ev_fork, 0);

    cudaMemsetAsync(pcnt, 0, NN * sizeof(int), s2);
    hist_dst<<<(EE + 255) / 256, 256, 0, s2>>>(dst, pcnt);
    scan_offsets<<<1, 1024, 0, s2>>>(pcnt, poff, pcur);
    scatter_csr<<<(EE + 255) / 256, 256, 0, s2>>>(src, dst, pcur, pcsrc);
    cudaEventRecord(ev_join, s2);

    // main stream: h copy, weight repack, first QKV GEMM
    cudaMemcpyAsync(ph, h_in, (size_t)NN * DD * sizeof(float), cudaMemcpyDeviceToDevice);
    repack_w<<<(LL * DD * QKVW + 255) / 256, 256>>>(Wq, Wk, Wv, pwqkv);

    dim3 grid_qkv(QKVW / 128, (NN + 127) / 128);
    dim3 grid_d(DD / 128, (NN + 127) / 128);
    dim3 grid_hus(HUSZ / 128, (NN + 127) / 128);

    for (int l = 0; l < LL; l++) {
        const float* wqkv = pwqkv + (size_t)l * DD * QKVW;
        const float* wo = Wo + (size_t)l * DD * DD;
        const float* lg = ln_g + (size_t)l * DD;
        const float* lb = ln_b + (size_t)l * DD;

        gemm_tc<<<grid_qkv, 256, GEMM_SMEM>>>(ph, wqkv, nullptr, pqkv, NN, QKVW, DD, 0);
        if (l == 0) cudaStreamWaitEvent(0, ev_join, 0);  // join CSR before gather
        attn_gather<<<(NN * 32 + 255) / 256, 256>>>(poff, pcsrc, pqkv, pagg);
        gemm_tc<<<grid_d, 256, GEMM_SMEM>>>(pagg, wo, nullptr, pattn, NN, DD, DD, 0);
        ln_residual<<<(NN * 32 + 255) / 256, 256>>>(pattn, ph, lg, lb);
    }

    gemm_tc<<<grid_hus, 256, GEMM_SMEM>>>(ph, w1, b1, pffn, NN, HUSZ, DD, 1);
    gemm_tc<<<grid_d, 256, GEMM_SMEM>>>(pffn, w2, b2, out, NN, DD, HUSZ, 0);
}

// round 6
// speedup vs baseline: 3.8640x; 1.0331x over previous
#include <cuda_runtime.h>
#include <math.h>

#define NN 20000
#define EE 320000
#define DD 256
#define HH 8
#define LL 2
#define HUSZ 1024
#define QKVW 768   // fused q|k|v width

// ---------------- scratch (no allocation allowed) ----------------
__device__ float g_qkv[NN * QKVW];         // fused q|k|v activations
__device__ float g_wqkv[LL * DD * QKVW];   // fused+rounded qkv weights
__device__ float g_wo[LL * DD * DD];       // rounded Wo
__device__ float g_w1[DD * HUSZ];          // rounded w1
__device__ float g_w2[HUSZ * DD];          // rounded w2
__device__ float g_agg[NN * DD];
__device__ float g_h[NN * DD];
__device__ float g_attn[NN * DD];
__device__ float g_ffn[NN * HUSZ];
__device__ int   g_cnt[NN];
__device__ int   g_off[NN + 1];
__device__ int   g_cur[NN];
__device__ int   g_csrc[EE];

// ---------------- helpers ----------------
__device__ __forceinline__ float rnd_tf32(float x) {
    float r;
    asm("cvt.rna.tf32.f32 %0, %1;" : "=f"(r) : "f"(x));
    return r;
}

__device__ __forceinline__ void cp16(float* smem_ptr, const float* gptr, bool p) {
    unsigned s = (unsigned)__cvta_generic_to_shared(smem_ptr);
    int bytes = p ? 16 : 0;
    asm volatile("cp.async.cg.shared.global [%0], [%1], 16, %2;\n"
                 :: "r"(s), "l"(gptr), "r"(bytes));
}
__device__ __forceinline__ void cp_commit() { asm volatile("cp.async.commit_group;\n" ::: "memory"); }
template <int N>
__device__ __forceinline__ void cp_wait() { asm volatile("cp.async.wait_group %0;\n" :: "n"(N) : "memory"); }

// ---------------- tf32 tensor-core GEMM, 3-stage cp.async, 1 barrier/tile ----
// Inputs MUST be pre-rounded to tf32 (producer-side); no cvt in hot loop.
#define AS_PAD 36
#define BS_PAD 136
#define A_STAGE (128 * AS_PAD)
#define B_STAGE (32 * BS_PAD)
#define NSTAGE 3
#define GEMM_SMEM ((NSTAGE * (A_STAGE + B_STAGE)) * sizeof(float))

__global__ __launch_bounds__(256) void gemm_tc(
    const float* __restrict__ A, const float* __restrict__ B,
    const float* __restrict__ bias, float* __restrict__ C,
    int M, int Nc, int Kc, int relu, int rnd_out)
{
    extern __shared__ float sm[];
    float* As = sm;
    float* Bs = sm + NSTAGE * A_STAGE;

    const int tid = threadIdx.x;
    const int wid = tid >> 5;
    const int lane = tid & 31;
    const int g = lane >> 2;
    const int t = lane & 3;

    const int warp_m = wid >> 2;
    const int warp_n = wid & 3;
    const int row0 = blockIdx.y * 128;
    const int col0 = blockIdx.x * 128;

    const int a_r = tid >> 3;
    const int a_c = (tid & 7) * 4;
    const int b_r = tid >> 5;
    const int b_c = (tid & 31) * 4;

    float acc[4][4][4];
    #pragma unroll
    for (int mi = 0; mi < 4; mi++)
        #pragma unroll
        for (int ni = 0; ni < 4; ni++)
            #pragma unroll
            for (int r = 0; r < 4; r++) acc[mi][ni][r] = 0.f;

    const int ntiles = Kc >> 5;

    auto load_stage = [&](int st, int k0) {
        float* as = As + st * A_STAGE;
        float* bs = Bs + st * B_STAGE;
        #pragma unroll
        for (int i = 0; i < 4; i++) {
            int r = i * 32 + a_r;
            cp16(&as[r * AS_PAD + a_c],
                 &A[(size_t)(row0 + r) * Kc + k0 + a_c],
                 row0 + r < M);
        }
        #pragma unroll
        for (int i = 0; i < 4; i++) {
            int r = i * 8 + b_r;
            cp16(&bs[r * BS_PAD + b_c],
                 &B[(size_t)(k0 + r) * Nc + col0 + b_c],
                 true);
        }
    };

    load_stage(0, 0);
    cp_commit();
    load_stage(1, 32);       // ntiles >= 8 always here
    cp_commit();

    for (int kt = 0; kt < ntiles; kt++) {
        cp_wait<1>();
        __syncthreads();
        if (kt + 2 < ntiles) load_stage((kt + 2) % NSTAGE, (kt + 2) * 32);
        cp_commit();

        const int st = kt % NSTAGE;
        const float* as = As + st * A_STAGE;
        const float* bs = Bs + st * B_STAGE;

        #pragma unroll
        for (int ks = 0; ks < 4; ks++) {
            const int kk = ks * 8;
            unsigned af[4][4];
            #pragma unroll
            for (int mi = 0; mi < 4; mi++) {
                int rb = warp_m * 64 + mi * 16;
                const float* ap = &as[(rb + g) * AS_PAD + kk + t];
                af[mi][0] = __float_as_uint(ap[0]);
                af[mi][1] = __float_as_uint(ap[8 * AS_PAD]);
                af[mi][2] = __float_as_uint(ap[4]);
                af[mi][3] = __float_as_uint(ap[8 * AS_PAD + 4]);
            }
            unsigned bf[4][2];
            #pragma unroll
            for (int ni = 0; ni < 4; ni++) {
                int nb = warp_n * 32 + ni * 8;
                const float* bp = &bs[(kk + t) * BS_PAD + nb + g];
                bf[ni][0] = __float_as_uint(bp[0]);
                bf[ni][1] = __float_as_uint(bp[4 * BS_PAD]);
            }
            #pragma unroll
            for (int mi = 0; mi < 4; mi++)
                #pragma unroll
                for (int ni = 0; ni < 4; ni++) {
                    asm volatile(
                        "mma.sync.aligned.m16n8k8.row.col.f32.tf32.tf32.f32 "
                        "{%0,%1,%2,%3}, {%4,%5,%6,%7}, {%8,%9}, {%0,%1,%2,%3};"
                        : "+f"(acc[mi][ni][0]), "+f"(acc[mi][ni][1]),
                          "+f"(acc[mi][ni][2]), "+f"(acc[mi][ni][3])
                        : "r"(af[mi][0]), "r"(af[mi][1]), "r"(af[mi][2]), "r"(af[mi][3]),
                          "r"(bf[ni][0]), "r"(bf[ni][1]));
                }
        }
    }

    #pragma unroll
    for (int mi = 0; mi < 4; mi++) {
        int rb = row0 + warp_m * 64 + mi * 16 + g;
        #pragma unroll
        for (int ni = 0; ni < 4; ni++) {
            int cb = col0 + warp_n * 32 + ni * 8 + 2 * t;
            #pragma unroll
            for (int half = 0; half < 2; half++) {
                int r = rb + half * 8;
                if (r >= M) continue;
                float v0 = acc[mi][ni][half * 2 + 0];
                float v1 = acc[mi][ni][half * 2 + 1];
                if (bias) { v0 += bias[cb]; v1 += bias[cb + 1]; }
                if (relu) { v0 = fmaxf(v0, 0.f); v1 = fmaxf(v1, 0.f); }
                if (rnd_out) { v0 = rnd_tf32(v0); v1 = rnd_tf32(v1); }
                *reinterpret_cast<float2*>(&C[(size_t)r * Nc + cb]) = make_float2(v0, v1);
            }
        }
    }
}

// ---------------- weight repack: Wq|Wk|Wv -> [L][D][768], rounded ----------------
__global__ void repack_w(const float* __restrict__ Wq, const float* __restrict__ Wk,
                         const float* __restrict__ Wv, float* __restrict__ out)
{
    int i = blockIdx.x * blockDim.x + threadIdx.x;
    if (i >= LL * DD * QKVW) return;
    int c = i % QKVW;
    int d = (i / QKVW) % DD;
    int l = i / (QKVW * DD);
    float v;
    if (c < 256)      v = Wq[(size_t)l * DD * DD + d * DD + c];
    else if (c < 512) v = Wk[(size_t)l * DD * DD + d * DD + (c - 256)];
    else              v = Wv[(size_t)l * DD * DD + d * DD + (c - 512)];
    out[i] = rnd_tf32(v);
}

// ---------------- tf32-rounding copy ----------------
__global__ void round_copy(const float* __restrict__ in, float* __restrict__ out, int n)
{
    int i = blockIdx.x * blockDim.x + threadIdx.x;
    if (i < n) out[i] = rnd_tf32(in[i]);
}

// ---------------- CSR build ----------------
__global__ void hist_dst(const int* __restrict__ dst, int* __restrict__ cnt)
{
    int i = blockIdx.x * blockDim.x + threadIdx.x;
    if (i < EE) atomicAdd(&cnt[dst[i]], 1);
}

__global__ __launch_bounds__(1024) void scan_offsets(const int* __restrict__ cnt,
                                                     int* __restrict__ off,
                                                     int* __restrict__ cur)
{
    __shared__ int wsum[32];
    __shared__ int carry_s;
    const int lane = threadIdx.x & 31;
    const int wid = threadIdx.x >> 5;
    if (threadIdx.x == 0) carry_s = 0;
    __syncthreads();
    for (int base = 0; base < NN; base += 1024) {
        int i = base + threadIdx.x;
        int v = (i < NN) ? cnt[i] : 0;
        int x = v;
        #pragma unroll
        for (int s = 1; s < 32; s <<= 1) {
            int t = __shfl_up_sync(0xffffffffu, x, s);
            if (lane >= s) x += t;
        }
        if (lane == 31) wsum[wid] = x;
        __syncthreads();
        if (wid == 0) {
            int w = wsum[lane];
            #pragma unroll
            for (int s = 1; s < 32; s <<= 1) {
                int t = __shfl_up_sync(0xffffffffu, w, s);
                if (lane >= s) w += t;
            }
            wsum[lane] = w;
        }
        __syncthreads();
        int warp_prefix = (wid > 0) ? wsum[wid - 1] : 0;
        int carry = carry_s;
        int excl = carry + warp_prefix + x - v;
        if (i < NN) { off[i] = excl; cur[i] = excl; }
        __syncthreads();
        if (threadIdx.x == 1023) carry_s = carry + wsum[31];
        __syncthreads();
    }
    if (threadIdx.x == 0) off[NN] = carry_s;
}

__global__ void scatter_csr(const int* __restrict__ src, const int* __restrict__ dst,
                            int* __restrict__ cur, int* __restrict__ csrc)
{
    int i = blockIdx.x * blockDim.x + threadIdx.x;
    if (i >= EE) return;
    int pos = atomicAdd(&cur[dst[i]], 1);
    csrc[pos] = src[i];
}

// ---------------- fused attention gather: one warp per dst node ----------------
__global__ __launch_bounds__(256) void attn_gather(
    const int* __restrict__ off, const int* __restrict__ csrc,
    const float* __restrict__ qkv, float* __restrict__ agg)
{
    int node = (blockIdx.x * blockDim.x + threadIdx.x) >> 5;
    int lane = threadIdx.x & 31;
    if (node >= NN) return;
    const int h = lane >> 2;
    const int sub = lane & 3;
    const int doff = h * 32 + sub * 8;

    int beg = off[node], end = off[node + 1];

    const float* qr = qkv + (size_t)node * QKVW + doff;
    float4 q0 = *reinterpret_cast<const float4*>(qr);
    float4 q1 = *reinterpret_cast<const float4*>(qr + 4);

    const float scale = 0.17677669529663687f;

    float mA = -INFINITY, zA = 0.f;
    float mB = -INFINITY, zB = 0.f;
    float accA[8], accB[8];
    #pragma unroll
    for (int j = 0; j < 8; j++) { accA[j] = 0.f; accB[j] = 0.f; }

    int p = beg;
    for (; p + 1 < end; p += 2) {
        int sA = csrc[p];
        int sB = csrc[p + 1];
        const float* krA = qkv + (size_t)sA * QKVW + 256 + doff;
        const float* vrA = qkv + (size_t)sA * QKVW + 512 + doff;
        const float* krB = qkv + (size_t)sB * QKVW + 256 + doff;
        const float* vrB = qkv + (size_t)sB * QKVW + 512 + doff;
        float4 kA0 = *reinterpret_cast<const float4*>(krA);
        float4 kB0 = *reinterpret_cast<const float4*>(krB);
        float4 kA1 = *reinterpret_cast<const float4*>(krA + 4);
        float4 kB1 = *reinterpret_cast<const float4*>(krB + 4);
        float4 vA0 = *reinterpret_cast<const float4*>(vrA);
        float4 vB0 = *reinterpret_cast<const float4*>(vrB);
        float4 vA1 = *reinterpret_cast<const float4*>(vrA + 4);
        float4 vB1 = *reinterpret_cast<const float4*>(vrB + 4);

        float pA = q0.x * kA0.x + q0.y * kA0.y + q0.z * kA0.z + q0.w * kA0.w
                 + q1.x * kA1.x + q1.y * kA1.y + q1.z * kA1.z + q1.w * kA1.w;
        float pB = q0.x * kB0.x + q0.y * kB0.y + q0.z * kB0.z + q0.w * kB0.w
                 + q1.x * kB1.x + q1.y * kB1.y + q1.z * kB1.z + q1.w * kB1.w;
        pA += __shfl_xor_sync(0xffffffffu, pA, 1);
        pB += __shfl_xor_sync(0xffffffffu, pB, 1);
        pA += __shfl_xor_sync(0xffffffffu, pA, 2);
        pB += __shfl_xor_sync(0xffffffffu, pB, 2);

        float lA = pA * scale;
        float lB = pB * scale;

        float nmA = fmaxf(mA, lA);
        float fA = __expf(mA - nmA);
        float aA = __expf(lA - nmA);
        zA = zA * fA + aA;
        mA = nmA;
        accA[0] = accA[0] * fA + aA * vA0.x;
        accA[1] = accA[1] * fA + aA * vA0.y;
        accA[2] = accA[2] * fA + aA * vA0.z;
        accA[3] = accA[3] * fA + aA * vA0.w;
        accA[4] = accA[4] * fA + aA * vA1.x;
        accA[5] = accA[5] * fA + aA * vA1.y;
        accA[6] = accA[6] * fA + aA * vA1.z;
        accA[7] = accA[7] * fA + aA * vA1.w;

        float nmB = fmaxf(mB, lB);
        float fB = __expf(mB - nmB);
        float aB = __expf(lB - nmB);
        zB = zB * fB + aB;
        mB = nmB;
        accB[0] = accB[0] * fB + aB * vB0.x;
        accB[1] = accB[1] * fB + aB * vB0.y;
        accB[2] = accB[2] * fB + aB * vB0.z;
        accB[3] = accB[3] * fB + aB * vB0.w;
        accB[4] = accB[4] * fB + aB * vB1.x;
        accB[5] = accB[5] * fB + aB * vB1.y;
        accB[6] = accB[6] * fB + aB * vB1.z;
        accB[7] = accB[7] * fB + aB * vB1.w;
    }
    if (p < end) {
        int s = csrc[p];
        const float* kr = qkv + (size_t)s * QKVW + 256 + doff;
        const float* vr = qkv + (size_t)s * QKVW + 512 + doff;
        float4 k0 = *reinterpret_cast<const float4*>(kr);
        float4 k1 = *reinterpret_cast<const float4*>(kr + 4);
        float4 v0 = *reinterpret_cast<const float4*>(vr);
        float4 v1 = *reinterpret_cast<const float4*>(vr + 4);
        float part = q0.x * k0.x + q0.y * k0.y + q0.z * k0.z + q0.w * k0.w
                   + q1.x * k1.x + q1.y * k1.y + q1.z * k1.z + q1.w * k1.w;
        part += __shfl_xor_sync(0xffffffffu, part, 1);
        part += __shfl_xor_sync(0xffffffffu, part, 2);
        float logit = part * scale;
        float nm = fmaxf(mA, logit);
        float f = __expf(mA - nm);
        float a = __expf(logit - nm);
        zA = zA * f + a;
        mA = nm;
        accA[0] = accA[0] * f + a * v0.x;
        accA[1] = accA[1] * f + a * v0.y;
        accA[2] = accA[2] * f + a * v0.z;
        accA[3] = accA[3] * f + a * v0.w;
        accA[4] = accA[4] * f + a * v1.x;
        accA[5] = accA[5] * f + a * v1.y;
        accA[6] = accA[6] * f + a * v1.z;
        accA[7] = accA[7] * f + a * v1.w;
    }

    float m = fmaxf(mA, mB);
    float fA = (zA > 0.f) ? __expf(mA - m) : 0.f;
    float fB = (zB > 0.f) ? __expf(mB - m) : 0.f;
    float z = zA * fA + zB * fB;
    float inv = 1.f / (z + 1e-9f);

    float4 o0, o1;
    o0.x = rnd_tf32((accA[0] * fA + accB[0] * fB) * inv);
    o0.y = rnd_tf32((accA[1] * fA + accB[1] * fB) * inv);
    o0.z = rnd_tf32((accA[2] * fA + accB[2] * fB) * inv);
    o0.w = rnd_tf32((accA[3] * fA + accB[3] * fB) * inv);
    o1.x = rnd_tf32((accA[4] * fA + accB[4] * fB) * inv);
    o1.y = rnd_tf32((accA[5] * fA + accB[5] * fB) * inv);
    o1.z = rnd_tf32((accA[6] * fA + accB[6] * fB) * inv);
    o1.w = rnd_tf32((accA[7] * fA + accB[7] * fB) * inv);
    if (end == beg) { o0 = make_float4(0.f, 0.f, 0.f, 0.f); o1 = o0; }
    *reinterpret_cast<float4*>(&agg[(size_t)node * DD + doff]) = o0;
    *reinterpret_cast<float4*>(&agg[(size_t)node * DD + doff + 4]) = o1;
}

// ---------------- residual + layernorm (tf32-rounded write) ----------------
__global__ void ln_residual(const float* __restrict__ attn, float* __restrict__ h,
                            const float* __restrict__ gamma, const float* __restrict__ beta)
{
    int row = (blockIdx.x * blockDim.x + threadIdx.x) >> 5;
    int lane = threadIdx.x & 31;
    if (row >= NN) return;
    float x[8];
    float s = 0.f;
    #pragma unroll
    for (int j = 0; j < 8; j++) {
        x[j] = attn[(size_t)row * DD + j * 32 + lane] + h[(size_t)row * DD + j * 32 + lane];
        s += x[j];
    }
    #pragma unroll
    for (int off = 16; off; off >>= 1) s += __shfl_xor_sync(0xffffffffu, s, off);
    float mu = s * (1.f / DD);
    float vs = 0.f;
    #pragma unroll
    for (int j = 0; j < 8; j++) { float dlt = x[j] - mu; vs += dlt * dlt; }
    #pragma unroll
    for (int off = 16; off; off >>= 1) vs += __shfl_xor_sync(0xffffffffu, vs, off);
    float inv = rsqrtf(vs * (1.f / DD) + 1e-5f);
    #pragma unroll
    for (int j = 0; j < 8; j++) {
        int c = j * 32 + lane;
        h[(size_t)row * DD + c] = rnd_tf32((x[j] - mu) * inv * gamma[c] + beta[c]);
    }
}

// ---------------- launch ----------------
extern "C" void kernel_launch(void* const* d_in, const int* in_sizes, int n_in,
                              void* d_out, int out_size)
{
    const float* h_in = (const float*)d_in[0];
    const int* src = (const int*)d_in[1];
    const int* dst = (const int*)d_in[2];
    const float* Wq = (const float*)d_in[3];
    const float* Wk = (const float*)d_in[4];
    const float* Wv = (const float*)d_in[5];
    const float* Wo = (const float*)d_in[6];
    const float* ln_g = (const float*)d_in[7];
    const float* ln_b = (const float*)d_in[8];
    const float* w1 = (const float*)d_in[9];
    const float* b1 = (const float*)d_in[10];
    const float* w2 = (const float*)d_in[11];
    const float* b2 = (const float*)d_in[12];
    float* out = (float*)d_out;

    float *pqkv, *pwqkv, *pwo, *pw1, *pw2, *pagg, *ph, *pattn, *pffn;
    int *pcnt, *poff, *pcur, *pcsrc;
    cudaGetSymbolAddress((void**)&pqkv, g_qkv);
    cudaGetSymbolAddress((void**)&pwqkv, g_wqkv);
    cudaGetSymbolAddress((void**)&pwo, g_wo);
    cudaGetSymbolAddress((void**)&pw1, g_w1);
    cudaGetSymbolAddress((void**)&pw2, g_w2);
    cudaGetSymbolAddress((void**)&pagg, g_agg);
    cudaGetSymbolAddress((void**)&ph, g_h);
    cudaGetSymbolAddress((void**)&pattn, g_attn);
    cudaGetSymbolAddress((void**)&pffn, g_ffn);
    cudaGetSymbolAddress((void**)&pcnt, g_cnt);
    cudaGetSymbolAddress((void**)&poff, g_off);
    cudaGetSymbolAddress((void**)&pcur, g_cur);
    cudaGetSymbolAddress((void**)&pcsrc, g_csrc);

    static cudaStream_t s2 = nullptr;
    static cudaEvent_t ev_fork = nullptr, ev_join = nullptr;
    static bool init_done = false;
    if (!init_done) {
        cudaFuncSetAttribute(gemm_tc, cudaFuncAttributeMaxDynamicSharedMemorySize, GEMM_SMEM);
        cudaStreamCreateWithFlags(&s2, cudaStreamNonBlocking);
        cudaEventCreateWithFlags(&ev_fork, cudaEventDisableTiming);
        cudaEventCreateWithFlags(&ev_join, cudaEventDisableTiming);
        init_done = true;
    }

    // fork: CSR build + weight rounding on s2, overlapped with main-stream work
    cudaEventRecord(ev_fork, 0);
    cudaStreamWaitEvent(s2, ev_fork, 0);

    cudaMemsetAsync(pcnt, 0, NN * sizeof(int), s2);
    hist_dst<<<(EE + 255) / 256, 256, 0, s2>>>(dst, pcnt);
    scan_offsets<<<1, 1024, 0, s2>>>(pcnt, poff, pcur);
    scatter_csr<<<(EE + 255) / 256, 256, 0, s2>>>(src, dst, pcur, pcsrc);
    round_copy<<<(LL * DD * DD + 255) / 256, 256, 0, s2>>>(Wo, pwo, LL * DD * DD);
    round_copy<<<(DD * HUSZ + 255) / 256, 256, 0, s2>>>(w1, pw1, DD * HUSZ);
    round_copy<<<(HUSZ * DD + 255) / 256, 256, 0, s2>>>(w2, pw2, HUSZ * DD);
    cudaEventRecord(ev_join, s2);

    // main stream: rounded h copy, weight repack, layers
    round_copy<<<(NN * DD + 255) / 256, 256>>>(h_in, ph, NN * DD);
    repack_w<<<(LL * DD * QKVW + 255) / 256, 256>>>(Wq, Wk, Wv, pwqkv);

    dim3 grid_qkv(QKVW / 128, (NN + 127) / 128);
    dim3 grid_d(DD / 128, (NN + 127) / 128);
    dim3 grid_hus(HUSZ / 128, (NN + 127) / 128);

    for (int l = 0; l < LL; l++) {
        const float* wqkv = pwqkv + (size_t)l * DD * QKVW;
        const float* wo = pwo + (size_t)l * DD * DD;
        const float* lg = ln_g + (size_t)l * DD;
        const float* lb = ln_b + (size_t)l * DD;

        gemm_tc<<<grid_qkv, 256, GEMM_SMEM>>>(ph, wqkv, nullptr, pqkv, NN, QKVW, DD, 0, 0);
        if (l == 0) cudaStreamWaitEvent(0, ev_join, 0);  // join CSR + rounded weights
        attn_gather<<<(NN * 32 + 255) / 256, 256>>>(poff, pcsrc, pqkv, pagg);
        gemm_tc<<<grid_d, 256, GEMM_SMEM>>>(pagg, wo, nullptr, pattn, NN, DD, DD, 0, 0);
        ln_residual<<<(NN * 32 + 255) / 256, 256>>>(pattn, ph, lg, lb);
    }

    gemm_tc<<<grid_hus, 256, GEMM_SMEM>>>(ph, pw1, b1, pffn, NN, HUSZ, DD, 1, 1);
    gemm_tc<<<grid_d, 256, GEMM_SMEM>>>(pffn, pw2, b2, out, NN, DD, HUSZ, 0, 0);
}

// round 8
// speedup vs baseline: 4.0666x; 1.0524x over previous
#include <cuda_runtime.h>
#include <cuda_fp16.h>
#include <math.h>

#define NN 20000
#define EE 320000
#define DD 256
#define HH 8
#define LL 2
#define HUSZ 1024
#define QKVW 768   // fused q|k|v width

// ---------------- scratch (no allocation allowed) ----------------
__device__ float  g_q[NN * DD];             // q activations (fp32, tf32-rounded)
__device__ __half g_kv16[NN * 512];         // k (0..255) | v (256..511) per node, fp16
__device__ float  g_wqkv[LL * DD * QKVW];   // fused+rounded qkv weights
__device__ float  g_wo[LL * DD * DD];       // rounded Wo
__device__ float  g_w1[DD * HUSZ];          // rounded w1
__device__ float  g_w2[HUSZ * DD];          // rounded w2
__device__ float  g_agg[NN * DD];
__device__ float  g_h[NN * DD];
__device__ float  g_attn[NN * DD];
__device__ float  g_ffn[NN * HUSZ];
__device__ int    g_cnt[NN];
__device__ int    g_off[NN + 1];
__device__ int    g_cur[NN];
__device__ int    g_csrc[EE];

// ---------------- helpers ----------------
__device__ __forceinline__ float rnd_tf32(float x) {
    float r;
    asm("cvt.rna.tf32.f32 %0, %1;" : "=f"(r) : "f"(x));
    return r;
}

__device__ __forceinline__ void cp16(float* smem_ptr, const float* gptr, bool p) {
    unsigned s = (unsigned)__cvta_generic_to_shared(smem_ptr);
    int bytes = p ? 16 : 0;
    asm volatile("cp.async.cg.shared.global [%0], [%1], 16, %2;\n"
                 :: "r"(s), "l"(gptr), "r"(bytes));
}
__device__ __forceinline__ void cp_commit() { asm volatile("cp.async.commit_group;\n" ::: "memory"); }
template <int N>
__device__ __forceinline__ void cp_wait() { asm volatile("cp.async.wait_group %0;\n" :: "n"(N) : "memory"); }

// ---------------- tf32 tensor-core GEMM, 3-stage cp.async, 1 barrier/tile ----
// Inputs pre-rounded to tf32. Optional split mode: q fp32 + kv fp16 outputs.
#define AS_PAD 36
#define BS_PAD 136
#define A_STAGE (128 * AS_PAD)
#define B_STAGE (32 * BS_PAD)
#define NSTAGE 3
#define GEMM_SMEM ((NSTAGE * (A_STAGE + B_STAGE)) * sizeof(float))

__global__ __launch_bounds__(256) void gemm_tc(
    const float* __restrict__ A, const float* __restrict__ B,
    const float* __restrict__ bias, float* __restrict__ C,
    float* __restrict__ Cq, __half* __restrict__ Ckv,
    int M, int Nc, int Kc, int relu, int rnd_out)
{
    extern __shared__ float sm[];
    float* As = sm;
    float* Bs = sm + NSTAGE * A_STAGE;

    const int tid = threadIdx.x;
    const int wid = tid >> 5;
    const int lane = tid & 31;
    const int g = lane >> 2;
    const int t = lane & 3;

    const int warp_m = wid >> 2;
    const int warp_n = wid & 3;
    const int row0 = blockIdx.y * 128;
    const int col0 = blockIdx.x * 128;

    const int a_r = tid >> 3;
    const int a_c = (tid & 7) * 4;
    const int b_r = tid >> 5;
    const int b_c = (tid & 31) * 4;

    float acc[4][4][4];
    #pragma unroll
    for (int mi = 0; mi < 4; mi++)
        #pragma unroll
        for (int ni = 0; ni < 4; ni++)
            #pragma unroll
            for (int r = 0; r < 4; r++) acc[mi][ni][r] = 0.f;

    const int ntiles = Kc >> 5;

    auto load_stage = [&](int st, int k0) {
        float* as = As + st * A_STAGE;
        float* bs = Bs + st * B_STAGE;
        #pragma unroll
        for (int i = 0; i < 4; i++) {
            int r = i * 32 + a_r;
            cp16(&as[r * AS_PAD + a_c],
                 &A[(size_t)(row0 + r) * Kc + k0 + a_c],
                 row0 + r < M);
        }
        #pragma unroll
        for (int i = 0; i < 4; i++) {
            int r = i * 8 + b_r;
            cp16(&bs[r * BS_PAD + b_c],
                 &B[(size_t)(k0 + r) * Nc + col0 + b_c],
                 true);
        }
    };

    load_stage(0, 0);
    cp_commit();
    load_stage(1, 32);
    cp_commit();

    for (int kt = 0; kt < ntiles; kt++) {
        cp_wait<1>();
        __syncthreads();
        if (kt + 2 < ntiles) load_stage((kt + 2) % NSTAGE, (kt + 2) * 32);
        cp_commit();

        const int st = kt % NSTAGE;
        const float* as = As + st * A_STAGE;
        const float* bs = Bs + st * B_STAGE;

        #pragma unroll
        for (int ks = 0; ks < 4; ks++) {
            const int kk = ks * 8;
            unsigned af[4][4];
            #pragma unroll
            for (int mi = 0; mi < 4; mi++) {
                int rb = warp_m * 64 + mi * 16;
                const float* ap = &as[(rb + g) * AS_PAD + kk + t];
                af[mi][0] = __float_as_uint(ap[0]);
                af[mi][1] = __float_as_uint(ap[8 * AS_PAD]);
                af[mi][2] = __float_as_uint(ap[4]);
                af[mi][3] = __float_as_uint(ap[8 * AS_PAD + 4]);
            }
            unsigned bf[4][2];
            #pragma unroll
            for (int ni = 0; ni < 4; ni++) {
                int nb = warp_n * 32 + ni * 8;
                const float* bp = &bs[(kk + t) * BS_PAD + nb + g];
                bf[ni][0] = __float_as_uint(bp[0]);
                bf[ni][1] = __float_as_uint(bp[4 * BS_PAD]);
            }
            #pragma unroll
            for (int mi = 0; mi < 4; mi++)
                #pragma unroll
                for (int ni = 0; ni < 4; ni++) {
                    asm volatile(
                        "mma.sync.aligned.m16n8k8.row.col.f32.tf32.tf32.f32 "
                        "{%0,%1,%2,%3}, {%4,%5,%6,%7}, {%8,%9}, {%0,%1,%2,%3};"
                        : "+f"(acc[mi][ni][0]), "+f"(acc[mi][ni][1]),
                          "+f"(acc[mi][ni][2]), "+f"(acc[mi][ni][3])
                        : "r"(af[mi][0]), "r"(af[mi][1]), "r"(af[mi][2]), "r"(af[mi][3]),
                          "r"(bf[ni][0]), "r"(bf[ni][1]));
                }
        }
    }

    #pragma unroll
    for (int mi = 0; mi < 4; mi++) {
        int rb = row0 + warp_m * 64 + mi * 16 + g;
        #pragma unroll
        for (int ni = 0; ni < 4; ni++) {
            int cb = col0 + warp_n * 32 + ni * 8 + 2 * t;
            #pragma unroll
            for (int half = 0; half < 2; half++) {
                int r = rb + half * 8;
                if (r >= M) continue;
                float v0 = acc[mi][ni][half * 2 + 0];
                float v1 = acc[mi][ni][half * 2 + 1];
                if (Ckv) {
                    // split mode: cols [0,256) -> q fp32 (tf32-rounded), [256,768) -> kv fp16
                    if (cb < 256) {
                        *reinterpret_cast<float2*>(&Cq[(size_t)r * DD + cb]) =
                            make_float2(rnd_tf32(v0), rnd_tf32(v1));
                    } else {
                        *reinterpret_cast<__half2*>(&Ckv[(size_t)r * 512 + (cb - 256)]) =
                            __floats2half2_rn(v0, v1);
                    }
                } else {
                    if (bias) { v0 += bias[cb]; v1 += bias[cb + 1]; }
                    if (relu) { v0 = fmaxf(v0, 0.f); v1 = fmaxf(v1, 0.f); }
                    if (rnd_out) { v0 = rnd_tf32(v0); v1 = rnd_tf32(v1); }
                    *reinterpret_cast<float2*>(&C[(size_t)r * Nc + cb]) = make_float2(v0, v1);
                }
            }
        }
    }
}

// ---------------- weight repack: Wq|Wk|Wv -> [L][D][768], rounded ----------------
__global__ void repack_w(const float* __restrict__ Wq, const float* __restrict__ Wk,
                         const float* __restrict__ Wv, float* __restrict__ out)
{
    int i = blockIdx.x * blockDim.x + threadIdx.x;
    if (i >= LL * DD * QKVW) return;
    int c = i % QKVW;
    int d = (i / QKVW) % DD;
    int l = i / (QKVW * DD);
    float v;
    if (c < 256)      v = Wq[(size_t)l * DD * DD + d * DD + c];
    else if (c < 512) v = Wk[(size_t)l * DD * DD + d * DD + (c - 256)];
    else              v = Wv[(size_t)l * DD * DD + d * DD + (c - 512)];
    out[i] = rnd_tf32(v);
}

// ---------------- tf32-rounding copy ----------------
__global__ void round_copy(const float* __restrict__ in, float* __restrict__ out, int n)
{
    int i = blockIdx.x * blockDim.x + threadIdx.x;
    if (i < n) out[i] = rnd_tf32(in[i]);
}

// ---------------- CSR build ----------------
__global__ void hist_dst(const int* __restrict__ dst, int* __restrict__ cnt)
{
    int i = blockIdx.x * blockDim.x + threadIdx.x;
    if (i < EE) atomicAdd(&cnt[dst[i]], 1);
}

__global__ __launch_bounds__(1024) void scan_offsets(const int* __restrict__ cnt,
                                                     int* __restrict__ off,
                                                     int* __restrict__ cur)
{
    __shared__ int wsum[32];
    __shared__ int carry_s;
    const int lane = threadIdx.x & 31;
    const int wid = threadIdx.x >> 5;
    if (threadIdx.x == 0) carry_s = 0;
    __syncthreads();
    for (int base = 0; base < NN; base += 1024) {
        int i = base + threadIdx.x;
        int v = (i < NN) ? cnt[i] : 0;
        int x = v;
        #pragma unroll
        for (int s = 1; s < 32; s <<= 1) {
            int t = __shfl_up_sync(0xffffffffu, x, s);
            if (lane >= s) x += t;
        }
        if (lane == 31) wsum[wid] = x;
        __syncthreads();
        if (wid == 0) {
            int w = wsum[lane];
            #pragma unroll
            for (int s = 1; s < 32; s <<= 1) {
                int t = __shfl_up_sync(0xffffffffu, w, s);
                if (lane >= s) w += t;
            }
            wsum[lane] = w;
        }
        __syncthreads();
        int warp_prefix = (wid > 0) ? wsum[wid - 1] : 0;
        int carry = carry_s;
        int excl = carry + warp_prefix + x - v;
        if (i < NN) { off[i] = excl; cur[i] = excl; }
        __syncthreads();
        if (threadIdx.x == 1023) carry_s = carry + wsum[31];
        __syncthreads();
    }
    if (threadIdx.x == 0) off[NN] = carry_s;
}

__global__ void scatter_csr(const int* __restrict__ src, const int* __restrict__ dst,
                            int* __restrict__ cur, int* __restrict__ csrc)
{
    int i = blockIdx.x * blockDim.x + threadIdx.x;
    if (i >= EE) return;
    int pos = atomicAdd(&cur[dst[i]], 1);
    csrc[pos] = src[i];
}

// ---------------- fused attention gather: one warp per dst node ----------------
// q: fp32 [NN,256]; kv: fp16 [NN,512] (k 0..255, v 256..511).
// Dual independent online-softmax states (even/odd edges) for 2x MLP.
__global__ __launch_bounds__(256) void attn_gather(
    const int* __restrict__ off, const int* __restrict__ csrc,
    const float* __restrict__ q, const __half* __restrict__ kv,
    float* __restrict__ agg)
{
    int node = (blockIdx.x * blockDim.x + threadIdx.x) >> 5;
    int lane = threadIdx.x & 31;
    if (node >= NN) return;
    const int h = lane >> 2;
    const int sub = lane & 3;
    const int doff = h * 32 + sub * 8;

    int beg = off[node], end = off[node + 1];

    float4 q0 = *reinterpret_cast<const float4*>(&q[(size_t)node * DD + doff]);
    float4 q1 = *reinterpret_cast<const float4*>(&q[(size_t)node * DD + doff + 4]);

    const float scale = 0.17677669529663687f;

    float mA = -INFINITY, zA = 0.f;
    float mB = -INFINITY, zB = 0.f;
    float accA[8], accB[8];
    #pragma unroll
    for (int j = 0; j < 8; j++) { accA[j] = 0.f; accB[j] = 0.f; }

    int p = beg;
    for (; p + 1 < end; p += 2) {
        int sA = csrc[p];
        int sB = csrc[p + 1];
        const __half* bA = kv + (size_t)sA * 512 + doff;
        const __half* bB = kv + (size_t)sB * 512 + doff;
        uint4 krA = *reinterpret_cast<const uint4*>(bA);         // 8 halfs k
        uint4 krB = *reinterpret_cast<const uint4*>(bB);
        uint4 vrA = *reinterpret_cast<const uint4*>(bA + 256);   // 8 halfs v
        uint4 vrB = *reinterpret_cast<const uint4*>(bB + 256);

        float2 kA0 = __half22float2(*reinterpret_cast<__half2*>(&krA.x));
        float2 kA1 = __half22float2(*reinterpret_cast<__half2*>(&krA.y));
        float2 kA2 = __half22float2(*reinterpret_cast<__half2*>(&krA.z));
        float2 kA3 = __half22float2(*reinterpret_cast<__half2*>(&krA.w));
        float2 kB0 = __half22float2(*reinterpret_cast<__half2*>(&krB.x));
        float2 kB1 = __half22float2(*reinterpret_cast<__half2*>(&krB.y));
        float2 kB2 = __half22float2(*reinterpret_cast<__half2*>(&krB.z));
        float2 kB3 = __half22float2(*reinterpret_cast<__half2*>(&krB.w));

        float pA = q0.x * kA0.x + q0.y * kA0.y + q0.z * kA1.x + q0.w * kA1.y
                 + q1.x * kA2.x + q1.y * kA2.y + q1.z * kA3.x + q1.w * kA3.y;
        float pB = q0.x * kB0.x + q0.y * kB0.y + q0.z * kB1.x + q0.w * kB1.y
                 + q1.x * kB2.x + q1.y * kB2.y + q1.z * kB3.x + q1.w * kB3.y;
        pA += __shfl_xor_sync(0xffffffffu, pA, 1);
        pB += __shfl_xor_sync(0xffffffffu, pB, 1);
        pA += __shfl_xor_sync(0xffffffffu, pA, 2);
        pB += __shfl_xor_sync(0xffffffffu, pB, 2);

        float lA = pA * scale;
        float lB = pB * scale;

        float2 vA0 = __half22float2(*reinterpret_cast<__half2*>(&vrA.x));
        float2 vA1 = __half22float2(*reinterpret_cast<__half2*>(&vrA.y));
        float2 vA2 = __half22float2(*reinterpret_cast<__half2*>(&vrA.z));
        float2 vA3 = __half22float2(*reinterpret_cast<__half2*>(&vrA.w));
        float2 vB0 = __half22float2(*reinterpret_cast<__half2*>(&vrB.x));
        float2 vB1 = __half22float2(*reinterpret_cast<__half2*>(&vrB.y));
        float2 vB2 = __half22float2(*reinterpret_cast<__half2*>(&vrB.z));
        float2 vB3 = __half22float2(*reinterpret_cast<__half2*>(&vrB.w));

        float nmA = fmaxf(mA, lA);
        float fA = __expf(mA - nmA);
        float aA = __expf(lA - nmA);
        zA = zA * fA + aA;
        mA = nmA;
        accA[0] = accA[0] * fA + aA * vA0.x;
        accA[1] = accA[1] * fA + aA * vA0.y;
        accA[2] = accA[2] * fA + aA * vA1.x;
        accA[3] = accA[3] * fA + aA * vA1.y;
        accA[4] = accA[4] * fA + aA * vA2.x;
        accA[5] = accA[5] * fA + aA * vA2.y;
        accA[6] = accA[6] * fA + aA * vA3.x;
        accA[7] = accA[7] * fA + aA * vA3.y;

        float nmB = fmaxf(mB, lB);
        float fB = __expf(mB - nmB);
        float aB = __expf(lB - nmB);
        zB = zB * fB + aB;
        mB = nmB;
        accB[0] = accB[0] * fB + aB * vB0.x;
        accB[1] = accB[1] * fB + aB * vB0.y;
        accB[2] = accB[2] * fB + aB * vB1.x;
        accB[3] = accB[3] * fB + aB * vB1.y;
        accB[4] = accB[4] * fB + aB * vB2.x;
        accB[5] = accB[5] * fB + aB * vB2.y;
        accB[6] = accB[6] * fB + aB * vB3.x;
        accB[7] = accB[7] * fB + aB * vB3.y;
    }
    if (p < end) {
        int s = csrc[p];
        const __half* b = kv + (size_t)s * 512 + doff;
        uint4 kr = *reinterpret_cast<const uint4*>(b);
        uint4 vr = *reinterpret_cast<const uint4*>(b + 256);
        float2 k0 = __half22float2(*reinterpret_cast<__half2*>(&kr.x));
        float2 k1 = __half22float2(*reinterpret_cast<__half2*>(&kr.y));
        float2 k2 = __half22float2(*reinterpret_cast<__half2*>(&kr.z));
        float2 k3 = __half22float2(*reinterpret_cast<__half2*>(&kr.w));
        float part = q0.x * k0.x + q0.y * k0.y + q0.z * k1.x + q0.w * k1.y
                   + q1.x * k2.x + q1.y * k2.y + q1.z * k3.x + q1.w * k3.y;
        part += __shfl_xor_sync(0xffffffffu, part, 1);
        part += __shfl_xor_sync(0xffffffffu, part, 2);
        float logit = part * scale;
        float2 v0 = __half22float2(*reinterpret_cast<__half2*>(&vr.x));
        float2 v1 = __half22float2(*reinterpret_cast<__half2*>(&vr.y));
        float2 v2 = __half22float2(*reinterpret_cast<__half2*>(&vr.z));
        float2 v3 = __half22float2(*reinterpret_cast<__half2*>(&vr.w));
        float nm = fmaxf(mA, logit);
        float f = __expf(mA - nm);
        float a = __expf(logit - nm);
        zA = zA * f + a;
        mA = nm;
        accA[0] = accA[0] * f + a * v0.x;
        accA[1] = accA[1] * f + a * v0.y;
        accA[2] = accA[2] * f + a * v1.x;
        accA[3] = accA[3] * f + a * v1.y;
        accA[4] = accA[4] * f + a * v2.x;
        accA[5] = accA[5] * f + a * v2.y;
        accA[6] = accA[6] * f + a * v3.x;
        accA[7] = accA[7] * f + a * v3.y;
    }

    float m = fmaxf(mA, mB);
    float fA = (zA > 0.f) ? __expf(mA - m) : 0.f;
    float fB = (zB > 0.f) ? __expf(mB - m) : 0.f;
    float z = zA * fA + zB * fB;
    float inv = 1.f / (z + 1e-9f);

    float4 o0, o1;
    o0.x = rnd_tf32((accA[0] * fA + accB[0] * fB) * inv);
    o0.y = rnd_tf32((accA[1] * fA + accB[1] * fB) * inv);
    o0.z = rnd_tf32((accA[2] * fA + accB[2] * fB) * inv);
    o0.w = rnd_tf32((accA[3] * fA + accB[3] * fB) * inv);
    o1.x = rnd_tf32((accA[4] * fA + accB[4] * fB) * inv);
    o1.y = rnd_tf32((accA[5] * fA + accB[5] * fB) * inv);
    o1.z = rnd_tf32((accA[6] * fA + accB[6] * fB) * inv);
    o1.w = rnd_tf32((accA[7] * fA + accB[7] * fB) * inv);
    if (end == beg) { o0 = make_float4(0.f, 0.f, 0.f, 0.f); o1 = o0; }
    *reinterpret_cast<float4*>(&agg[(size_t)node * DD + doff]) = o0;
    *reinterpret_cast<float4*>(&agg[(size_t)node * DD + doff + 4]) = o1;
}

// ---------------- residual + layernorm (tf32-rounded write) ----------------
__global__ void ln_residual(const float* __restrict__ attn, float* __restrict__ h,
                            const float* __restrict__ gamma, const float* __restrict__ beta)
{
    int row = (blockIdx.x * blockDim.x + threadIdx.x) >> 5;
    int lane = threadIdx.x & 31;
    if (row >= NN) return;
    float x[8];
    float s = 0.f;
    #pragma unroll
    for (int j = 0; j < 8; j++) {
        x[j] = attn[(size_t)row * DD + j * 32 + lane] + h[(size_t)row * DD + j * 32 + lane];
        s += x[j];
    }
    #pragma unroll
    for (int off = 16; off; off >>= 1) s += __shfl_xor_sync(0xffffffffu, s, off);
    float mu = s * (1.f / DD);
    float vs = 0.f;
    #pragma unroll
    for (int j = 0; j < 8; j++) { float dlt = x[j] - mu; vs += dlt * dlt; }
    #pragma unroll
    for (int off = 16; off; off >>= 1) vs += __shfl_xor_sync(0xffffffffu, vs, off);
    float inv = rsqrtf(vs * (1.f / DD) + 1e-5f);
    #pragma unroll
    for (int j = 0; j < 8; j++) {
        int c = j * 32 + lane;
        h[(size_t)row * DD + c] = rnd_tf32((x[j] - mu) * inv * gamma[c] + beta[c]);
    }
}

// ---------------- launch ----------------
extern "C" void kernel_launch(void* const* d_in, const int* in_sizes, int n_in,
                              void* d_out, int out_size)
{
    const float* h_in = (const float*)d_in[0];
    const int* src = (const int*)d_in[1];
    const int* dst = (const int*)d_in[2];
    const float* Wq = (const float*)d_in[3];
    const float* Wk = (const float*)d_in[4];
    const float* Wv = (const float*)d_in[5];
    const float* Wo = (const float*)d_in[6];
    const float* ln_g = (const float*)d_in[7];
    const float* ln_b = (const float*)d_in[8];
    const float* w1 = (const float*)d_in[9];
    const float* b1 = (const float*)d_in[10];
    const float* w2 = (const float*)d_in[11];
    const float* b2 = (const float*)d_in[12];
    float* out = (float*)d_out;

    float *pq, *pwqkv, *pwo, *pw1, *pw2, *pagg, *ph, *pattn, *pffn;
    __half* pkv;
    int *pcnt, *poff, *pcur, *pcsrc;
    cudaGetSymbolAddress((void**)&pq, g_q);
    cudaGetSymbolAddress((void**)&pkv, g_kv16);
    cudaGetSymbolAddress((void**)&pwqkv, g_wqkv);
    cudaGetSymbolAddress((void**)&pwo, g_wo);
    cudaGetSymbolAddress((void**)&pw1, g_w1);
    cudaGetSymbolAddress((void**)&pw2, g_w2);
    cudaGetSymbolAddress((void**)&pagg, g_agg);
    cudaGetSymbolAddress((void**)&ph, g_h);
    cudaGetSymbolAddress((void**)&pattn, g_attn);
    cudaGetSymbolAddress((void**)&pffn, g_ffn);
    cudaGetSymbolAddress((void**)&pcnt, g_cnt);
    cudaGetSymbolAddress((void**)&poff, g_off);
    cudaGetSymbolAddress((void**)&pcur, g_cur);
    cudaGetSymbolAddress((void**)&pcsrc, g_csrc);

    static cudaStream_t s2 = nullptr;
    static cudaEvent_t ev_fork = nullptr, ev_join = nullptr;
    static bool init_done = false;
    if (!init_done) {
        cudaFuncSetAttribute(gemm_tc, cudaFuncAttributeMaxDynamicSharedMemorySize, GEMM_SMEM);
        cudaStreamCreateWithFlags(&s2, cudaStreamNonBlocking);
        cudaEventCreateWithFlags(&ev_fork, cudaEventDisableTiming);
        cudaEventCreateWithFlags(&ev_join, cudaEventDisableTiming);
        init_done = true;
    }

    // fork: CSR build + weight rounding on s2
    cudaEventRecord(ev_fork, 0);
    cudaStreamWaitEvent(s2, ev_fork, 0);

    cudaMemsetAsync(pcnt, 0, NN * sizeof(int), s2);
    hist_dst<<<(EE + 255) / 256, 256, 0, s2>>>(dst, pcnt);
    scan_offsets<<<1, 1024, 0, s2>>>(pcnt, poff, pcur);
    scatter_csr<<<(EE + 255) / 256, 256, 0, s2>>>(src, dst, pcur, pcsrc);
    round_copy<<<(LL * DD * DD + 255) / 256, 256, 0, s2>>>(Wo, pwo, LL * DD * DD);
    round_copy<<<(DD * HUSZ + 255) / 256, 256, 0, s2>>>(w1, pw1, DD * HUSZ);
    round_copy<<<(HUSZ * DD + 255) / 256, 256, 0, s2>>>(w2, pw2, HUSZ * DD);
    cudaEventRecord(ev_join, s2);

    // main stream
    round_copy<<<(NN * DD + 255) / 256, 256>>>(h_in, ph, NN * DD);
    repack_w<<<(LL * DD * QKVW + 255) / 256, 256>>>(Wq, Wk, Wv, pwqkv);

    dim3 grid_qkv(QKVW / 128, (NN + 127) / 128);
    dim3 grid_d(DD / 128, (NN + 127) / 128);
    dim3 grid_hus(HUSZ / 128, (NN + 127) / 128);

    for (int l = 0; l < LL; l++) {
        const float* wqkv = pwqkv + (size_t)l * DD * QKVW;
        const float* wo = pwo + (size_t)l * DD * DD;
        const float* lg = ln_g + (size_t)l * DD;
        const float* lb = ln_b + (size_t)l * DD;

        gemm_tc<<<grid_qkv, 256, GEMM_SMEM>>>(ph, wqkv, nullptr, nullptr, pq, pkv,
                                              NN, QKVW, DD, 0, 0);
        if (l == 0) cudaStreamWaitEvent(0, ev_join, 0);
        attn_gather<<<(NN * 32 + 255) / 256, 256>>>(poff, pcsrc, pq, pkv, pagg);
        gemm_tc<<<grid_d, 256, GEMM_SMEM>>>(pagg, wo, nullptr, pattn, nullptr, nullptr,
                                            NN, DD, DD, 0, 0);
        ln_residual<<<(NN * 32 + 255) / 256, 256>>>(pattn, ph, lg, lb);
    }

    gemm_tc<<<grid_hus, 256, GEMM_SMEM>>>(ph, pw1, b1, pffn, nullptr, nullptr,
                                          NN, HUSZ, DD, 1, 1);
    gemm_tc<<<grid_d, 256, GEMM_SMEM>>>(pffn, pw2, b2, out, nullptr, nullptr,
                                        NN, DD, HUSZ, 0, 0);
}

// round 9
// speedup vs baseline: 5.3169x; 1.3074x over previous
#include <cuda_runtime.h>
#include <cuda_fp16.h>
#include <math.h>

#define NN 20000
#define EE 320000
#define DD 256
#define HH 8
#define LL 2
#define HUSZ 1024
#define QKVW 768

// ---------------- scratch (no allocation allowed) ----------------
__device__ __half g_h16[NN * DD];
__device__ __half g_qkv16[NN * QKVW];        // q|k|v fp16
__device__ __half g_agg16[NN * DD];
__device__ __half g_attn16[NN * DD];
__device__ __half g_ffn16[NN * HUSZ];
__device__ __half g_wqkvT[LL * QKVW * DD];   // [l][768][256] fp16 (N,K)
__device__ __half g_woT[LL * DD * DD];       // [l][256][256]
__device__ __half g_w1T[HUSZ * DD];          // [1024][256]
__device__ __half g_w2T[DD * HUSZ];          // [256][1024]
__device__ int    g_cnt[NN];
__device__ int    g_off[NN + 1];
__device__ int    g_cur[NN];
__device__ int    g_csrc[EE];

// ---------------- helpers ----------------
__device__ __forceinline__ void cp16h(__half* smem_ptr, const __half* gptr, bool p) {
    unsigned s = (unsigned)__cvta_generic_to_shared(smem_ptr);
    int bytes = p ? 16 : 0;
    asm volatile("cp.async.cg.shared.global [%0], [%1], 16, %2;\n"
                 :: "r"(s), "l"(gptr), "r"(bytes));
}
__device__ __forceinline__ void cp_commit() { asm volatile("cp.async.commit_group;\n" ::: "memory"); }
template <int N>
__device__ __forceinline__ void cp_wait() { asm volatile("cp.async.wait_group %0;\n" :: "n"(N) : "memory"); }

// ---------------- fp16 tensor-core GEMM (m16n8k16), 3-stage cp.async ----------
// C[M,Nc] = A[M,Kc] @ BT[Nc,Kc]^T. A,BT fp16 row-major (K contiguous).
// Block 128x128, BK=32, 8 warps, warp tile 64x32.
#define HSTRIDE 40                      // halfs per smem row (32 + 8 pad, 80B = 16B-mult)
#define H_STAGE (128 * HSTRIDE)         // halfs per tile per stage
#define NSTAGE 3
#define GEMM_SMEM ((size_t)NSTAGE * 2 * H_STAGE * sizeof(__half))

__global__ __launch_bounds__(256) void gemm_h(
    const __half* __restrict__ A, const __half* __restrict__ BT,
    const float* __restrict__ bias, float* __restrict__ Cf, __half* __restrict__ Ch,
    int M, int Nc, int Kc, int relu)
{
    extern __shared__ __half smh[];
    __half* As = smh;
    __half* Bs = smh + NSTAGE * H_STAGE;

    const int tid = threadIdx.x;
    const int wid = tid >> 5;
    const int lane = tid & 31;
    const int g = lane >> 2;
    const int t = lane & 3;

    const int warp_m = wid >> 2;        // 0..1
    const int warp_n = wid & 3;         // 0..3
    const int row0 = blockIdx.y * 128;
    const int col0 = blockIdx.x * 128;

    float acc[4][4][4];
    #pragma unroll
    for (int mi = 0; mi < 4; mi++)
        #pragma unroll
        for (int ni = 0; ni < 4; ni++)
            #pragma unroll
            for (int r = 0; r < 4; r++) acc[mi][ni][r] = 0.f;

    const int ntiles = Kc >> 5;

    auto load_stage = [&](int st, int k0) {
        __half* as = As + st * H_STAGE;
        __half* bs = Bs + st * H_STAGE;
        #pragma unroll
        for (int i = 0; i < 2; i++) {
            int lin = i * 256 + tid;     // 0..511
            int row = lin >> 2;          // 0..127
            int seg = (lin & 3) * 8;     // 0,8,16,24
            cp16h(&as[row * HSTRIDE + seg],
                  &A[(size_t)(row0 + row) * Kc + k0 + seg],
                  row0 + row < M);
            cp16h(&bs[row * HSTRIDE + seg],
                  &BT[(size_t)(col0 + row) * Kc + k0 + seg],
                  true);
        }
    };

    load_stage(0, 0);
    cp_commit();
    load_stage(1, 32);
    cp_commit();

    for (int kt = 0; kt < ntiles; kt++) {
        cp_wait<1>();
        __syncthreads();
        if (kt + 2 < ntiles) load_stage((kt + 2) % NSTAGE, (kt + 2) * 32);
        cp_commit();

        const int st = kt % NSTAGE;
        const __half* as = As + st * H_STAGE;
        const __half* bs = Bs + st * H_STAGE;

        #pragma unroll
        for (int ks = 0; ks < 2; ks++) {
            const int kk = ks * 16;
            unsigned af[4][4];
            #pragma unroll
            for (int mi = 0; mi < 4; mi++) {
                int rb = warp_m * 64 + mi * 16;
                const __half* ap = &as[(rb + g) * HSTRIDE + kk + 2 * t];
                af[mi][0] = *reinterpret_cast<const unsigned*>(ap);
                af[mi][1] = *reinterpret_cast<const unsigned*>(ap + 8 * HSTRIDE);
                af[mi][2] = *reinterpret_cast<const unsigned*>(ap + 8);
                af[mi][3] = *reinterpret_cast<const unsigned*>(ap + 8 * HSTRIDE + 8);
            }
            unsigned bf[4][2];
            #pragma unroll
            for (int ni = 0; ni < 4; ni++) {
                int nb = warp_n * 32 + ni * 8;
                const __half* bp = &bs[(nb + g) * HSTRIDE + kk + 2 * t];
                bf[ni][0] = *reinterpret_cast<const unsigned*>(bp);
                bf[ni][1] = *reinterpret_cast<const unsigned*>(bp + 8);
            }
            #pragma unroll
            for (int mi = 0; mi < 4; mi++)
                #pragma unroll
                for (int ni = 0; ni < 4; ni++) {
                    asm volatile(
                        "mma.sync.aligned.m16n8k16.row.col.f32.f16.f16.f32 "
                        "{%0,%1,%2,%3}, {%4,%5,%6,%7}, {%8,%9}, {%0,%1,%2,%3};"
                        : "+f"(acc[mi][ni][0]), "+f"(acc[mi][ni][1]),
                          "+f"(acc[mi][ni][2]), "+f"(acc[mi][ni][3])
                        : "r"(af[mi][0]), "r"(af[mi][1]), "r"(af[mi][2]), "r"(af[mi][3]),
                          "r"(bf[ni][0]), "r"(bf[ni][1]));
                }
        }
    }

    #pragma unroll
    for (int mi = 0; mi < 4; mi++) {
        int rb = row0 + warp_m * 64 + mi * 16 + g;
        #pragma unroll
        for (int ni = 0; ni < 4; ni++) {
            int cb = col0 + warp_n * 32 + ni * 8 + 2 * t;
            #pragma unroll
            for (int half = 0; half < 2; half++) {
                int r = rb + half * 8;
                if (r >= M) continue;
                float v0 = acc[mi][ni][half * 2 + 0];
                float v1 = acc[mi][ni][half * 2 + 1];
                if (bias) { v0 += bias[cb]; v1 += bias[cb + 1]; }
                if (relu) { v0 = fmaxf(v0, 0.f); v1 = fmaxf(v1, 0.f); }
                if (Ch) {
                    *reinterpret_cast<__half2*>(&Ch[(size_t)r * Nc + cb]) =
                        __floats2half2_rn(v0, v1);
                } else {
                    *reinterpret_cast<float2*>(&Cf[(size_t)r * Nc + cb]) =
                        make_float2(v0, v1);
                }
            }
        }
    }
}

// ---------------- conversions ----------------
__global__ void f2h_copy(const float* __restrict__ in, __half* __restrict__ out, int n)
{
    int i = blockIdx.x * blockDim.x + threadIdx.x;
    if (i < n) out[i] = __float2half_rn(in[i]);
}

// src fp32 [R][C] -> dst fp16 [C][R]
__global__ void transpose_h(const float* __restrict__ src, __half* __restrict__ dst,
                            int R, int C)
{
    __shared__ float t[32][33];
    int cb = blockIdx.x * 32, rb = blockIdx.y * 32;
    int tx = threadIdx.x, ty = threadIdx.y;  // 32 x 8
    #pragma unroll
    for (int j = 0; j < 4; j++)
        t[ty + j * 8][tx] = src[(size_t)(rb + ty + j * 8) * C + cb + tx];
    __syncthreads();
    #pragma unroll
    for (int j = 0; j < 4; j++)
        dst[(size_t)(cb + ty + j * 8) * R + rb + tx] = __float2half_rn(t[tx][ty + j * 8]);
}

// ---------------- CSR build ----------------
__global__ void hist_dst(const int* __restrict__ dst, int* __restrict__ cnt)
{
    int i = blockIdx.x * blockDim.x + threadIdx.x;
    if (i < EE) atomicAdd(&cnt[dst[i]], 1);
}

__global__ __launch_bounds__(1024) void scan_offsets(const int* __restrict__ cnt,
                                                     int* __restrict__ off,
                                                     int* __restrict__ cur)
{
    __shared__ int wsum[32];
    __shared__ int carry_s;
    const int lane = threadIdx.x & 31;
    const int wid = threadIdx.x >> 5;
    if (threadIdx.x == 0) carry_s = 0;
    __syncthreads();
    for (int base = 0; base < NN; base += 1024) {
        int i = base + threadIdx.x;
        int v = (i < NN) ? cnt[i] : 0;
        int x = v;
        #pragma unroll
        for (int s = 1; s < 32; s <<= 1) {
            int t = __shfl_up_sync(0xffffffffu, x, s);
            if (lane >= s) x += t;
        }
        if (lane == 31) wsum[wid] = x;
        __syncthreads();
        if (wid == 0) {
            int w = wsum[lane];
            #pragma unroll
            for (int s = 1; s < 32; s <<= 1) {
                int t = __shfl_up_sync(0xffffffffu, w, s);
                if (lane >= s) w += t;
            }
            wsum[lane] = w;
        }
        __syncthreads();
        int warp_prefix = (wid > 0) ? wsum[wid - 1] : 0;
        int carry = carry_s;
        int excl = carry + warp_prefix + x - v;
        if (i < NN) { off[i] = excl; cur[i] = excl; }
        __syncthreads();
        if (threadIdx.x == 1023) carry_s = carry + wsum[31];
        __syncthreads();
    }
    if (threadIdx.x == 0) off[NN] = carry_s;
}

__global__ void scatter_csr(const int* __restrict__ src, const int* __restrict__ dst,
                            int* __restrict__ cur, int* __restrict__ csrc)
{
    int i = blockIdx.x * blockDim.x + threadIdx.x;
    if (i >= EE) return;
    int pos = atomicAdd(&cur[dst[i]], 1);
    csrc[pos] = src[i];
}

// ---------------- fused attention gather: one warp per dst node ----------------
// qkv fp16 [NN,768]: q +0, k +256, v +512. agg out fp16.
__global__ __launch_bounds__(256) void attn_gather(
    const int* __restrict__ off, const int* __restrict__ csrc,
    const __half* __restrict__ qkv, __half* __restrict__ agg)
{
    int node = (blockIdx.x * blockDim.x + threadIdx.x) >> 5;
    int lane = threadIdx.x & 31;
    if (node >= NN) return;
    const int h = lane >> 2;
    const int sub = lane & 3;
    const int doff = h * 32 + sub * 8;

    int beg = off[node], end = off[node + 1];

    // q: 8 halfs -> 8 floats
    uint4 qb = *reinterpret_cast<const uint4*>(&qkv[(size_t)node * QKVW + doff]);
    float2 qf0 = __half22float2(*reinterpret_cast<__half2*>(&qb.x));
    float2 qf1 = __half22float2(*reinterpret_cast<__half2*>(&qb.y));
    float2 qf2 = __half22float2(*reinterpret_cast<__half2*>(&qb.z));
    float2 qf3 = __half22float2(*reinterpret_cast<__half2*>(&qb.w));

    const float scale = 0.17677669529663687f;

    float mA = -INFINITY, zA = 0.f;
    float mB = -INFINITY, zB = 0.f;
    float accA[8], accB[8];
    #pragma unroll
    for (int j = 0; j < 8; j++) { accA[j] = 0.f; accB[j] = 0.f; }

    int p = beg;
    for (; p + 1 < end; p += 2) {
        int sA = csrc[p];
        int sB = csrc[p + 1];
        const __half* bA = qkv + (size_t)sA * QKVW + 256 + doff;
        const __half* bB = qkv + (size_t)sB * QKVW + 256 + doff;
        uint4 krA = *reinterpret_cast<const uint4*>(bA);
        uint4 krB = *reinterpret_cast<const uint4*>(bB);
        uint4 vrA = *reinterpret_cast<const uint4*>(bA + 256);
        uint4 vrB = *reinterpret_cast<const uint4*>(bB + 256);

        float2 kA0 = __half22float2(*reinterpret_cast<__half2*>(&krA.x));
        float2 kA1 = __half22float2(*reinterpret_cast<__half2*>(&krA.y));
        float2 kA2 = __half22float2(*reinterpret_cast<__half2*>(&krA.z));
        float2 kA3 = __half22float2(*reinterpret_cast<__half2*>(&krA.w));
        float2 kB0 = __half22float2(*reinterpret_cast<__half2*>(&krB.x));
        float2 kB1 = __half22float2(*reinterpret_cast<__half2*>(&krB.y));
        float2 kB2 = __half22float2(*reinterpret_cast<__half2*>(&krB.z));
        float2 kB3 = __half22float2(*reinterpret_cast<__half2*>(&krB.w));

        float pA = qf0.x * kA0.x + qf0.y * kA0.y + qf1.x * kA1.x + qf1.y * kA1.y
                 + qf2.x * kA2.x + qf2.y * kA2.y + qf3.x * kA3.x + qf3.y * kA3.y;
        float pB = qf0.x * kB0.x + qf0.y * kB0.y + qf1.x * kB1.x + qf1.y * kB1.y
                 + qf2.x * kB2.x + qf2.y * kB2.y + qf3.x * kB3.x + qf3.y * kB3.y;
        pA += __shfl_xor_sync(0xffffffffu, pA, 1);
        pB += __shfl_xor_sync(0xffffffffu, pB, 1);
        pA += __shfl_xor_sync(0xffffffffu, pA, 2);
        pB += __shfl_xor_sync(0xffffffffu, pB, 2);

        float lA = pA * scale;
        float lB = pB * scale;

        float2 vA0 = __half22float2(*reinterpret_cast<__half2*>(&vrA.x));
        float2 vA1 = __half22float2(*reinterpret_cast<__half2*>(&vrA.y));
        float2 vA2 = __half22float2(*reinterpret_cast<__half2*>(&vrA.z));
        float2 vA3 = __half22float2(*reinterpret_cast<__half2*>(&vrA.w));
        float2 vB0 = __half22float2(*reinterpret_cast<__half2*>(&vrB.x));
        float2 vB1 = __half22float2(*reinterpret_cast<__half2*>(&vrB.y));
        float2 vB2 = __half22float2(*reinterpret_cast<__half2*>(&vrB.z));
        float2 vB3 = __half22float2(*reinterpret_cast<__half2*>(&vrB.w));

        float nmA = fmaxf(mA, lA);
        float fA = __expf(mA - nmA);
        float aA = __expf(lA - nmA);
        zA = zA * fA + aA;
        mA = nmA;
        accA[0] = accA[0] * fA + aA * vA0.x;
        accA[1] = accA[1] * fA + aA * vA0.y;
        accA[2] = accA[2] * fA + aA * vA1.x;
        accA[3] = accA[3] * fA + aA * vA1.y;
        accA[4] = accA[4] * fA + aA * vA2.x;
        accA[5] = accA[5] * fA + aA * vA2.y;
        accA[6] = accA[6] * fA + aA * vA3.x;
        accA[7] = accA[7] * fA + aA * vA3.y;

        float nmB = fmaxf(mB, lB);
        float fB = __expf(mB - nmB);
        float aB = __expf(lB - nmB);
        zB = zB * fB + aB;
        mB = nmB;
        accB[0] = accB[0] * fB + aB * vB0.x;
        accB[1] = accB[1] * fB + aB * vB0.y;
        accB[2] = accB[2] * fB + aB * vB1.x;
        accB[3] = accB[3] * fB + aB * vB1.y;
        accB[4] = accB[4] * fB + aB * vB2.x;
        accB[5] = accB[5] * fB + aB * vB2.y;
        accB[6] = accB[6] * fB + aB * vB3.x;
        accB[7] = accB[7] * fB + aB * vB3.y;
    }
    if (p < end) {
        int s = csrc[p];
        const __half* b = qkv + (size_t)s * QKVW + 256 + doff;
        uint4 kr = *reinterpret_cast<const uint4*>(b);
        uint4 vr = *reinterpret_cast<const uint4*>(b + 256);
        float2 k0 = __half22float2(*reinterpret_cast<__half2*>(&kr.x));
        float2 k1 = __half22float2(*reinterpret_cast<__half2*>(&kr.y));
        float2 k2 = __half22float2(*reinterpret_cast<__half2*>(&kr.z));
        float2 k3 = __half22float2(*reinterpret_cast<__half2*>(&kr.w));
        float part = qf0.x * k0.x + qf0.y * k0.y + qf1.x * k1.x + qf1.y * k1.y
                   + qf2.x * k2.x + qf2.y * k2.y + qf3.x * k3.x + qf3.y * k3.y;
        part += __shfl_xor_sync(0xffffffffu, part, 1);
        part += __shfl_xor_sync(0xffffffffu, part, 2);
        float logit = part * scale;
        float2 v0 = __half22float2(*reinterpret_cast<__half2*>(&vr.x));
        float2 v1 = __half22float2(*reinterpret_cast<__half2*>(&vr.y));
        float2 v2 = __half22float2(*reinterpret_cast<__half2*>(&vr.z));
        float2 v3 = __half22float2(*reinterpret_cast<__half2*>(&vr.w));
        float nm = fmaxf(mA, logit);
        float f = __expf(mA - nm);
        float a = __expf(logit - nm);
        zA = zA * f + a;
        mA = nm;
        accA[0] = accA[0] * f + a * v0.x;
        accA[1] = accA[1] * f + a * v0.y;
        accA[2] = accA[2] * f + a * v1.x;
        accA[3] = accA[3] * f + a * v1.y;
        accA[4] = accA[4] * f + a * v2.x;
        accA[5] = accA[5] * f + a * v2.y;
        accA[6] = accA[6] * f + a * v3.x;
        accA[7] = accA[7] * f + a * v3.y;
    }

    float m = fmaxf(mA, mB);
    float fA = (zA > 0.f) ? __expf(mA - m) : 0.f;
    float fB = (zB > 0.f) ? __expf(mB - m) : 0.f;
    float z = zA * fA + zB * fB;
    float inv = 1.f / (z + 1e-9f);

    uint4 outw;
    float o[8];
    #pragma unroll
    for (int j = 0; j < 8; j++) o[j] = (accA[j] * fA + accB[j] * fB) * inv;
    if (end == beg) {
        #pragma unroll
        for (int j = 0; j < 8; j++) o[j] = 0.f;
    }
    *reinterpret_cast<__half2*>(&outw.x) = __floats2half2_rn(o[0], o[1]);
    *reinterpret_cast<__half2*>(&outw.y) = __floats2half2_rn(o[2], o[3]);
    *reinterpret_cast<__half2*>(&outw.z) = __floats2half2_rn(o[4], o[5]);
    *reinterpret_cast<__half2*>(&outw.w) = __floats2half2_rn(o[6], o[7]);
    *reinterpret_cast<uint4*>(&agg[(size_t)node * DD + doff]) = outw;
}

// ---------------- residual + layernorm (fp16 in/out, fp32 math) ----------------
__global__ void ln_residual(const __half* __restrict__ attn, __half* __restrict__ h,
                            const float* __restrict__ gamma, const float* __restrict__ beta)
{
    int row = (blockIdx.x * blockDim.x + threadIdx.x) >> 5;
    int lane = threadIdx.x & 31;
    if (row >= NN) return;
    float x[8];
    float s = 0.f;
    #pragma unroll
    for (int j = 0; j < 8; j++) {
        int idx = row * DD + j * 32 + lane;
        x[j] = __half2float(attn[idx]) + __half2float(h[idx]);
        s += x[j];
    }
    #pragma unroll
    for (int off = 16; off; off >>= 1) s += __shfl_xor_sync(0xffffffffu, s, off);
    float mu = s * (1.f / DD);
    float vs = 0.f;
    #pragma unroll
    for (int j = 0; j < 8; j++) { float dlt = x[j] - mu; vs += dlt * dlt; }
    #pragma unroll
    for (int off = 16; off; off >>= 1) vs += __shfl_xor_sync(0xffffffffu, vs, off);
    float inv = rsqrtf(vs * (1.f / DD) + 1e-5f);
    #pragma unroll
    for (int j = 0; j < 8; j++) {
        int c = j * 32 + lane;
        h[row * DD + c] = __float2half_rn((x[j] - mu) * inv * gamma[c] + beta[c]);
    }
}

// ---------------- launch ----------------
extern "C" void kernel_launch(void* const* d_in, const int* in_sizes, int n_in,
                              void* d_out, int out_size)
{
    const float* h_in = (const float*)d_in[0];
    const int* src = (const int*)d_in[1];
    const int* dst = (const int*)d_in[2];
    const float* Wq = (const float*)d_in[3];
    const float* Wk = (const float*)d_in[4];
    const float* Wv = (const float*)d_in[5];
    const float* Wo = (const float*)d_in[6];
    const float* ln_g = (const float*)d_in[7];
    const float* ln_b = (const float*)d_in[8];
    const float* w1 = (const float*)d_in[9];
    const float* b1 = (const float*)d_in[10];
    const float* w2 = (const float*)d_in[11];
    const float* b2 = (const float*)d_in[12];
    float* out = (float*)d_out;

    __half *ph16, *pqkv16, *pagg16, *pattn16, *pffn16, *pwqkvT, *pwoT, *pw1T, *pw2T;
    int *pcnt, *poff, *pcur, *pcsrc;
    cudaGetSymbolAddress((void**)&ph16, g_h16);
    cudaGetSymbolAddress((void**)&pqkv16, g_qkv16);
    cudaGetSymbolAddress((void**)&pagg16, g_agg16);
    cudaGetSymbolAddress((void**)&pattn16, g_attn16);
    cudaGetSymbolAddress((void**)&pffn16, g_ffn16);
    cudaGetSymbolAddress((void**)&pwqkvT, g_wqkvT);
    cudaGetSymbolAddress((void**)&pwoT, g_woT);
    cudaGetSymbolAddress((void**)&pw1T, g_w1T);
    cudaGetSymbolAddress((void**)&pw2T, g_w2T);
    cudaGetSymbolAddress((void**)&pcnt, g_cnt);
    cudaGetSymbolAddress((void**)&poff, g_off);
    cudaGetSymbolAddress((void**)&pcur, g_cur);
    cudaGetSymbolAddress((void**)&pcsrc, g_csrc);

    static cudaStream_t s2 = nullptr;
    static cudaEvent_t ev_fork = nullptr, ev_join = nullptr;
    static bool init_done = false;
    if (!init_done) {
        cudaFuncSetAttribute(gemm_h, cudaFuncAttributeMaxDynamicSharedMemorySize, GEMM_SMEM);
        cudaStreamCreateWithFlags(&s2, cudaStreamNonBlocking);
        cudaEventCreateWithFlags(&ev_fork, cudaEventDisableTiming);
        cudaEventCreateWithFlags(&ev_join, cudaEventDisableTiming);
        init_done = true;
    }

    dim3 tb(32, 8);

    // fork: CSR build + Wo/FFN weight transposes on s2
    cudaEventRecord(ev_fork, 0);
    cudaStreamWaitEvent(s2, ev_fork, 0);

    cudaMemsetAsync(pcnt, 0, NN * sizeof(int), s2);
    hist_dst<<<(EE + 255) / 256, 256, 0, s2>>>(dst, pcnt);
    scan_offsets<<<1, 1024, 0, s2>>>(pcnt, poff, pcur);
    scatter_csr<<<(EE + 255) / 256, 256, 0, s2>>>(src, dst, pcur, pcsrc);
    for (int l = 0; l < LL; l++)
        transpose_h<<<dim3(DD / 32, DD / 32), tb, 0, s2>>>(
            Wo + (size_t)l * DD * DD, pwoT + (size_t)l * DD * DD, DD, DD);
    transpose_h<<<dim3(HUSZ / 32, DD / 32), tb, 0, s2>>>(w1, pw1T, DD, HUSZ);
    transpose_h<<<dim3(DD / 32, HUSZ / 32), tb, 0, s2>>>(w2, pw2T, HUSZ, DD);
    cudaEventRecord(ev_join, s2);

    // main stream: h -> fp16; qkv weight transposes (needed first)
    f2h_copy<<<(NN * DD + 255) / 256, 256>>>(h_in, ph16, NN * DD);
    for (int l = 0; l < LL; l++) {
        __half* dstT = pwqkvT + (size_t)l * QKVW * DD;
        transpose_h<<<dim3(DD / 32, DD / 32), tb>>>(Wq + (size_t)l * DD * DD, dstT, DD, DD);
        transpose_h<<<dim3(DD / 32, DD / 32), tb>>>(Wk + (size_t)l * DD * DD, dstT + 256 * DD, DD, DD);
        transpose_h<<<dim3(DD / 32, DD / 32), tb>>>(Wv + (size_t)l * DD * DD, dstT + 512 * DD, DD, DD);
    }

    dim3 grid_qkv(QKVW / 128, (NN + 127) / 128);
    dim3 grid_d(DD / 128, (NN + 127) / 128);
    dim3 grid_hus(HUSZ / 128, (NN + 127) / 128);

    for (int l = 0; l < LL; l++) {
        const __half* wqkvT = pwqkvT + (size_t)l * QKVW * DD;
        const __half* woT = pwoT + (size_t)l * DD * DD;
        const float* lg = ln_g + (size_t)l * DD;
        const float* lb = ln_b + (size_t)l * DD;

        gemm_h<<<grid_qkv, 256, GEMM_SMEM>>>(ph16, wqkvT, nullptr, nullptr, pqkv16,
                                             NN, QKVW, DD, 0);
        if (l == 0) cudaStreamWaitEvent(0, ev_join, 0);
        attn_gather<<<(NN * 32 + 255) / 256, 256>>>(poff, pcsrc, pqkv16, pagg16);
        gemm_h<<<grid_d, 256, GEMM_SMEM>>>(pagg16, woT, nullptr, nullptr, pattn16,
                                           NN, DD, DD, 0);
        ln_residual<<<(NN * 32 + 255) / 256, 256>>>(pattn16, ph16, lg, lb);
    }

    gemm_h<<<grid_hus, 256, GEMM_SMEM>>>(ph16, pw1T, b1, nullptr, pffn16,
                                         NN, HUSZ, DD, 1);
    gemm_h<<<grid_d, 256, GEMM_SMEM>>>(pffn16, pw2T, b2, out, nullptr,
                                       NN, DD, HUSZ, 0);
}

// round 12
// speedup vs baseline: 5.6063x; 1.0544x over previous
#include <cuda_runtime.h>
#include <cuda_fp16.h>
#include <math.h>
#include <stdint.h>

#define NN 20000
#define EE 320000
#define DD 256
#define HH 8
#define LL 2
#define HUSZ 1024
#define QKVW 768

// ---------------- scratch (no allocation allowed) ----------------
__device__ __half g_h16[NN * DD];
__device__ __half g_qkv16[NN * QKVW];
__device__ __half g_agg16[NN * DD];
__device__ __half g_attn16[NN * DD];
__device__ __half g_ffn16[NN * HUSZ];
__device__ __half g_wqkvT[LL * QKVW * DD];
__device__ __half g_woT[LL * DD * DD];
__device__ __half g_w1T[HUSZ * DD];
__device__ __half g_w2T[DD * HUSZ];
__device__ int    g_cnt[NN];
__device__ int    g_off[NN + 1];
__device__ int    g_cur[NN];
__device__ int    g_csrc[EE];

// ---------------- helpers ----------------
__device__ __forceinline__ void cp16h(__half* smem_ptr, const __half* gptr, bool p) {
    unsigned s = (unsigned)__cvta_generic_to_shared(smem_ptr);
    int bytes = p ? 16 : 0;
    asm volatile("cp.async.cg.shared.global [%0], [%1], 16, %2;\n"
                 :: "r"(s), "l"(gptr), "r"(bytes));
}
__device__ __forceinline__ void cp_commit() { asm volatile("cp.async.commit_group;\n" ::: "memory"); }
template <int N>
__device__ __forceinline__ void cp_wait() { asm volatile("cp.async.wait_group %0;\n" :: "n"(N) : "memory"); }

// ---------------- fp16 tensor-core GEMM (m16n8k16), ldmatrix frags ----------
#define HSTRIDE 40                      // halfs per smem row (80B: 16B-aligned, LDSM conflict-free)
#define H_STAGE (128 * HSTRIDE)
#define NSTAGE 3
#define GEMM_SMEM ((size_t)NSTAGE * 2 * H_STAGE * sizeof(__half))

__global__ __launch_bounds__(256) void gemm_h(
    const __half* __restrict__ A, const __half* __restrict__ BT,
    const float* __restrict__ bias, float* __restrict__ Cf, __half* __restrict__ Ch,
    int M, int Nc, int Kc, int relu)
{
    extern __shared__ __half smh[];

    const int tid = threadIdx.x;
    const int wid = tid >> 5;
    const int lane = tid & 31;
    const int g = lane >> 2;
    const int t = lane & 3;

    const int warp_m = wid >> 2;
    const int warp_n = wid & 3;
    const int row0 = blockIdx.y * 128;
    const int col0 = blockIdx.x * 128;

    const uint32_t sh0 = (uint32_t)__cvta_generic_to_shared(smh);

    // per-lane ldmatrix offsets (halfs)
    const int a_lane = ((lane & 7) + ((lane >> 3) & 1) * 8) * HSTRIDE + (lane >> 4) * 8;
    const int b_lane = (lane & 7) * HSTRIDE + ((lane >> 3) & 1) * 8;

    float acc[4][4][4];
    #pragma unroll
    for (int mi = 0; mi < 4; mi++)
        #pragma unroll
        for (int ni = 0; ni < 4; ni++)
            #pragma unroll
            for (int r = 0; r < 4; r++) acc[mi][ni][r] = 0.f;

    const int ntiles = Kc >> 5;

    auto load_stage = [&](int st, int k0) {
        __half* as = smh + st * H_STAGE;
        __half* bs = smh + (NSTAGE + st) * H_STAGE;
        #pragma unroll
        for (int i = 0; i < 2; i++) {
            int lin = i * 256 + tid;
            int row = lin >> 2;
            int seg = (lin & 3) * 8;
            cp16h(&as[row * HSTRIDE + seg],
                  &A[(size_t)(row0 + row) * Kc + k0 + seg],
                  row0 + row < M);
            cp16h(&bs[row * HSTRIDE + seg],
                  &BT[(size_t)(col0 + row) * Kc + k0 + seg],
                  true);
        }
    };

    load_stage(0, 0);
    cp_commit();
    load_stage(1, 32);
    cp_commit();

    for (int kt = 0; kt < ntiles; kt++) {
        cp_wait<1>();
        __syncthreads();
        if (kt + 2 < ntiles) load_stage((kt + 2) % NSTAGE, (kt + 2) * 32);
        cp_commit();

        const int st = kt % NSTAGE;
        const uint32_t as_b = sh0 + (uint32_t)(st * H_STAGE) * 2;
        const uint32_t bs_b = sh0 + (uint32_t)((NSTAGE + st) * H_STAGE) * 2;

        #pragma unroll
        for (int ks = 0; ks < 2; ks++) {
            const int kk = ks * 16;
            const uint32_t a_base = as_b + 2u * (warp_m * 64 * HSTRIDE + kk + a_lane);
            const uint32_t b_base = bs_b + 2u * (warp_n * 32 * HSTRIDE + kk + b_lane);

            unsigned af[4][4];
            #pragma unroll
            for (int mi = 0; mi < 4; mi++) {
                uint32_t addr = a_base + 2u * (mi * 16 * HSTRIDE);
                asm volatile("ldmatrix.sync.aligned.m8n8.x4.shared.b16 {%0,%1,%2,%3}, [%4];"
                             : "=r"(af[mi][0]), "=r"(af[mi][1]), "=r"(af[mi][2]), "=r"(af[mi][3])
                             : "r"(addr));
            }
            unsigned bf[4][2];
            #pragma unroll
            for (int ni = 0; ni < 4; ni++) {
                uint32_t addr = b_base + 2u * (ni * 8 * HSTRIDE);
                asm volatile("ldmatrix.sync.aligned.m8n8.x2.shared.b16 {%0,%1}, [%2];"
                             : "=r"(bf[ni][0]), "=r"(bf[ni][1])
                             : "r"(addr));
            }
            #pragma unroll
            for (int mi = 0; mi < 4; mi++)
                #pragma unroll
                for (int ni = 0; ni < 4; ni++) {
                    asm volatile(
                        "mma.sync.aligned.m16n8k16.row.col.f32.f16.f16.f32 "
                        "{%0,%1,%2,%3}, {%4,%5,%6,%7}, {%8,%9}, {%0,%1,%2,%3};"
                        : "+f"(acc[mi][ni][0]), "+f"(acc[mi][ni][1]),
                          "+f"(acc[mi][ni][2]), "+f"(acc[mi][ni][3])
                        : "r"(af[mi][0]), "r"(af[mi][1]), "r"(af[mi][2]), "r"(af[mi][3]),
                          "r"(bf[ni][0]), "r"(bf[ni][1]));
                }
        }
    }

    #pragma unroll
    for (int mi = 0; mi < 4; mi++) {
        int rb = row0 + warp_m * 64 + mi * 16 + g;
        #pragma unroll
        for (int ni = 0; ni < 4; ni++) {
            int cb = col0 + warp_n * 32 + ni * 8 + 2 * t;
            #pragma unroll
            for (int half = 0; half < 2; half++) {
                int r = rb + half * 8;
                if (r >= M) continue;
                float v0 = acc[mi][ni][half * 2 + 0];
                float v1 = acc[mi][ni][half * 2 + 1];
                if (bias) { v0 += bias[cb]; v1 += bias[cb + 1]; }
                if (relu) { v0 = fmaxf(v0, 0.f); v1 = fmaxf(v1, 0.f); }
                if (Ch) {
                    *reinterpret_cast<__half2*>(&Ch[(size_t)r * Nc + cb]) =
                        __floats2half2_rn(v0, v1);
                } else {
                    *reinterpret_cast<float2*>(&Cf[(size_t)r * Nc + cb]) =
                        make_float2(v0, v1);
                }
            }
        }
    }
}

// ---------------- conversions ----------------
__global__ void f2h_copy(const float* __restrict__ in, __half* __restrict__ out, int n)
{
    int i = blockIdx.x * blockDim.x + threadIdx.x;
    if (i < n) out[i] = __float2half_rn(in[i]);
}

__global__ void transpose_h(const float* __restrict__ src, __half* __restrict__ dst,
                            int R, int C)
{
    __shared__ float t[32][33];
    int cb = blockIdx.x * 32, rb = blockIdx.y * 32;
    int tx = threadIdx.x, ty = threadIdx.y;
    #pragma unroll
    for (int j = 0; j < 4; j++)
        t[ty + j * 8][tx] = src[(size_t)(rb + ty + j * 8) * C + cb + tx];
    __syncthreads();
    #pragma unroll
    for (int j = 0; j < 4; j++)
        dst[(size_t)(cb + ty + j * 8) * R + rb + tx] = __float2half_rn(t[tx][ty + j * 8]);
}

// ---------------- CSR build ----------------
__global__ void hist_dst(const int* __restrict__ dst, int* __restrict__ cnt)
{
    int i = blockIdx.x * blockDim.x + threadIdx.x;
    if (i < EE) atomicAdd(&cnt[dst[i]], 1);
}

__global__ __launch_bounds__(1024) void scan_offsets(const int* __restrict__ cnt,
                                                     int* __restrict__ off,
                                                     int* __restrict__ cur)
{
    __shared__ int wsum[32];
    __shared__ int carry_s;
    const int lane = threadIdx.x & 31;
    const int wid = threadIdx.x >> 5;
    if (threadIdx.x == 0) carry_s = 0;
    __syncthreads();
    for (int base = 0; base < NN; base += 1024) {
        int i = base + threadIdx.x;
        int v = (i < NN) ? cnt[i] : 0;
        int x = v;
        #pragma unroll
        for (int s = 1; s < 32; s <<= 1) {
            int t = __shfl_up_sync(0xffffffffu, x, s);
            if (lane >= s) x += t;
        }
        if (lane == 31) wsum[wid] = x;
        __syncthreads();
        if (wid == 0) {
            int w = wsum[lane];
            #pragma unroll
            for (int s = 1; s < 32; s <<= 1) {
                int t = __shfl_up_sync(0xffffffffu, w, s);
                if (lane >= s) w += t;
            }
            wsum[lane] = w;
        }
        __syncthreads();
        int warp_prefix = (wid > 0) ? wsum[wid - 1] : 0;
        int carry = carry_s;
        int excl = carry + warp_prefix + x - v;
        if (i < NN) { off[i] = excl; cur[i] = excl; }
        __syncthreads();
        if (threadIdx.x == 1023) carry_s = carry + wsum[31];
        __syncthreads();
    }
    if (threadIdx.x == 0) off[NN] = carry_s;
}

__global__ void scatter_csr(const int* __restrict__ src, const int* __restrict__ dst,
                            int* __restrict__ cur, int* __restrict__ csrc)
{
    int i = blockIdx.x * blockDim.x + threadIdx.x;
    if (i >= EE) return;
    int pos = atomicAdd(&cur[dst[i]], 1);
    csrc[pos] = src[i];
}

// ---------------- fused attention gather: one warp per dst node ----------------
__global__ __launch_bounds__(256) void attn_gather(
    const int* __restrict__ off, const int* __restrict__ csrc,
    const __half* __restrict__ qkv, __half* __restrict__ agg)
{
    int node = (blockIdx.x * blockDim.x + threadIdx.x) >> 5;
    int lane = threadIdx.x & 31;
    if (node >= NN) return;
    const int h = lane >> 2;
    const int sub = lane & 3;
    const int doff = h * 32 + sub * 8;

    int beg = off[node], end = off[node + 1];

    uint4 qb = *reinterpret_cast<const uint4*>(&qkv[(size_t)node * QKVW + doff]);
    float2 qf0 = __half22float2(*reinterpret_cast<__half2*>(&qb.x));
    float2 qf1 = __half22float2(*reinterpret_cast<__half2*>(&qb.y));
    float2 qf2 = __half22float2(*reinterpret_cast<__half2*>(&qb.z));
    float2 qf3 = __half22float2(*reinterpret_cast<__half2*>(&qb.w));

    const float scale = 0.17677669529663687f;

    float mA = -INFINITY, zA = 0.f;
    float mB = -INFINITY, zB = 0.f;
    float accA[8], accB[8];
    #pragma unroll
    for (int j = 0; j < 8; j++) { accA[j] = 0.f; accB[j] = 0.f; }

    int p = beg;
    for (; p + 1 < end; p += 2) {
        int sA = csrc[p];
        int sB = csrc[p + 1];
        const __half* bA = qkv + (size_t)sA * QKVW + 256 + doff;
        const __half* bB = qkv + (size_t)sB * QKVW + 256 + doff;
        uint4 krA = *reinterpret_cast<const uint4*>(bA);
        uint4 krB = *reinterpret_cast<const uint4*>(bB);
        uint4 vrA = *reinterpret_cast<const uint4*>(bA + 256);
        uint4 vrB = *reinterpret_cast<const uint4*>(bB + 256);

        float2 kA0 = __half22float2(*reinterpret_cast<__half2*>(&krA.x));
        float2 kA1 = __half22float2(*reinterpret_cast<__half2*>(&krA.y));
        float2 kA2 = __half22float2(*reinterpret_cast<__half2*>(&krA.z));
        float2 kA3 = __half22float2(*reinterpret_cast<__half2*>(&krA.w));
        float2 kB0 = __half22float2(*reinterpret_cast<__half2*>(&krB.x));
        float2 kB1 = __half22float2(*reinterpret_cast<__half2*>(&krB.y));
        float2 kB2 = __half22float2(*reinterpret_cast<__half2*>(&krB.z));
        float2 kB3 = __half22float2(*reinterpret_cast<__half2*>(&krB.w));

        float pA = qf0.x * kA0.x + qf0.y * kA0.y + qf1.x * kA1.x + qf1.y * kA1.y
                 + qf2.x * kA2.x + qf2.y * kA2.y + qf3.x * kA3.x + qf3.y * kA3.y;
        float pB = qf0.x * kB0.x + qf0.y * kB0.y + qf1.x * kB1.x + qf1.y * kB1.y
                 + qf2.x * kB2.x + qf2.y * kB2.y + qf3.x * kB3.x + qf3.y * kB3.y;
        pA += __shfl_xor_sync(0xffffffffu, pA, 1);
        pB += __shfl_xor_sync(0xffffffffu, pB, 1);
        pA += __shfl_xor_sync(0xffffffffu, pA, 2);
        pB += __shfl_xor_sync(0xffffffffu, pB, 2);

        float lA = pA * scale;
        float lB = pB * scale;

        float2 vA0 = __half22float2(*reinterpret_cast<__half2*>(&vrA.x));
        float2 vA1 = __half22float2(*reinterpret_cast<__half2*>(&vrA.y));
        float2 vA2 = __half22float2(*reinterpret_cast<__half2*>(&vrA.z));
        float2 vA3 = __half22float2(*reinterpret_cast<__half2*>(&vrA.w));
        float2 vB0 = __half22float2(*reinterpret_cast<__half2*>(&vrB.x));
        float2 vB1 = __half22float2(*reinterpret_cast<__half2*>(&vrB.y));
        float2 vB2 = __half22float2(*reinterpret_cast<__half2*>(&vrB.z));
        float2 vB3 = __half22float2(*reinterpret_cast<__half2*>(&vrB.w));

        float nmA = fmaxf(mA, lA);
        float fA = __expf(mA - nmA);
        float aA = __expf(lA - nmA);
        zA = zA * fA + aA;
        mA = nmA;
        accA[0] = accA[0] * fA + aA * vA0.x;
        accA[1] = accA[1] * fA + aA * vA0.y;
        accA[2] = accA[2] * fA + aA * vA1.x;
        accA[3] = accA[3] * fA + aA * vA1.y;
        accA[4] = accA[4] * fA + aA * vA2.x;
        accA[5] = accA[5] * fA + aA * vA2.y;
        accA[6] = accA[6] * fA + aA * vA3.x;
        accA[7] = accA[7] * fA + aA * vA3.y;

        float nmB = fmaxf(mB, lB);
        float fB = __expf(mB - nmB);
        float aB = __expf(lB - nmB);
        zB = zB * fB + aB;
        mB = nmB;
        accB[0] = accB[0] * fB + aB * vB0.x;
        accB[1] = accB[1] * fB + aB * vB0.y;
        accB[2] = accB[2] * fB + aB * vB1.x;
        accB[3] = accB[3] * fB + aB * vB1.y;
        accB[4] = accB[4] * fB + aB * vB2.x;
        accB[5] = accB[5] * fB + aB * vB2.y;
        accB[6] = accB[6] * fB + aB * vB3.x;
        accB[7] = accB[7] * fB + aB * vB3.y;
    }
    if (p < end) {
        int s = csrc[p];
        const __half* b = qkv + (size_t)s * QKVW + 256 + doff;
        uint4 kr = *reinterpret_cast<const uint4*>(b);
        uint4 vr = *reinterpret_cast<const uint4*>(b + 256);
        float2 k0 = __half22float2(*reinterpret_cast<__half2*>(&kr.x));
        float2 k1 = __half22float2(*reinterpret_cast<__half2*>(&kr.y));
        float2 k2 = __half22float2(*reinterpret_cast<__half2*>(&kr.z));
        float2 k3 = __half22float2(*reinterpret_cast<__half2*>(&kr.w));
        float part = qf0.x * k0.x + qf0.y * k0.y + qf1.x * k1.x + qf1.y * k1.y
                   + qf2.x * k2.x + qf2.y * k2.y + qf3.x * k3.x + qf3.y * k3.y;
        part += __shfl_xor_sync(0xffffffffu, part, 1);
        part += __shfl_xor_sync(0xffffffffu, part, 2);
        float logit = part * scale;
        float2 v0 = __half22float2(*reinterpret_cast<__half2*>(&vr.x));
        float2 v1 = __half22float2(*reinterpret_cast<__half2*>(&vr.y));
        float2 v2 = __half22float2(*reinterpret_cast<__half2*>(&vr.z));
        float2 v3 = __half22float2(*reinterpret_cast<__half2*>(&vr.w));
        float nm = fmaxf(mA, logit);
        float f = __expf(mA - nm);
        float a = __expf(logit - nm);
        zA = zA * f + a;
        mA = nm;
        accA[0] = accA[0] * f + a * v0.x;
        accA[1] = accA[1] * f + a * v0.y;
        accA[2] = accA[2] * f + a * v1.x;
        accA[3] = accA[3] * f + a * v1.y;
        accA[4] = accA[4] * f + a * v2.x;
        accA[5] = accA[5] * f + a * v2.y;
        accA[6] = accA[6] * f + a * v3.x;
        accA[7] = accA[7] * f + a * v3.y;
    }

    float m = fmaxf(mA, mB);
    float fA = (zA > 0.f) ? __expf(mA - m) : 0.f;
    float fB = (zB > 0.f) ? __expf(mB - m) : 0.f;
    float z = zA * fA + zB * fB;
    float inv = 1.f / (z + 1e-9f);

    uint4 outw;
    float o[8];
    #pragma unroll
    for (int j = 0; j < 8; j++) o[j] = (accA[j] * fA + accB[j] * fB) * inv;
    if (end == beg) {
        #pragma unroll
        for (int j = 0; j < 8; j++) o[j] = 0.f;
    }
    *reinterpret_cast<__half2*>(&outw.x) = __floats2half2_rn(o[0], o[1]);
    *reinterpret_cast<__half2*>(&outw.y) = __floats2half2_rn(o[2], o[3]);
    *reinterpret_cast<__half2*>(&outw.z) = __floats2half2_rn(o[4], o[5]);
    *reinterpret_cast<__half2*>(&outw.w) = __floats2half2_rn(o[6], o[7]);
    *reinterpret_cast<uint4*>(&agg[(size_t)node * DD + doff]) = outw;
}

// ---------------- residual + layernorm (fp16 in/out, fp32 math) ----------------
__global__ void ln_residual(const __half* __restrict__ attn, __half* __restrict__ h,
                            const float* __restrict__ gamma, const float* __restrict__ beta)
{
    int row = (blockIdx.x * blockDim.x + threadIdx.x) >> 5;
    int lane = threadIdx.x & 31;
    if (row >= NN) return;
    float x[8];
    float s = 0.f;
    #pragma unroll
    for (int j = 0; j < 8; j++) {
        int idx = row * DD + j * 32 + lane;
        x[j] = __half2float(attn[idx]) + __half2float(h[idx]);
        s += x[j];
    }
    #pragma unroll
    for (int off = 16; off; off >>= 1) s += __shfl_xor_sync(0xffffffffu, s, off);
    float mu = s * (1.f / DD);
    float vs = 0.f;
    #pragma unroll
    for (int j = 0; j < 8; j++) { float dlt = x[j] - mu; vs += dlt * dlt; }
    #pragma unroll
    for (int off = 16; off; off >>= 1) vs += __shfl_xor_sync(0xffffffffu, vs, off);
    float inv = rsqrtf(vs * (1.f / DD) + 1e-5f);
    #pragma unroll
    for (int j = 0; j < 8; j++) {
        int c = j * 32 + lane;
        h[row * DD + c] = __float2half_rn((x[j] - mu) * inv * gamma[c] + beta[c]);
    }
}

// ---------------- launch ----------------
extern "C" void kernel_launch(void* const* d_in, const int* in_sizes, int n_in,
                              void* d_out, int out_size)
{
    const float* h_in = (const float*)d_in[0];
    const int* src = (const int*)d_in[1];
    const int* dst = (const int*)d_in[2];
    const float* Wq = (const float*)d_in[3];
    const float* Wk = (const float*)d_in[4];
    const float* Wv = (const float*)d_in[5];
    const float* Wo = (const float*)d_in[6];
    const float* ln_g = (const float*)d_in[7];
    const float* ln_b = (const float*)d_in[8];
    const float* w1 = (const float*)d_in[9];
    const float* b1 = (const float*)d_in[10];
    const float* w2 = (const float*)d_in[11];
    const float* b2 = (const float*)d_in[12];
    float* out = (float*)d_out;

    __half *ph16, *pqkv16, *pagg16, *pattn16, *pffn16, *pwqkvT, *pwoT, *pw1T, *pw2T;
    int *pcnt, *poff, *pcur, *pcsrc;
    cudaGetSymbolAddress((void**)&ph16, g_h16);
    cudaGetSymbolAddress((void**)&pqkv16, g_qkv16);
    cudaGetSymbolAddress((void**)&pagg16, g_agg16);
    cudaGetSymbolAddress((void**)&pattn16, g_attn16);
    cudaGetSymbolAddress((void**)&pffn16, g_ffn16);
    cudaGetSymbolAddress((void**)&pwqkvT, g_wqkvT);
    cudaGetSymbolAddress((void**)&pwoT, g_woT);
    cudaGetSymbolAddress((void**)&pw1T, g_w1T);
    cudaGetSymbolAddress((void**)&pw2T, g_w2T);
    cudaGetSymbolAddress((void**)&pcnt, g_cnt);
    cudaGetSymbolAddress((void**)&poff, g_off);
    cudaGetSymbolAddress((void**)&pcur, g_cur);
    cudaGetSymbolAddress((void**)&pcsrc, g_csrc);

    static cudaStream_t s2 = nullptr;
    static cudaEvent_t ev_fork = nullptr, ev_join = nullptr;
    static bool init_done = false;
    if (!init_done) {
        cudaFuncSetAttribute(gemm_h, cudaFuncAttributeMaxDynamicSharedMemorySize, GEMM_SMEM);
        cudaStreamCreateWithFlags(&s2, cudaStreamNonBlocking);
        cudaEventCreateWithFlags(&ev_fork, cudaEventDisableTiming);
        cudaEventCreateWithFlags(&ev_join, cudaEventDisableTiming);
        init_done = true;
    }

    dim3 tb(32, 8);

    // fork: CSR build + layer-1 qkv transposes + Wo/FFN transposes on s2
    cudaEventRecord(ev_fork, 0);
    cudaStreamWaitEvent(s2, ev_fork, 0);

    cudaMemsetAsync(pcnt, 0, NN * sizeof(int), s2);
    hist_dst<<<(EE + 255) / 256, 256, 0, s2>>>(dst, pcnt);
    scan_offsets<<<1, 1024, 0, s2>>>(pcnt, poff, pcur);
    scatter_csr<<<(EE + 255) / 256, 256, 0, s2>>>(src, dst, pcur, pcsrc);
    {
        __half* dstT = pwqkvT + (size_t)1 * QKVW * DD;
        transpose_h<<<dim3(DD / 32, DD / 32), tb, 0, s2>>>(Wq + (size_t)1 * DD * DD, dstT, DD, DD);
        transpose_h<<<dim3(DD / 32, DD / 32), tb, 0, s2>>>(Wk + (size_t)1 * DD * DD, dstT + 256 * DD, DD, DD);
        transpose_h<<<dim3(DD / 32, DD / 32), tb, 0, s2>>>(Wv + (size_t)1 * DD * DD, dstT + 512 * DD, DD, DD);
    }
    for (int l = 0; l < LL; l++)
        transpose_h<<<dim3(DD / 32, DD / 32), tb, 0, s2>>>(
            Wo + (size_t)l * DD * DD, pwoT + (size_t)l * DD * DD, DD, DD);
    transpose_h<<<dim3(HUSZ / 32, DD / 32), tb, 0, s2>>>(w1, pw1T, DD, HUSZ);
    transpose_h<<<dim3(DD / 32, HUSZ / 32), tb, 0, s2>>>(w2, pw2T, HUSZ, DD);
    cudaEventRecord(ev_join, s2);

    // main stream: h -> fp16; layer-0 qkv weight transposes only
    f2h_copy<<<(NN * DD + 255) / 256, 256>>>(h_in, ph16, NN * DD);
    transpose_h<<<dim3(DD / 32, DD / 32), tb>>>(Wq, pwqkvT, DD, DD);
    transpose_h<<<dim3(DD / 32, DD / 32), tb>>>(Wk, pwqkvT + 256 * DD, DD, DD);
    transpose_h<<<dim3(DD / 32, DD / 32), tb>>>(Wv, pwqkvT + 512 * DD, DD, DD);

    dim3 grid_qkv(QKVW / 128, (NN + 127) / 128);
    dim3 grid_d(DD / 128, (NN + 127) / 128);
    dim3 grid_hus(HUSZ / 128, (NN + 127) / 128);

    for (int l = 0; l < LL; l++) {
        const __half* wqkvT = pwqkvT + (size_t)l * QKVW * DD;
        const __half* woT = pwoT + (size_t)l * DD * DD;
        const float* lg = ln_g + (size_t)l * DD;
        const float* lb = ln_b + (size_t)l * DD;

        gemm_h<<<grid_qkv, 256, GEMM_SMEM>>>(ph16, wqkvT, nullptr, nullptr, pqkv16,
                                             NN, QKVW, DD, 0);
        if (l == 0) cudaStreamWaitEvent(0, ev_join, 0);
        attn_gather<<<(NN * 32 + 255) / 256, 256>>>(poff, pcsrc, pqkv16, pagg16);
        gemm_h<<<grid_d, 256, GEMM_SMEM>>>(pagg16, woT, nullptr, nullptr, pattn16,
                                           NN, DD, DD, 0);
        ln_residual<<<(NN * 32 + 255) / 256, 256>>>(pattn16, ph16, lg, lb);
    }

    gemm_h<<<grid_hus, 256, GEMM_SMEM>>>(ph16, pw1T, b1, nullptr, pffn16,
                                         NN, HUSZ, DD, 1);
    gemm_h<<<grid_d, 256, GEMM_SMEM>>>(pffn16, pw2T, b2, out, nullptr,
                                       NN, DD, HUSZ, 0);
}

// round 14
// speedup vs baseline: 6.0131x; 1.0726x over previous
#include <cuda_runtime.h>
#include <cuda_fp16.h>
#include <math.h>
#include <stdint.h>

#define NN 20000
#define EE 320000
#define DD 256
#define HH 8
#define LL 2
#define HUSZ 1024
#define QKVW 768

// ---------------- scratch (no allocation allowed) ----------------
__device__ __half g_h16[NN * DD];
__device__ __half g_qkv16[NN * QKVW];
__device__ __half g_agg16[NN * DD];
__device__ __half g_attn16[NN * DD];
__device__ __half g_ffn16[NN * HUSZ];
__device__ __half g_wqkvT[LL * QKVW * DD];
__device__ __half g_woT[LL * DD * DD];
__device__ __half g_w1T[HUSZ * DD];
__device__ __half g_w2T[DD * HUSZ];
__device__ int    g_cnt[NN];
__device__ int    g_off[NN + 1];
__device__ int    g_cur[NN];
__device__ int    g_csrc[EE];

// ---------------- helpers ----------------
__device__ __forceinline__ void cp16h(__half* smem_ptr, const __half* gptr, bool p) {
    unsigned s = (unsigned)__cvta_generic_to_shared(smem_ptr);
    int bytes = p ? 16 : 0;
    asm volatile("cp.async.cg.shared.global [%0], [%1], 16, %2;\n"
                 :: "r"(s), "l"(gptr), "r"(bytes));
}
__device__ __forceinline__ void cp_commit() { asm volatile("cp.async.commit_group;\n" ::: "memory"); }
template <int N>
__device__ __forceinline__ void cp_wait() { asm volatile("cp.async.wait_group %0;\n" :: "n"(N) : "memory"); }

#define HSTRIDE 40
#define NSTAGE 3

// ================ gemm_h: BM=128, BN=128 ================
#define H_STAGE (128 * HSTRIDE)
#define GEMM_SMEM ((size_t)NSTAGE * 2 * H_STAGE * sizeof(__half))

__global__ __launch_bounds__(256) void gemm_h(
    const __half* __restrict__ A, const __half* __restrict__ BT,
    const float* __restrict__ bias, float* __restrict__ Cf, __half* __restrict__ Ch,
    int M, int Nc, int Kc, int relu)
{
    extern __shared__ __half smh[];

    const int tid = threadIdx.x;
    const int wid = tid >> 5;
    const int lane = tid & 31;
    const int g = lane >> 2;
    const int t = lane & 3;

    const int warp_m = wid >> 2;
    const int warp_n = wid & 3;
    const int row0 = blockIdx.y * 128;
    const int col0 = blockIdx.x * 128;

    const uint32_t sh0 = (uint32_t)__cvta_generic_to_shared(smh);

    const int a_lane = ((lane & 7) + ((lane >> 3) & 1) * 8) * HSTRIDE + (lane >> 4) * 8;
    const int b_lane4 = (lane & 7) * HSTRIDE + ((lane >> 3) & 1) * 8 + (lane >> 4) * 8 * HSTRIDE;

    float acc[4][4][4];
    #pragma unroll
    for (int mi = 0; mi < 4; mi++)
        #pragma unroll
        for (int ni = 0; ni < 4; ni++)
            #pragma unroll
            for (int r = 0; r < 4; r++) acc[mi][ni][r] = 0.f;

    const int ntiles = Kc >> 5;

    auto load_stage = [&](int st, int k0) {
        __half* as = smh + st * H_STAGE;
        __half* bs = smh + (NSTAGE + st) * H_STAGE;
        #pragma unroll
        for (int i = 0; i < 2; i++) {
            int lin = i * 256 + tid;
            int row = lin >> 2;
            int seg = (lin & 3) * 8;
            cp16h(&as[row * HSTRIDE + seg],
                  &A[(size_t)(row0 + row) * Kc + k0 + seg],
                  row0 + row < M);
            cp16h(&bs[row * HSTRIDE + seg],
                  &BT[(size_t)(col0 + row) * Kc + k0 + seg],
                  true);
        }
    };

    load_stage(0, 0);
    cp_commit();
    load_stage(1, 32);
    cp_commit();

    for (int kt = 0; kt < ntiles; kt++) {
        cp_wait<1>();
        __syncthreads();
        if (kt + 2 < ntiles) load_stage((kt + 2) % NSTAGE, (kt + 2) * 32);
        cp_commit();

        const int st = kt % NSTAGE;
        const uint32_t as_b = sh0 + (uint32_t)(st * H_STAGE) * 2;
        const uint32_t bs_b = sh0 + (uint32_t)((NSTAGE + st) * H_STAGE) * 2;

        #pragma unroll
        for (int ks = 0; ks < 2; ks++) {
            const int kk = ks * 16;
            const uint32_t a_base = as_b + 2u * (warp_m * 64 * HSTRIDE + kk + a_lane);
            const uint32_t b_base = bs_b + 2u * (warp_n * 32 * HSTRIDE + kk + b_lane4);

            unsigned af[4][4];
            #pragma unroll
            for (int mi = 0; mi < 4; mi++) {
                uint32_t addr = a_base + 2u * (mi * 16 * HSTRIDE);
                asm volatile("ldmatrix.sync.aligned.m8n8.x4.shared.b16 {%0,%1,%2,%3}, [%4];"
                             : "=r"(af[mi][0]), "=r"(af[mi][1]), "=r"(af[mi][2]), "=r"(af[mi][3])
                             : "r"(addr));
            }
            unsigned bf[4][2];
            #pragma unroll
            for (int np = 0; np < 2; np++) {
                uint32_t addr = b_base + 2u * (np * 16 * HSTRIDE);
                asm volatile("ldmatrix.sync.aligned.m8n8.x4.shared.b16 {%0,%1,%2,%3}, [%4];"
                             : "=r"(bf[2 * np][0]), "=r"(bf[2 * np][1]),
                               "=r"(bf[2 * np + 1][0]), "=r"(bf[2 * np + 1][1])
                             : "r"(addr));
            }
            #pragma unroll
            for (int mi = 0; mi < 4; mi++)
                #pragma unroll
                for (int ni = 0; ni < 4; ni++) {
                    asm volatile(
                        "mma.sync.aligned.m16n8k16.row.col.f32.f16.f16.f32 "
                        "{%0,%1,%2,%3}, {%4,%5,%6,%7}, {%8,%9}, {%0,%1,%2,%3};"
                        : "+f"(acc[mi][ni][0]), "+f"(acc[mi][ni][1]),
                          "+f"(acc[mi][ni][2]), "+f"(acc[mi][ni][3])
                        : "r"(af[mi][0]), "r"(af[mi][1]), "r"(af[mi][2]), "r"(af[mi][3]),
                          "r"(bf[ni][0]), "r"(bf[ni][1]));
                }
        }
    }

    #pragma unroll
    for (int mi = 0; mi < 4; mi++) {
        int rb = row0 + warp_m * 64 + mi * 16 + g;
        #pragma unroll
        for (int ni = 0; ni < 4; ni++) {
            int cb = col0 + warp_n * 32 + ni * 8 + 2 * t;
            #pragma unroll
            for (int half = 0; half < 2; half++) {
                int r = rb + half * 8;
                if (r >= M) continue;
                float v0 = acc[mi][ni][half * 2 + 0];
                float v1 = acc[mi][ni][half * 2 + 1];
                if (bias) { v0 += bias[cb]; v1 += bias[cb + 1]; }
                if (relu) { v0 = fmaxf(v0, 0.f); v1 = fmaxf(v1, 0.f); }
                if (Ch) {
                    *reinterpret_cast<__half2*>(&Ch[(size_t)r * Nc + cb]) =
                        __floats2half2_rn(v0, v1);
                } else {
                    *reinterpret_cast<float2*>(&Cf[(size_t)r * Nc + cb]) =
                        make_float2(v0, v1);
                }
            }
        }
    }
}

// ================ gemm_h64: BM=64, BN=128 (better wave balance, 3 CTA/SM) ====
#define A64_STAGE (64 * HSTRIDE)
#define B64_STAGE (128 * HSTRIDE)
#define GEMM64_SMEM ((size_t)NSTAGE * (A64_STAGE + B64_STAGE) * sizeof(__half))

__global__ __launch_bounds__(256) void gemm_h64(
    const __half* __restrict__ A, const __half* __restrict__ BT,
    const float* __restrict__ bias, float* __restrict__ Cf, __half* __restrict__ Ch,
    int M, int Nc, int Kc, int relu)
{
    extern __shared__ __half smh[];

    const int tid = threadIdx.x;
    const int wid = tid >> 5;
    const int lane = tid & 31;
    const int g = lane >> 2;
    const int t = lane & 3;

    const int warp_m = wid >> 2;        // 0..1, 32 rows each
    const int warp_n = wid & 3;
    const int row0 = blockIdx.y * 64;
    const int col0 = blockIdx.x * 128;

    const uint32_t sh0 = (uint32_t)__cvta_generic_to_shared(smh);

    const int a_lane = ((lane & 7) + ((lane >> 3) & 1) * 8) * HSTRIDE + (lane >> 4) * 8;
    const int b_lane4 = (lane & 7) * HSTRIDE + ((lane >> 3) & 1) * 8 + (lane >> 4) * 8 * HSTRIDE;

    float acc[2][4][4];
    #pragma unroll
    for (int mi = 0; mi < 2; mi++)
        #pragma unroll
        for (int ni = 0; ni < 4; ni++)
            #pragma unroll
            for (int r = 0; r < 4; r++) acc[mi][ni][r] = 0.f;

    const int ntiles = Kc >> 5;

    auto load_stage = [&](int st, int k0) {
        __half* as = smh + st * A64_STAGE;
        __half* bs = smh + NSTAGE * A64_STAGE + st * B64_STAGE;
        {
            int row = tid >> 2;              // 0..63
            int seg = (tid & 3) * 8;
            cp16h(&as[row * HSTRIDE + seg],
                  &A[(size_t)(row0 + row) * Kc + k0 + seg],
                  row0 + row < M);
        }
        #pragma unroll
        for (int i = 0; i < 2; i++) {
            int lin = i * 256 + tid;
            int row = lin >> 2;
            int seg = (lin & 3) * 8;
            cp16h(&bs[row * HSTRIDE + seg],
                  &BT[(size_t)(col0 + row) * Kc + k0 + seg],
                  true);
        }
    };

    load_stage(0, 0);
    cp_commit();
    load_stage(1, 32);
    cp_commit();

    for (int kt = 0; kt < ntiles; kt++) {
        cp_wait<1>();
        __syncthreads();
        if (kt + 2 < ntiles) load_stage((kt + 2) % NSTAGE, (kt + 2) * 32);
        cp_commit();

        const int st = kt % NSTAGE;
        const uint32_t as_b = sh0 + (uint32_t)(st * A64_STAGE) * 2;
        const uint32_t bs_b = sh0 + (uint32_t)(NSTAGE * A64_STAGE + st * B64_STAGE) * 2;

        #pragma unroll
        for (int ks = 0; ks < 2; ks++) {
            const int kk = ks * 16;
            const uint32_t a_base = as_b + 2u * (warp_m * 32 * HSTRIDE + kk + a_lane);
            const uint32_t b_base = bs_b + 2u * (warp_n * 32 * HSTRIDE + kk + b_lane4);

            unsigned af[2][4];
            #pragma unroll
            for (int mi = 0; mi < 2; mi++) {
                uint32_t addr = a_base + 2u * (mi * 16 * HSTRIDE);
                asm volatile("ldmatrix.sync.aligned.m8n8.x4.shared.b16 {%0,%1,%2,%3}, [%4];"
                             : "=r"(af[mi][0]), "=r"(af[mi][1]), "=r"(af[mi][2]), "=r"(af[mi][3])
                             : "r"(addr));
            }
            unsigned bf[4][2];
            #pragma unroll
            for (int np = 0; np < 2; np++) {
                uint32_t addr = b_base + 2u * (np * 16 * HSTRIDE);
                asm volatile("ldmatrix.sync.aligned.m8n8.x4.shared.b16 {%0,%1,%2,%3}, [%4];"
                             : "=r"(bf[2 * np][0]), "=r"(bf[2 * np][1]),
                               "=r"(bf[2 * np + 1][0]), "=r"(bf[2 * np + 1][1])
                             : "r"(addr));
            }
            #pragma unroll
            for (int mi = 0; mi < 2; mi++)
                #pragma unroll
                for (int ni = 0; ni < 4; ni++) {
                    asm volatile(
                        "mma.sync.aligned.m16n8k16.row.col.f32.f16.f16.f32 "
                        "{%0,%1,%2,%3}, {%4,%5,%6,%7}, {%8,%9}, {%0,%1,%2,%3};"
                        : "+f"(acc[mi][ni][0]), "+f"(acc[mi][ni][1]),
                          "+f"(acc[mi][ni][2]), "+f"(acc[mi][ni][3])
                        : "r"(af[mi][0]), "r"(af[mi][1]), "r"(af[mi][2]), "r"(af[mi][3]),
                          "r"(bf[ni][0]), "r"(bf[ni][1]));
                }
        }
    }

    #pragma unroll
    for (int mi = 0; mi < 2; mi++) {
        int rb = row0 + warp_m * 32 + mi * 16 + g;
        #pragma unroll
        for (int ni = 0; ni < 4; ni++) {
            int cb = col0 + warp_n * 32 + ni * 8 + 2 * t;
            #pragma unroll
            for (int half = 0; half < 2; half++) {
                int r = rb + half * 8;
                if (r >= M) continue;
                float v0 = acc[mi][ni][half * 2 + 0];
                float v1 = acc[mi][ni][half * 2 + 1];
                if (bias) { v0 += bias[cb]; v1 += bias[cb + 1]; }
                if (relu) { v0 = fmaxf(v0, 0.f); v1 = fmaxf(v1, 0.f); }
                if (Ch) {
                    *reinterpret_cast<__half2*>(&Ch[(size_t)r * Nc + cb]) =
                        __floats2half2_rn(v0, v1);
                } else {
                    *reinterpret_cast<float2*>(&Cf[(size_t)r * Nc + cb]) =
                        make_float2(v0, v1);
                }
            }
        }
    }
}

// ---------------- fused prep ----------------
__device__ __forceinline__ void trans_block(const float* __restrict__ src,
                                            __half* __restrict__ dst,
                                            int R, int C, int bx, int by,
                                            int tx, int ty)
{
    __shared__ float t[32][33];
    int cb = bx * 32, rb = by * 32;
    #pragma unroll
    for (int j = 0; j < 4; j++)
        t[ty + j * 8][tx] = src[(size_t)(rb + ty + j * 8) * C + cb + tx];
    __syncthreads();
    #pragma unroll
    for (int j = 0; j < 4; j++)
        dst[(size_t)(cb + ty + j * 8) * R + rb + tx] = __float2half_rn(t[tx][ty + j * 8]);
}

// main-stream prep: layer-0 Wq/Wk/Wv transposes (blocks 0..191) + h f2h (rest)
__global__ __launch_bounds__(256) void prep_main(
    const float* __restrict__ h_in, __half* __restrict__ h16,
    const float* __restrict__ Wq, const float* __restrict__ Wk,
    const float* __restrict__ Wv, __half* __restrict__ wqkvT)
{
    int b = blockIdx.x;
    int tid = threadIdx.x;
    int tx = tid & 31, ty = tid >> 5;
    if (b < 64) {
        trans_block(Wq, wqkvT, DD, DD, b & 7, b >> 3, tx, ty);
    } else if (b < 128) {
        int bb = b - 64;
        trans_block(Wk, wqkvT + 256 * DD, DD, DD, bb & 7, bb >> 3, tx, ty);
    } else if (b < 192) {
        int bb = b - 128;
        trans_block(Wv, wqkvT + 512 * DD, DD, DD, bb & 7, bb >> 3, tx, ty);
    } else {
        int idx = (b - 192) * 2048 + tid * 8;   // NN*DD = 5,120,000 = 2500*2048
        float4 a = *reinterpret_cast<const float4*>(&h_in[idx]);
        float4 c = *reinterpret_cast<const float4*>(&h_in[idx + 4]);
        uint4 o;
        *reinterpret_cast<__half2*>(&o.x) = __floats2half2_rn(a.x, a.y);
        *reinterpret_cast<__half2*>(&o.y) = __floats2half2_rn(a.z, a.w);
        *reinterpret_cast<__half2*>(&o.z) = __floats2half2_rn(c.x, c.y);
        *reinterpret_cast<__half2*>(&o.w) = __floats2half2_rn(c.z, c.w);
        *reinterpret_cast<uint4*>(&h16[idx]) = o;
    }
}

// s2 prep: layer-1 Wq/Wk/Wv + Wo(l0,l1) + w1 + w2 transposes, 832 blocks
__global__ __launch_bounds__(256) void prep_s2(
    const float* __restrict__ Wq, const float* __restrict__ Wk,
    const float* __restrict__ Wv, const float* __restrict__ Wo,
    const float* __restrict__ w1, const float* __restrict__ w2,
    __half* __restrict__ wqkvT, __half* __restrict__ woT,
    __half* __restrict__ w1T, __half* __restrict__ w2T)
{
    int b = blockIdx.x;
    int tid = threadIdx.x;
    int tx = tid & 31, ty = tid >> 5;
    const size_t WSZ = (size_t)DD * DD;
    __half* qkv1 = wqkvT + (size_t)QKVW * DD;
    if (b < 64) {
        trans_block(Wq + WSZ, qkv1, DD, DD, b & 7, b >> 3, tx, ty);
    } else if (b < 128) {
        int bb = b - 64;
        trans_block(Wk + WSZ, qkv1 + 256 * DD, DD, DD, bb & 7, bb >> 3, tx, ty);
    } else if (b < 192) {
        int bb = b - 128;
        trans_block(Wv + WSZ, qkv1 + 512 * DD, DD, DD, bb & 7, bb >> 3, tx, ty);
    } else if (b < 256) {
        int bb = b - 192;
        trans_block(Wo, woT, DD, DD, bb & 7, bb >> 3, tx, ty);
    } else if (b < 320) {
        int bb = b - 256;
        trans_block(Wo + WSZ, woT + WSZ, DD, DD, bb & 7, bb >> 3, tx, ty);
    } else if (b < 576) {
        int bb = b - 320;                      // w1: R=DD, C=HUSZ -> 32 x 8 blocks
        trans_block(w1, w1T, DD, HUSZ, bb & 31, bb >> 5, tx, ty);
    } else {
        int bb = b - 576;                      // w2: R=HUSZ, C=DD -> 8 x 32 blocks
        trans_block(w2, w2T, HUSZ, DD, bb & 7, bb >> 3, tx, ty);
    }
}

// ---------------- CSR build ----------------
__global__ void hist_dst(const int* __restrict__ dst, int* __restrict__ cnt)
{
    int i = blockIdx.x * blockDim.x + threadIdx.x;
    if (i < EE) atomicAdd(&cnt[dst[i]], 1);
}

__global__ __launch_bounds__(1024) void scan_offsets(const int* __restrict__ cnt,
                                                     int* __restrict__ off,
                                                     int* __restrict__ cur)
{
    __shared__ int wsum[32];
    __shared__ int carry_s;
    const int lane = threadIdx.x & 31;
    const int wid = threadIdx.x >> 5;
    if (threadIdx.x == 0) carry_s = 0;
    __syncthreads();
    for (int base = 0; base < NN; base += 1024) {
        int i = base + threadIdx.x;
        int v = (i < NN) ? cnt[i] : 0;
        int x = v;
        #pragma unroll
        for (int s = 1; s < 32; s <<= 1) {
            int t = __shfl_up_sync(0xffffffffu, x, s);
            if (lane >= s) x += t;
        }
        if (lane == 31) wsum[wid] = x;
        __syncthreads();
        if (wid == 0) {
            int w = wsum[lane];
            #pragma unroll
            for (int s = 1; s < 32; s <<= 1) {
                int t = __shfl_up_sync(0xffffffffu, w, s);
                if (lane >= s) w += t;
            }
            wsum[lane] = w;
        }
        __syncthreads();
        int warp_prefix = (wid > 0) ? wsum[wid - 1] : 0;
        int carry = carry_s;
        int excl = carry + warp_prefix + x - v;
        if (i < NN) { off[i] = excl; cur[i] = excl; }
        __syncthreads();
        if (threadIdx.x == 1023) carry_s = carry + wsum[31];
        __syncthreads();
    }
    if (threadIdx.x == 0) off[NN] = carry_s;
}

__global__ void scatter_csr(const int* __restrict__ src, const int* __restrict__ dst,
                            int* __restrict__ cur, int* __restrict__ csrc)
{
    int i = blockIdx.x * blockDim.x + threadIdx.x;
    if (i >= EE) return;
    int pos = atomicAdd(&cur[dst[i]], 1);
    csrc[pos] = src[i];
}

// ---------------- fused attention gather: one warp per dst node ----------------
__global__ __launch_bounds__(256) void attn_gather(
    const int* __restrict__ off, const int* __restrict__ csrc,
    const __half* __restrict__ qkv, __half* __restrict__ agg)
{
    int node = (blockIdx.x * blockDim.x + threadIdx.x) >> 5;
    int lane = threadIdx.x & 31;
    if (node >= NN) return;
    const int h = lane >> 2;
    const int sub = lane & 3;
    const int doff = h * 32 + sub * 8;

    int beg = off[node], end = off[node + 1];

    uint4 qb = *reinterpret_cast<const uint4*>(&qkv[(size_t)node * QKVW + doff]);
    float2 qf0 = __half22float2(*reinterpret_cast<__half2*>(&qb.x));
    float2 qf1 = __half22float2(*reinterpret_cast<__half2*>(&qb.y));
    float2 qf2 = __half22float2(*reinterpret_cast<__half2*>(&qb.z));
    float2 qf3 = __half22float2(*reinterpret_cast<__half2*>(&qb.w));

    const float scale = 0.17677669529663687f;

    float mA = -INFINITY, zA = 0.f;
    float mB = -INFINITY, zB = 0.f;
    float accA[8], accB[8];
    #pragma unroll
    for (int j = 0; j < 8; j++) { accA[j] = 0.f; accB[j] = 0.f; }

    int p = beg;
    for (; p + 1 < end; p += 2) {
        int sA = csrc[p];
        int sB = csrc[p + 1];
        const __half* bA = qkv + (size_t)sA * QKVW + 256 + doff;
        const __half* bB = qkv + (size_t)sB * QKVW + 256 + doff;
        uint4 krA = *reinterpret_cast<const uint4*>(bA);
        uint4 krB = *reinterpret_cast<const uint4*>(bB);
        uint4 vrA = *reinterpret_cast<const uint4*>(bA + 256);
        uint4 vrB = *reinterpret_cast<const uint4*>(bB + 256);

        float2 kA0 = __half22float2(*reinterpret_cast<__half2*>(&krA.x));
        float2 kA1 = __half22float2(*reinterpret_cast<__half2*>(&krA.y));
        float2 kA2 = __half22float2(*reinterpret_cast<__half2*>(&krA.z));
        float2 kA3 = __half22float2(*reinterpret_cast<__half2*>(&krA.w));
        float2 kB0 = __half22float2(*reinterpret_cast<__half2*>(&krB.x));
        float2 kB1 = __half22float2(*reinterpret_cast<__half2*>(&krB.y));
        float2 kB2 = __half22float2(*reinterpret_cast<__half2*>(&krB.z));
        float2 kB3 = __half22float2(*reinterpret_cast<__half2*>(&krB.w));

        float pA = qf0.x * kA0.x + qf0.y * kA0.y + qf1.x * kA1.x + qf1.y * kA1.y
                 + qf2.x * kA2.x + qf2.y * kA2.y + qf3.x * kA3.x + qf3.y * kA3.y;
        float pB = qf0.x * kB0.x + qf0.y * kB0.y + qf1.x * kB1.x + qf1.y * kB1.y
                 + qf2.x * kB2.x + qf2.y * kB2.y + qf3.x * kB3.x + qf3.y * kB3.y;
        pA += __shfl_xor_sync(0xffffffffu, pA, 1);
        pB += __shfl_xor_sync(0xffffffffu, pB, 1);
        pA += __shfl_xor_sync(0xffffffffu, pA, 2);
        pB += __shfl_xor_sync(0xffffffffu, pB, 2);

        float lA = pA * scale;
        float lB = pB * scale;

        float2 vA0 = __half22float2(*reinterpret_cast<__half2*>(&vrA.x));
        float2 vA1 = __half22float2(*reinterpret_cast<__half2*>(&vrA.y));
        float2 vA2 = __half22float2(*reinterpret_cast<__half2*>(&vrA.z));
        float2 vA3 = __half22float2(*reinterpret_cast<__half2*>(&vrA.w));
        float2 vB0 = __half22float2(*reinterpret_cast<__half2*>(&vrB.x));
        float2 vB1 = __half22float2(*reinterpret_cast<__half2*>(&vrB.y));
        float2 vB2 = __half22float2(*reinterpret_cast<__half2*>(&vrB.z));
        float2 vB3 = __half22float2(*reinterpret_cast<__half2*>(&vrB.w));

        float nmA = fmaxf(mA, lA);
        float fA = __expf(mA - nmA);
        float aA = __expf(lA - nmA);
        zA = zA * fA + aA;
        mA = nmA;
        accA[0] = accA[0] * fA + aA * vA0.x;
        accA[1] = accA[1] * fA + aA * vA0.y;
        accA[2] = accA[2] * fA + aA * vA1.x;
        accA[3] = accA[3] * fA + aA * vA1.y;
        accA[4] = accA[4] * fA + aA * vA2.x;
        accA[5] = accA[5] * fA + aA * vA2.y;
        accA[6] = accA[6] * fA + aA * vA3.x;
        accA[7] = accA[7] * fA + aA * vA3.y;

        float nmB = fmaxf(mB, lB);
        float fB = __expf(mB - nmB);
        float aB = __expf(lB - nmB);
        zB = zB * fB + aB;
        mB = nmB;
        accB[0] = accB[0] * fB + aB * vB0.x;
        accB[1] = accB[1] * fB + aB * vB0.y;
        accB[2] = accB[2] * fB + aB * vB1.x;
        accB[3] = accB[3] * fB + aB * vB1.y;
        accB[4] = accB[4] * fB + aB * vB2.x;
        accB[5] = accB[5] * fB + aB * vB2.y;
        accB[6] = accB[6] * fB + aB * vB3.x;
        accB[7] = accB[7] * fB + aB * vB3.y;
    }
    if (p < end) {
        int s = csrc[p];
        const __half* b = qkv + (size_t)s * QKVW + 256 + doff;
        uint4 kr = *reinterpret_cast<const uint4*>(b);
        uint4 vr = *reinterpret_cast<const uint4*>(b + 256);
        float2 k0 = __half22float2(*reinterpret_cast<__half2*>(&kr.x));
        float2 k1 = __half22float2(*reinterpret_cast<__half2*>(&kr.y));
        float2 k2 = __half22float2(*reinterpret_cast<__half2*>(&kr.z));
        float2 k3 = __half22float2(*reinterpret_cast<__half2*>(&kr.w));
        float part = qf0.x * k0.x + qf0.y * k0.y + qf1.x * k1.x + qf1.y * k1.y
                   + qf2.x * k2.x + qf2.y * k2.y + qf3.x * k3.x + qf3.y * k3.y;
        part += __shfl_xor_sync(0xffffffffu, part, 1);
        part += __shfl_xor_sync(0xffffffffu, part, 2);
        float logit = part * scale;
        float2 v0 = __half22float2(*reinterpret_cast<__half2*>(&vr.x));
        float2 v1 = __half22float2(*reinterpret_cast<__half2*>(&vr.y));
        float2 v2 = __half22float2(*reinterpret_cast<__half2*>(&vr.z));
        float2 v3 = __half22float2(*reinterpret_cast<__half2*>(&vr.w));
        float nm = fmaxf(mA, logit);
        float f = __expf(mA - nm);
        float a = __expf(logit - nm);
        zA = zA * f + a;
        mA = nm;
        accA[0] = accA[0] * f + a * v0.x;
        accA[1] = accA[1] * f + a * v0.y;
        accA[2] = accA[2] * f + a * v1.x;
        accA[3] = accA[3] * f + a * v1.y;
        accA[4] = accA[4] * f + a * v2.x;
        accA[5] = accA[5] * f + a * v2.y;
        accA[6] = accA[6] * f + a * v3.x;
        accA[7] = accA[7] * f + a * v3.y;
    }

    float m = fmaxf(mA, mB);
    float fA = (zA > 0.f) ? __expf(mA - m) : 0.f;
    float fB = (zB > 0.f) ? __expf(mB - m) : 0.f;
    float z = zA * fA + zB * fB;
    float inv = 1.f / (z + 1e-9f);

    uint4 outw;
    float o[8];
    #pragma unroll
    for (int j = 0; j < 8; j++) o[j] = (accA[j] * fA + accB[j] * fB) * inv;
    if (end == beg) {
        #pragma unroll
        for (int j = 0; j < 8; j++) o[j] = 0.f;
    }
    *reinterpret_cast<__half2*>(&outw.x) = __floats2half2_rn(o[0], o[1]);
    *reinterpret_cast<__half2*>(&outw.y) = __floats2half2_rn(o[2], o[3]);
    *reinterpret_cast<__half2*>(&outw.z) = __floats2half2_rn(o[4], o[5]);
    *reinterpret_cast<__half2*>(&outw.w) = __floats2half2_rn(o[6], o[7]);
    *reinterpret_cast<uint4*>(&agg[(size_t)node * DD + doff]) = outw;
}

// ---------------- residual + layernorm (fp16 in/out, fp32 math) ----------------
__global__ void ln_residual(const __half* __restrict__ attn, __half* __restrict__ h,
                            const float* __restrict__ gamma, const float* __restrict__ beta)
{
    int row = (blockIdx.x * blockDim.x + threadIdx.x) >> 5;
    int lane = threadIdx.x & 31;
    if (row >= NN) return;
    float x[8];
    float s = 0.f;
    #pragma unroll
    for (int j = 0; j < 8; j++) {
        int idx = row * DD + j * 32 + lane;
        x[j] = __half2float(attn[idx]) + __half2float(h[idx]);
        s += x[j];
    }
    #pragma unroll
    for (int off = 16; off; off >>= 1) s += __shfl_xor_sync(0xffffffffu, s, off);
    float mu = s * (1.f / DD);
    float vs = 0.f;
    #pragma unroll
    for (int j = 0; j < 8; j++) { float dlt = x[j] - mu; vs += dlt * dlt; }
    #pragma unroll
    for (int off = 16; off; off >>= 1) vs += __shfl_xor_sync(0xffffffffu, vs, off);
    float inv = rsqrtf(vs * (1.f / DD) + 1e-5f);
    #pragma unroll
    for (int j = 0; j < 8; j++) {
        int c = j * 32 + lane;
        h[row * DD + c] = __float2half_rn((x[j] - mu) * inv * gamma[c] + beta[c]);
    }
}

// ---------------- launch ----------------
extern "C" void kernel_launch(void* const* d_in, const int* in_sizes, int n_in,
                              void* d_out, int out_size)
{
    const float* h_in = (const float*)d_in[0];
    const int* src = (const int*)d_in[1];
    const int* dst = (const int*)d_in[2];
    const float* Wq = (const float*)d_in[3];
    const float* Wk = (const float*)d_in[4];
    const float* Wv = (const float*)d_in[5];
    const float* Wo = (const float*)d_in[6];
    const float* ln_g = (const float*)d_in[7];
    const float* ln_b = (const float*)d_in[8];
    const float* w1 = (const float*)d_in[9];
    const float* b1 = (const float*)d_in[10];
    const float* w2 = (const float*)d_in[11];
    const float* b2 = (const float*)d_in[12];
    float* out = (float*)d_out;

    __half *ph16, *pqkv16, *pagg16, *pattn16, *pffn16, *pwqkvT, *pwoT, *pw1T, *pw2T;
    int *pcnt, *poff, *pcur, *pcsrc;
    cudaGetSymbolAddress((void**)&ph16, g_h16);
    cudaGetSymbolAddress((void**)&pqkv16, g_qkv16);
    cudaGetSymbolAddress((void**)&pagg16, g_agg16);
    cudaGetSymbolAddress((void**)&pattn16, g_attn16);
    cudaGetSymbolAddress((void**)&pffn16, g_ffn16);
    cudaGetSymbolAddress((void**)&pwqkvT, g_wqkvT);
    cudaGetSymbolAddress((void**)&pwoT, g_woT);
    cudaGetSymbolAddress((void**)&pw1T, g_w1T);
    cudaGetSymbolAddress((void**)&pw2T, g_w2T);
    cudaGetSymbolAddress((void**)&pcnt, g_cnt);
    cudaGetSymbolAddress((void**)&poff, g_off);
    cudaGetSymbolAddress((void**)&pcur, g_cur);
    cudaGetSymbolAddress((void**)&pcsrc, g_csrc);

    static cudaStream_t s2 = nullptr;
    static cudaEvent_t ev_fork = nullptr, ev_join = nullptr;
    static bool init_done = false;
    if (!init_done) {
        cudaFuncSetAttribute(gemm_h, cudaFuncAttributeMaxDynamicSharedMemorySize, GEMM_SMEM);
        cudaFuncSetAttribute(gemm_h64, cudaFuncAttributeMaxDynamicSharedMemorySize, GEMM64_SMEM);
        cudaStreamCreateWithFlags(&s2, cudaStreamNonBlocking);
        cudaEventCreateWithFlags(&ev_fork, cudaEventDisableTiming);
        cudaEventCreateWithFlags(&ev_join, cudaEventDisableTiming);
        init_done = true;
    }

    // fork: CSR build + remaining weight transposes on s2
    cudaEventRecord(ev_fork, 0);
    cudaStreamWaitEvent(s2, ev_fork, 0);

    prep_s2<<<832, 256, 0, s2>>>(Wq, Wk, Wv, Wo, w1, w2, pwqkvT, pwoT, pw1T, pw2T);
    cudaMemsetAsync(pcnt, 0, NN * sizeof(int), s2);
    hist_dst<<<(EE + 255) / 256, 256, 0, s2>>>(dst, pcnt);
    scan_offsets<<<1, 1024, 0, s2>>>(pcnt, poff, pcur);
    scatter_csr<<<(EE + 255) / 256, 256, 0, s2>>>(src, dst, pcur, pcsrc);
    cudaEventRecord(ev_join, s2);

    // main stream: fused h->fp16 + layer-0 qkv transposes
    prep_main<<<192 + 2500, 256>>>(h_in, ph16, Wq, Wk, Wv, pwqkvT);

    dim3 grid_qkv(QKVW / 128, (NN + 127) / 128);
    dim3 grid_d64(DD / 128, (NN + 63) / 64);
    dim3 grid_hus(HUSZ / 128, (NN + 127) / 128);

    for (int l = 0; l < LL; l++) {
        const __half* wqkvT = pwqkvT + (size_t)l * QKVW * DD;
        const __half* woT = pwoT + (size_t)l * DD * DD;
        const float* lg = ln_g + (size_t)l * DD;
        const float* lb = ln_b + (size_t)l * DD;

        gemm_h<<<grid_qkv, 256, GEMM_SMEM>>>(ph16, wqkvT, nullptr, nullptr, pqkv16,
                                             NN, QKVW, DD, 0);
        if (l == 0) cudaStreamWaitEvent(0, ev_join, 0);
        attn_gather<<<(NN * 32 + 255) / 256, 256>>>(poff, pcsrc, pqkv16, pagg16);
        gemm_h64<<<grid_d64, 256, GEMM64_SMEM>>>(pagg16, woT, nullptr, nullptr, pattn16,
                                                 NN, DD, DD, 0);
        ln_residual<<<(NN * 32 + 255) / 256, 256>>>(pattn16, ph16, lg, lb);
    }

    gemm_h<<<grid_hus, 256, GEMM_SMEM>>>(ph16, pw1T, b1, nullptr, pffn16,
                                         NN, HUSZ, DD, 1);
    gemm_h64<<<grid_d64, 256, GEMM64_SMEM>>>(pffn16, pw2T, b2, out, nullptr,
                                             NN, DD, HUSZ, 0);
}